// round 1
// baseline (speedup 1.0000x reference)
#include <cuda_runtime.h>
#include <math.h>

#define EDIM 1024
#define NH   16
#define HD   64
#define TQ   2048
#define NB   4
#define MROWS (NB*TQ)   // 8192

// ---------------- scratch (device globals: no allocations allowed) ----------
__device__ float g_q [MROWS*EDIM];
__device__ float g_k [MROWS*EDIM];
__device__ float g_v [MROWS*EDIM];
__device__ float g_ao[MROWS*EDIM];

// ---------------- GEMM: C[M,N] = A[M,K] @ W[K,N] + bias[N] ------------------
#define GBM 128
#define GBN 128
#define GBK 8

__global__ __launch_bounds__(256, 2)
void sgemm_bias_kernel(const float* __restrict__ A,
                       const float* __restrict__ W,
                       const float* __restrict__ bias,
                       float* __restrict__ C,
                       int M, int N, int K)
{
    __shared__ float As[GBK][GBM];   // transposed A tile
    __shared__ float Ws[GBK][GBN];

    const int tid = threadIdx.x;
    const int tx  = tid % 16;         // col group (8 cols each)
    const int ty  = tid / 16;         // row group (8 rows each)
    const int bm  = blockIdx.y * GBM;
    const int bn  = blockIdx.x * GBN;

    // load mapping
    const int arow  = tid >> 1;          // 0..127
    const int acol4 = (tid & 1) * 4;     // 0 or 4
    const int wrow  = tid >> 5;          // 0..7
    const int wcol4 = (tid & 31) * 4;    // 0..124

    float acc[8][8];
#pragma unroll
    for (int i = 0; i < 8; i++)
#pragma unroll
        for (int j = 0; j < 8; j++) acc[i][j] = 0.0f;

    for (int k0 = 0; k0 < K; k0 += GBK) {
        float4 av = *reinterpret_cast<const float4*>(&A[(size_t)(bm + arow) * K + k0 + acol4]);
        As[acol4 + 0][arow] = av.x;
        As[acol4 + 1][arow] = av.y;
        As[acol4 + 2][arow] = av.z;
        As[acol4 + 3][arow] = av.w;
        *reinterpret_cast<float4*>(&Ws[wrow][wcol4]) =
            *reinterpret_cast<const float4*>(&W[(size_t)(k0 + wrow) * N + bn + wcol4]);
        __syncthreads();

#pragma unroll
        for (int k = 0; k < GBK; k++) {
            float4 a0 = *reinterpret_cast<const float4*>(&As[k][ty * 8 + 0]);
            float4 a1 = *reinterpret_cast<const float4*>(&As[k][ty * 8 + 4]);
            float4 b0 = *reinterpret_cast<const float4*>(&Ws[k][tx * 8 + 0]);
            float4 b1 = *reinterpret_cast<const float4*>(&Ws[k][tx * 8 + 4]);
            float a[8] = {a0.x, a0.y, a0.z, a0.w, a1.x, a1.y, a1.z, a1.w};
            float b[8] = {b0.x, b0.y, b0.z, b0.w, b1.x, b1.y, b1.z, b1.w};
#pragma unroll
            for (int i = 0; i < 8; i++)
#pragma unroll
                for (int j = 0; j < 8; j++)
                    acc[i][j] = fmaf(a[i], b[j], acc[i][j]);
        }
        __syncthreads();
    }

    // epilogue with bias
#pragma unroll
    for (int i = 0; i < 8; i++) {
        const int row = bm + ty * 8 + i;
        float* cp = &C[(size_t)row * N + bn + tx * 8];
        float4 o0, o1;
        o0.x = acc[i][0] + bias[bn + tx * 8 + 0];
        o0.y = acc[i][1] + bias[bn + tx * 8 + 1];
        o0.z = acc[i][2] + bias[bn + tx * 8 + 2];
        o0.w = acc[i][3] + bias[bn + tx * 8 + 3];
        o1.x = acc[i][4] + bias[bn + tx * 8 + 4];
        o1.y = acc[i][5] + bias[bn + tx * 8 + 5];
        o1.z = acc[i][6] + bias[bn + tx * 8 + 6];
        o1.w = acc[i][7] + bias[bn + tx * 8 + 7];
        *reinterpret_cast<float4*>(cp + 0) = o0;
        *reinterpret_cast<float4*>(cp + 4) = o1;
    }
}

// ---------------- cumprod(cos(x)) along last dim (1024) ---------------------
__global__ __launch_bounds__(1024)
void cumprod_cos_kernel(float* __restrict__ data)
{
    __shared__ float s[EDIM];
    const int row = blockIdx.x;
    const int t   = threadIdx.x;
    float v = cosf(data[(size_t)row * EDIM + t]);
    s[t] = v;
    __syncthreads();
#pragma unroll
    for (int off = 1; off < EDIM; off <<= 1) {
        float p = (t >= off) ? s[t - off] : 1.0f;
        __syncthreads();
        s[t] *= p;
        __syncthreads();
    }
    data[(size_t)row * EDIM + t] = s[t];
}

// ---------------- attention: thread-per-query online softmax ----------------
#define ATQ 128   // queries per block (== blockDim.x)
#define ATK 64    // key tile

__global__ __launch_bounds__(ATQ)
void attention_kernel(const float* __restrict__ Qm,   // query matrix (B*T, E)
                      const float* __restrict__ Km,   // key matrix
                      const float* __restrict__ Vm,   // value matrix
                      float* __restrict__ O)          // (B*T, E) combined heads
{
    __shared__ float Ks[ATK][HD];
    __shared__ float Vs[ATK][HD];

    const int t  = threadIdx.x;
    const int qb = blockIdx.x * ATQ;
    const int h  = blockIdx.y;
    const int b  = blockIdx.z;

    const int row = b * TQ + qb + t;  // this thread's query token
    const float* qptr = Qm + (size_t)row * EDIM + h * HD;

    float4 q[16];
#pragma unroll
    for (int c = 0; c < 16; c++) q[c] = reinterpret_cast<const float4*>(qptr)[c];

    float acc[64];
#pragma unroll
    for (int i = 0; i < 64; i++) acc[i] = 0.0f;
    float mval = -1e30f, lval = 0.0f;
    const float scale = 0.125f;   // 1/sqrt(64)

    for (int kb = 0; kb < TQ; kb += ATK) {
        // cooperative load of K,V tiles (coalesced float4)
        for (int idx = t; idx < ATK * (HD / 4); idx += ATQ) {
            const int r = idx >> 4;           // HD/4 = 16 float4 per row
            const int c = idx & 15;
            const size_t gro = (size_t)(b * TQ + kb + r) * EDIM + h * HD;
            reinterpret_cast<float4*>(&Ks[r][0])[c] =
                reinterpret_cast<const float4*>(Km + gro)[c];
            reinterpret_cast<float4*>(&Vs[r][0])[c] =
                reinterpret_cast<const float4*>(Vm + gro)[c];
        }
        __syncthreads();

        for (int kk = 0; kk < ATK; kk++) {
            float s = 0.0f;
#pragma unroll
            for (int c = 0; c < 16; c++) {
                float4 kv = reinterpret_cast<const float4*>(&Ks[kk][0])[c];
                s = fmaf(q[c].x, kv.x, s);
                s = fmaf(q[c].y, kv.y, s);
                s = fmaf(q[c].z, kv.z, s);
                s = fmaf(q[c].w, kv.w, s);
            }
            s *= scale;
            if (s > mval) {                     // rare record-high rescale
                float corr = __expf(mval - s);
                lval *= corr;
#pragma unroll
                for (int i = 0; i < 64; i++) acc[i] *= corr;
                mval = s;
            }
            float p = __expf(s - mval);
            lval += p;
#pragma unroll
            for (int c = 0; c < 16; c++) {
                float4 vv = reinterpret_cast<const float4*>(&Vs[kk][0])[c];
                acc[4 * c + 0] = fmaf(p, vv.x, acc[4 * c + 0]);
                acc[4 * c + 1] = fmaf(p, vv.y, acc[4 * c + 1]);
                acc[4 * c + 2] = fmaf(p, vv.z, acc[4 * c + 2]);
                acc[4 * c + 3] = fmaf(p, vv.w, acc[4 * c + 3]);
            }
        }
        __syncthreads();
    }

    const float inv = 1.0f / lval;
    float* op = O + (size_t)row * EDIM + h * HD;
#pragma unroll
    for (int c = 0; c < 16; c++) {
        float4 o;
        o.x = acc[4 * c + 0] * inv;
        o.y = acc[4 * c + 1] * inv;
        o.z = acc[4 * c + 2] * inv;
        o.w = acc[4 * c + 3] * inv;
        reinterpret_cast<float4*>(op)[c] = o;
    }
}

// ---------------- launch ----------------------------------------------------
extern "C" void kernel_launch(void* const* d_in, const int* in_sizes, int n_in,
                              void* d_out, int out_size)
{
    const float* x  = (const float*)d_in[0];
    const float* Wq = (const float*)d_in[1];
    const float* bq = (const float*)d_in[2];
    const float* Wk = (const float*)d_in[3];
    const float* bk = (const float*)d_in[4];
    const float* Wv = (const float*)d_in[5];
    const float* bv = (const float*)d_in[6];
    const float* Wo = (const float*)d_in[7];
    const float* bo = (const float*)d_in[8];
    float* out = (float*)d_out;

    float *q, *k, *v, *ao;
    cudaGetSymbolAddress((void**)&q,  g_q);
    cudaGetSymbolAddress((void**)&k,  g_k);
    cudaGetSymbolAddress((void**)&v,  g_v);
    cudaGetSymbolAddress((void**)&ao, g_ao);

    dim3 gg(EDIM / GBN, MROWS / GBM);   // (8, 64)
    sgemm_bias_kernel<<<gg, 256>>>(x, Wq, bq, q, MROWS, EDIM, EDIM);
    sgemm_bias_kernel<<<gg, 256>>>(x, Wk, bk, k, MROWS, EDIM, EDIM);
    sgemm_bias_kernel<<<gg, 256>>>(x, Wv, bv, v, MROWS, EDIM, EDIM);

    cumprod_cos_kernel<<<MROWS, 1024>>>(q);
    cumprod_cos_kernel<<<MROWS, 1024>>>(k);

    // NOTE reference role swap: query = quantum(k-proj), key = quantum(q-proj)
    dim3 ga(TQ / ATQ, NH, NB);          // (16, 16, 4)
    attention_kernel<<<ga, ATQ>>>(k, q, v, ao);

    sgemm_bias_kernel<<<gg, 256>>>(ao, Wo, bo, out, MROWS, EDIM, EDIM);
}

// round 5
// speedup vs baseline: 1.4614x; 1.4614x over previous
#include <cuda_runtime.h>
#include <cuda_bf16.h>
#include <math.h>
#include <stdint.h>

#define EDIM 1024
#define NH   16
#define HD   64
#define TQ   2048
#define NB   4
#define MROWS (NB*TQ)   // 8192

// tcgen05 is arch-SPECIFIC: only emit it in the sm_103a/sm_100a feature pass.
// The generic compute_103 PTX pass compiles an empty body (never executed:
// the driver always selects the exact-match sm_103a cubin on GB300).
#if defined(__CUDA_ARCH_FEAT_SM103_ALL) || defined(__CUDA_ARCH_FEAT_SM100_ALL) || \
    defined(__CUDA_ARCH_FEAT_SM101_ALL) || defined(__CUDA_ARCH_SPECIFIC__)
#define TCGEN05_OK 1
#endif

// ---------------- scratch (device globals: no allocations allowed) ----------
__device__ float g_q [MROWS*EDIM];
__device__ float g_k [MROWS*EDIM];
__device__ float g_v [MROWS*EDIM];
__device__ float g_ao[MROWS*EDIM];
__device__ __nv_bfloat16 g_xhi [MROWS*EDIM];
__device__ __nv_bfloat16 g_xlo [MROWS*EDIM];
__device__ __nv_bfloat16 g_aohi[MROWS*EDIM];
__device__ __nv_bfloat16 g_aolo[MROWS*EDIM];
__device__ __nv_bfloat16 g_wthi[4*EDIM*EDIM];   // W^T (N-major rows, K contiguous)
__device__ __nv_bfloat16 g_wtlo[4*EDIM*EDIM];

// ======================= PTX helpers (sm_103a) ==============================
__device__ __forceinline__ uint32_t smem_to_u32(const void* p) {
    uint32_t a;
    asm("{ .reg .u64 t; cvta.to.shared.u64 t, %1; cvt.u32.u64 %0, t; }" : "=r"(a) : "l"(p));
    return a;
}
__device__ __forceinline__ uint32_t elect_one_pred() {
    uint32_t pred;
    asm volatile("{\n\t.reg .pred p;\n\telect.sync _|p, 0xFFFFFFFF;\n\tselp.b32 %0, 1, 0, p;\n\t}" : "=r"(pred));
    return pred;
}
#define MBARRIER_INIT(mbar, count) \
    asm volatile("mbarrier.init.shared.b64 [%0], %1;" :: "r"((uint32_t)(mbar)), "r"((uint32_t)(count)) : "memory")
#define MBARRIER_WAIT_PARITY(mbar_smem_addr, phase_parity) do { \
    uint32_t _mbar = (uint32_t)(mbar_smem_addr); \
    uint32_t _parity = (uint32_t)(phase_parity); \
    uint32_t _done; \
    asm volatile("{\n\t.reg .pred p;\n\tmbarrier.try_wait.parity.acquire.cta.shared::cta.b64 p, [%1], %2;\n\tselp.b32 %0, 1, 0, p;\n\t}" \
        : "=r"(_done) : "r"(_mbar), "r"(_parity) : "memory"); \
    if (!_done) { \
        asm volatile("{\n\t.reg .pred P1;\n\tWAIT_LOOP_%=:\n\t" \
            "mbarrier.try_wait.parity.acquire.cta.shared::cta.b64 P1, [%0], %1, 0x989680;\n\t" \
            "@P1 bra.uni WAIT_DONE_%=;\n\tbra.uni WAIT_LOOP_%=;\n\tWAIT_DONE_%=:\n\t}" \
            :: "r"(_mbar), "r"(_parity) : "memory"); \
    } \
} while(0)

#ifdef TCGEN05_OK
#define TCGEN05_ALLOC(smem_addr, nCols) \
    asm volatile("tcgen05.alloc.cta_group::1.sync.aligned.shared::cta.b32 [%0], %1;" \
        :: "r"((uint32_t)(smem_addr)), "r"((uint32_t)(nCols)) : "memory")
#define TCGEN05_DEALLOC(tmem_addr, nCols) \
    asm volatile("tcgen05.dealloc.cta_group::1.sync.aligned.b32 %0, %1;" :: "r"(tmem_addr), "r"((uint32_t)(nCols)))
#define TCGEN05_RELINQUISH() \
    asm volatile("tcgen05.relinquish_alloc_permit.cta_group::1.sync.aligned;")
#define TCGEN05_COMMIT(mbar) \
    asm volatile("tcgen05.commit.cta_group::1.mbarrier::arrive::one.shared::cluster.b64 [%0];" \
        :: "r"((uint32_t)(mbar)) : "memory")
#define TCGEN05_FENCE_AFTER()  asm volatile("tcgen05.fence::after_thread_sync;" ::: "memory")
#define TCGEN05_WAIT_LD()      asm volatile("tcgen05.wait::ld.sync.aligned;" ::: "memory")
#define TCGEN05_LD_32X32B_X32(r, tmem_addr) \
    asm volatile("tcgen05.ld.sync.aligned.32x32b.x32.b32 " \
        "{%0, %1, %2, %3, %4, %5, %6, %7, %8, %9, %10, %11, %12, %13, %14, %15, " \
        " %16, %17, %18, %19, %20, %21, %22, %23, %24, %25, %26, %27, %28, %29, %30, %31}, [%32];" \
        : "=r"((r)[0]),  "=r"((r)[1]),  "=r"((r)[2]),  "=r"((r)[3]), \
          "=r"((r)[4]),  "=r"((r)[5]),  "=r"((r)[6]),  "=r"((r)[7]), \
          "=r"((r)[8]),  "=r"((r)[9]),  "=r"((r)[10]), "=r"((r)[11]), \
          "=r"((r)[12]), "=r"((r)[13]), "=r"((r)[14]), "=r"((r)[15]), \
          "=r"((r)[16]), "=r"((r)[17]), "=r"((r)[18]), "=r"((r)[19]), \
          "=r"((r)[20]), "=r"((r)[21]), "=r"((r)[22]), "=r"((r)[23]), \
          "=r"((r)[24]), "=r"((r)[25]), "=r"((r)[26]), "=r"((r)[27]), \
          "=r"((r)[28]), "=r"((r)[29]), "=r"((r)[30]), "=r"((r)[31]) \
        : "r"(tmem_addr))

__device__ __forceinline__ void mma_f16_ss_cg1(uint32_t d, uint64_t a, uint64_t b,
                                               uint32_t idesc, uint32_t en) {
    asm volatile(
        "{\n\t.reg .pred p;\n\tsetp.ne.u32 p, %5, 0;\n\t"
        "tcgen05.mma.cta_group::1.kind::f16 [%0], %1, %2, %3, {%4,%4,%4,%4}, p;\n\t}"
        :: "r"(d), "l"(a), "l"(b), "r"(idesc), "r"(0u), "r"(en) : "memory");
}
#endif // TCGEN05_OK

static constexpr uint64_t SMEM_DESC_BASE_SW128 =
    (uint64_t(2)  << 61) | (uint64_t(1) << 46) | (uint64_t(64) << 32) | (uint64_t(1) << 16);
#define MAKE_SMEM_DESC(base_addr) (SMEM_DESC_BASE_SW128 | ((uint64_t)((base_addr) >> 4) & 0x3FFF))

// idesc kind::f16: dtype=F32, atype=btype=BF16, N=128, M=128
#define MMA_IDESC 0x8200490u

// ======================= tcgen05 GEMM =======================================
// C[M=8192,1024] = (Ahi+Alo)[M,1024] @ (Bhi+Blo)^T + bias   (B is N-major K-contig)
// tile 128x128, K-chunk 64 bf16 (=128B SW128 atom), 3-term split MMA.
#define NCHUNK 16               // 1024 / 64
#define TILE_BYTES 16384        // 128 rows x 128 B
#define BUF_BYTES  (4*TILE_BYTES)
#define SMEM_HDR   1024
#define GEMM_SMEM  (SMEM_HDR + 2*BUF_BYTES)   // 132096

__global__ __launch_bounds__(256, 1)
void gemm_tc_kernel(const __nv_bfloat16* __restrict__ Ahi,
                    const __nv_bfloat16* __restrict__ Alo,
                    const __nv_bfloat16* __restrict__ Bhi,
                    const __nv_bfloat16* __restrict__ Blo,
                    const float* __restrict__ bias,
                    float* __restrict__ C)
{
#ifdef TCGEN05_OK
    extern __shared__ char smem[];
    const uint32_t sbase = smem_to_u32(smem);
    const int tid = threadIdx.x;
    const int wid = tid >> 5;
    const int lid = tid & 31;
    const int bm = blockIdx.y * 128;
    const int bn = blockIdx.x * 128;

    if (wid == 0) TCGEN05_ALLOC(sbase + 0, 128);
    if (tid == 0) { MBARRIER_INIT(sbase + 16, 1); MBARRIER_INIT(sbase + 24, 1); }
    __syncthreads();
    uint32_t tmem;
    asm volatile("ld.shared.b32 %0, [%1];" : "=r"(tmem) : "r"(sbase + 0));

    for (int c = 0; c < NCHUNK; c++) {
        const int b = c & 1;
        if (c >= 2) MBARRIER_WAIT_PARITY(sbase + 16 + 8*b, ((c - 2) >> 1) & 1);
        const uint32_t buf = SMEM_HDR + b * BUF_BYTES;

        // load 4 tiles (Ahi, Alo, Bhi, Blo): 128 rows x 64 bf16 each, SW128-swizzled
#pragma unroll
        for (int t4 = 0; t4 < 4; t4++) {
            const __nv_bfloat16* src = (t4 == 0) ? Ahi : (t4 == 1) ? Alo : (t4 == 2) ? Bhi : Blo;
            const int rbase = (t4 < 2) ? bm : bn;
#pragma unroll
            for (int j = 0; j < 4; j++) {
                const int i = j * 256 + tid;
                const int r = i >> 3, g = i & 7;
                uint4 v = *reinterpret_cast<const uint4*>(
                    src + (((size_t)(rbase + r)) << 10) + c * 64 + g * 8);
                uint32_t off = (uint32_t)(r * 128 + g * 16);
                off ^= (off >> 3) & 0x70;
                *reinterpret_cast<uint4*>(smem + buf + t4 * TILE_BYTES + off) = v;
            }
        }
        __syncthreads();

        if (wid == 0) {
            TCGEN05_FENCE_AFTER();
            if (elect_one_pred()) {
                asm volatile("fence.proxy.async.shared::cta;" ::: "memory");
                const uint64_t dAh = MAKE_SMEM_DESC(sbase + buf + 0 * TILE_BYTES);
                const uint64_t dAl = MAKE_SMEM_DESC(sbase + buf + 1 * TILE_BYTES);
                const uint64_t dBh = MAKE_SMEM_DESC(sbase + buf + 2 * TILE_BYTES);
                const uint64_t dBl = MAKE_SMEM_DESC(sbase + buf + 3 * TILE_BYTES);
#pragma unroll
                for (int k = 0; k < 4; k++) {
                    mma_f16_ss_cg1(tmem, dAh + 2*k, dBh + 2*k, MMA_IDESC, (c > 0 || k > 0));
                    mma_f16_ss_cg1(tmem, dAh + 2*k, dBl + 2*k, MMA_IDESC, 1);
                    mma_f16_ss_cg1(tmem, dAl + 2*k, dBh + 2*k, MMA_IDESC, 1);
                }
                TCGEN05_COMMIT(sbase + 16 + 8*b);
            }
        }
    }

    // drain both buffers' final commits (8 commits each -> wait parity 1)
    MBARRIER_WAIT_PARITY(sbase + 16, 1);
    MBARRIER_WAIT_PARITY(sbase + 24, 1);
    TCGEN05_FENCE_AFTER();

    if (wid < 4) {
        const int row = bm + wid * 32 + lid;
#pragma unroll
        for (int base = 0; base < 128; base += 32) {
            uint32_t dreg[32];
            TCGEN05_LD_32X32B_X32(dreg, tmem + base);
            TCGEN05_WAIT_LD();
            float* cp = C + (size_t)row * EDIM + bn + base;
            const float* bp = bias + bn + base;
#pragma unroll
            for (int c4 = 0; c4 < 8; c4++) {
                float4 o;
                o.x = __uint_as_float(dreg[c4*4+0]) + bp[c4*4+0];
                o.y = __uint_as_float(dreg[c4*4+1]) + bp[c4*4+1];
                o.z = __uint_as_float(dreg[c4*4+2]) + bp[c4*4+2];
                o.w = __uint_as_float(dreg[c4*4+3]) + bp[c4*4+3];
                *reinterpret_cast<float4*>(cp + c4*4) = o;
            }
        }
    }
    __syncthreads();
    if (wid == 0) {
        TCGEN05_RELINQUISH();
        TCGEN05_DEALLOC(tmem, 128);
    }
#endif // TCGEN05_OK
}

// ---------------- fp32 -> bf16 hi/lo split ----------------------------------
__global__ __launch_bounds__(256)
void split_bf16_kernel(const float4* __restrict__ in,
                       uint2* __restrict__ hi, uint2* __restrict__ lo, int n4)
{
    const int i = blockIdx.x * blockDim.x + threadIdx.x;
    if (i >= n4) return;
    float4 v = in[i];
    __nv_bfloat16 h0 = __float2bfloat16_rn(v.x);
    __nv_bfloat16 h1 = __float2bfloat16_rn(v.y);
    __nv_bfloat16 h2 = __float2bfloat16_rn(v.z);
    __nv_bfloat16 h3 = __float2bfloat16_rn(v.w);
    __nv_bfloat16 l0 = __float2bfloat16_rn(v.x - __bfloat162float(h0));
    __nv_bfloat16 l1 = __float2bfloat16_rn(v.y - __bfloat162float(h1));
    __nv_bfloat16 l2 = __float2bfloat16_rn(v.z - __bfloat162float(h2));
    __nv_bfloat16 l3 = __float2bfloat16_rn(v.w - __bfloat162float(h3));
    uint2 ph, pl;
    ph.x = ((uint32_t)__bfloat16_as_ushort(h1) << 16) | __bfloat16_as_ushort(h0);
    ph.y = ((uint32_t)__bfloat16_as_ushort(h3) << 16) | __bfloat16_as_ushort(h2);
    pl.x = ((uint32_t)__bfloat16_as_ushort(l1) << 16) | __bfloat16_as_ushort(l0);
    pl.y = ((uint32_t)__bfloat16_as_ushort(l3) << 16) | __bfloat16_as_ushort(l2);
    hi[i] = ph;
    lo[i] = pl;
}

// ---------------- W [K,N] -> W^T hi/lo bf16 [N,K] ---------------------------
__global__ __launch_bounds__(256)
void transpose_split_kernel(const float* __restrict__ W,
                            __nv_bfloat16* __restrict__ Thi,
                            __nv_bfloat16* __restrict__ Tlo)
{
    __shared__ float tile[32][33];
    const int bx = blockIdx.x * 32;   // n
    const int by = blockIdx.y * 32;   // k
    const int tx = threadIdx.x, ty = threadIdx.y;
#pragma unroll
    for (int j = ty; j < 32; j += 8)
        tile[j][tx] = W[(size_t)(by + j) * EDIM + bx + tx];
    __syncthreads();
#pragma unroll
    for (int j = ty; j < 32; j += 8) {
        float v = tile[tx][j];        // = W[by+tx][bx+j]
        __nv_bfloat16 h = __float2bfloat16_rn(v);
        __nv_bfloat16 l = __float2bfloat16_rn(v - __bfloat162float(h));
        Thi[(size_t)(bx + j) * EDIM + by + tx] = h;
        Tlo[(size_t)(bx + j) * EDIM + by + tx] = l;
    }
}

// ---------------- cumprod(cos(x)) along last dim (1024) ---------------------
__global__ __launch_bounds__(1024)
void cumprod_cos_kernel(float* __restrict__ data)
{
    __shared__ float s[EDIM];
    const int row = blockIdx.x;
    const int t   = threadIdx.x;
    float v = cosf(data[(size_t)row * EDIM + t]);
    s[t] = v;
    __syncthreads();
#pragma unroll
    for (int off = 1; off < EDIM; off <<= 1) {
        float p = (t >= off) ? s[t - off] : 1.0f;
        __syncthreads();
        s[t] *= p;
        __syncthreads();
    }
    data[(size_t)row * EDIM + t] = s[t];
}

// ---------------- attention: thread-per-query online softmax ----------------
#define ATQ 128
#define ATK 64

__global__ __launch_bounds__(ATQ)
void attention_kernel(const float* __restrict__ Qm,
                      const float* __restrict__ Km,
                      const float* __restrict__ Vm,
                      float* __restrict__ O)
{
    __shared__ float Ks[ATK][HD];
    __shared__ float Vs[ATK][HD];

    const int t  = threadIdx.x;
    const int qb = blockIdx.x * ATQ;
    const int h  = blockIdx.y;
    const int b  = blockIdx.z;

    const int row = b * TQ + qb + t;
    const float* qptr = Qm + (size_t)row * EDIM + h * HD;

    float4 q[16];
#pragma unroll
    for (int c = 0; c < 16; c++) q[c] = reinterpret_cast<const float4*>(qptr)[c];

    float acc[64];
#pragma unroll
    for (int i = 0; i < 64; i++) acc[i] = 0.0f;
    float mval = -1e30f, lval = 0.0f;
    const float scale = 0.125f;

    for (int kb = 0; kb < TQ; kb += ATK) {
        for (int idx = t; idx < ATK * (HD / 4); idx += ATQ) {
            const int r = idx >> 4;
            const int c = idx & 15;
            const size_t gro = (size_t)(b * TQ + kb + r) * EDIM + h * HD;
            reinterpret_cast<float4*>(&Ks[r][0])[c] =
                reinterpret_cast<const float4*>(Km + gro)[c];
            reinterpret_cast<float4*>(&Vs[r][0])[c] =
                reinterpret_cast<const float4*>(Vm + gro)[c];
        }
        __syncthreads();

        for (int kk = 0; kk < ATK; kk++) {
            float s = 0.0f;
#pragma unroll
            for (int c = 0; c < 16; c++) {
                float4 kv = reinterpret_cast<const float4*>(&Ks[kk][0])[c];
                s = fmaf(q[c].x, kv.x, s);
                s = fmaf(q[c].y, kv.y, s);
                s = fmaf(q[c].z, kv.z, s);
                s = fmaf(q[c].w, kv.w, s);
            }
            s *= scale;
            if (s > mval) {
                float corr = __expf(mval - s);
                lval *= corr;
#pragma unroll
                for (int i = 0; i < 64; i++) acc[i] *= corr;
                mval = s;
            }
            float p = __expf(s - mval);
            lval += p;
#pragma unroll
            for (int c = 0; c < 16; c++) {
                float4 vv = reinterpret_cast<const float4*>(&Vs[kk][0])[c];
                acc[4 * c + 0] = fmaf(p, vv.x, acc[4 * c + 0]);
                acc[4 * c + 1] = fmaf(p, vv.y, acc[4 * c + 1]);
                acc[4 * c + 2] = fmaf(p, vv.z, acc[4 * c + 2]);
                acc[4 * c + 3] = fmaf(p, vv.w, acc[4 * c + 3]);
            }
        }
        __syncthreads();
    }

    const float inv = 1.0f / lval;
    float* op = O + (size_t)row * EDIM + h * HD;
#pragma unroll
    for (int c = 0; c < 16; c++) {
        float4 o;
        o.x = acc[4 * c + 0] * inv;
        o.y = acc[4 * c + 1] * inv;
        o.z = acc[4 * c + 2] * inv;
        o.w = acc[4 * c + 3] * inv;
        reinterpret_cast<float4*>(op)[c] = o;
    }
}

// ---------------- launch ----------------------------------------------------
extern "C" void kernel_launch(void* const* d_in, const int* in_sizes, int n_in,
                              void* d_out, int out_size)
{
    const float* x  = (const float*)d_in[0];
    const float* Wq = (const float*)d_in[1];
    const float* bq = (const float*)d_in[2];
    const float* Wk = (const float*)d_in[3];
    const float* bk = (const float*)d_in[4];
    const float* Wv = (const float*)d_in[5];
    const float* bv = (const float*)d_in[6];
    const float* Wo = (const float*)d_in[7];
    const float* bo = (const float*)d_in[8];
    float* out = (float*)d_out;

    float *q, *k, *v, *ao;
    __nv_bfloat16 *xhi, *xlo, *aohi, *aolo, *wthi, *wtlo;
    cudaGetSymbolAddress((void**)&q,    g_q);
    cudaGetSymbolAddress((void**)&k,    g_k);
    cudaGetSymbolAddress((void**)&v,    g_v);
    cudaGetSymbolAddress((void**)&ao,   g_ao);
    cudaGetSymbolAddress((void**)&xhi,  g_xhi);
    cudaGetSymbolAddress((void**)&xlo,  g_xlo);
    cudaGetSymbolAddress((void**)&aohi, g_aohi);
    cudaGetSymbolAddress((void**)&aolo, g_aolo);
    cudaGetSymbolAddress((void**)&wthi, g_wthi);
    cudaGetSymbolAddress((void**)&wtlo, g_wtlo);

    cudaFuncSetAttribute(gemm_tc_kernel, cudaFuncAttributeMaxDynamicSharedMemorySize, GEMM_SMEM);

    const int n4 = MROWS * EDIM / 4;
    split_bf16_kernel<<<(n4 + 255) / 256, 256>>>((const float4*)x, (uint2*)xhi, (uint2*)xlo, n4);

    dim3 tb(32, 8), tg(32, 32);
    transpose_split_kernel<<<tg, tb>>>(Wq, wthi + 0*EDIM*EDIM, wtlo + 0*EDIM*EDIM);
    transpose_split_kernel<<<tg, tb>>>(Wk, wthi + 1*EDIM*EDIM, wtlo + 1*EDIM*EDIM);
    transpose_split_kernel<<<tg, tb>>>(Wv, wthi + 2*EDIM*EDIM, wtlo + 2*EDIM*EDIM);
    transpose_split_kernel<<<tg, tb>>>(Wo, wthi + 3*EDIM*EDIM, wtlo + 3*EDIM*EDIM);

    dim3 gg(EDIM / 128, MROWS / 128);   // (8, 64)
    gemm_tc_kernel<<<gg, 256, GEMM_SMEM>>>(xhi, xlo, wthi + 0*EDIM*EDIM, wtlo + 0*EDIM*EDIM, bq, q);
    gemm_tc_kernel<<<gg, 256, GEMM_SMEM>>>(xhi, xlo, wthi + 1*EDIM*EDIM, wtlo + 1*EDIM*EDIM, bk, k);
    gemm_tc_kernel<<<gg, 256, GEMM_SMEM>>>(xhi, xlo, wthi + 2*EDIM*EDIM, wtlo + 2*EDIM*EDIM, bv, v);

    cumprod_cos_kernel<<<MROWS, 1024>>>(q);
    cumprod_cos_kernel<<<MROWS, 1024>>>(k);

    // reference role swap: query = quantum(k-proj), key = quantum(q-proj)
    dim3 ga(TQ / ATQ, NH, NB);
    attention_kernel<<<ga, ATQ>>>(k, q, v, ao);

    split_bf16_kernel<<<(n4 + 255) / 256, 256>>>((const float4*)ao, (uint2*)aohi, (uint2*)aolo, n4);
    gemm_tc_kernel<<<gg, 256, GEMM_SMEM>>>(aohi, aolo, wthi + 3*EDIM*EDIM, wtlo + 3*EDIM*EDIM, bo, out);
}

// round 8
// speedup vs baseline: 5.1337x; 3.5130x over previous
#include <cuda_runtime.h>
#include <cuda_bf16.h>
#include <math.h>
#include <stdint.h>

#define EDIM 1024
#define NH   16
#define HD   64
#define TQ   2048
#define NB   4
#define MROWS (NB*TQ)   // 8192

#if defined(__CUDA_ARCH_FEAT_SM103_ALL) || defined(__CUDA_ARCH_FEAT_SM100_ALL) || \
    defined(__CUDA_ARCH_FEAT_SM101_ALL) || defined(__CUDA_ARCH_SPECIFIC__)
#define TCGEN05_OK 1
#endif

// ---------------- scratch (device globals: no allocations allowed) ----------
__device__ float g_q [MROWS*EDIM];
__device__ float g_k [MROWS*EDIM];
__device__ float g_v [MROWS*EDIM];
__device__ __nv_bfloat16 g_xhi [MROWS*EDIM];
__device__ __nv_bfloat16 g_xlo [MROWS*EDIM];
__device__ __nv_bfloat16 g_qhi [MROWS*EDIM];
__device__ __nv_bfloat16 g_qlo [MROWS*EDIM];
__device__ __nv_bfloat16 g_khi [MROWS*EDIM];
__device__ __nv_bfloat16 g_klo [MROWS*EDIM];
__device__ __nv_bfloat16 g_vthi[MROWS*EDIM];   // V^T per (b,h): [64 d][2048 tok]
__device__ __nv_bfloat16 g_vtlo[MROWS*EDIM];
__device__ __nv_bfloat16 g_aohi[MROWS*EDIM];
__device__ __nv_bfloat16 g_aolo[MROWS*EDIM];
__device__ __nv_bfloat16 g_wthi[4*EDIM*EDIM];   // W^T (N-major rows, K contiguous)
__device__ __nv_bfloat16 g_wtlo[4*EDIM*EDIM];

// ======================= PTX helpers (sm_103a) ==============================
__device__ __forceinline__ uint32_t smem_to_u32(const void* p) {
    uint32_t a;
    asm("{ .reg .u64 t; cvta.to.shared.u64 t, %1; cvt.u32.u64 %0, t; }" : "=r"(a) : "l"(p));
    return a;
}
__device__ __forceinline__ uint32_t elect_one_pred() {
    uint32_t pred;
    asm volatile("{\n\t.reg .pred p;\n\telect.sync _|p, 0xFFFFFFFF;\n\tselp.b32 %0, 1, 0, p;\n\t}" : "=r"(pred));
    return pred;
}
#define MBARRIER_INIT(mbar, count) \
    asm volatile("mbarrier.init.shared.b64 [%0], %1;" :: "r"((uint32_t)(mbar)), "r"((uint32_t)(count)) : "memory")
#define MBARRIER_WAIT_PARITY(mbar_smem_addr, phase_parity) do { \
    uint32_t _mbar = (uint32_t)(mbar_smem_addr); \
    uint32_t _parity = (uint32_t)(phase_parity); \
    uint32_t _done; \
    asm volatile("{\n\t.reg .pred p;\n\tmbarrier.try_wait.parity.acquire.cta.shared::cta.b64 p, [%1], %2;\n\tselp.b32 %0, 1, 0, p;\n\t}" \
        : "=r"(_done) : "r"(_mbar), "r"(_parity) : "memory"); \
    if (!_done) { \
        asm volatile("{\n\t.reg .pred P1;\n\tWAIT_LOOP_%=:\n\t" \
            "mbarrier.try_wait.parity.acquire.cta.shared::cta.b64 P1, [%0], %1, 0x989680;\n\t" \
            "@P1 bra.uni WAIT_DONE_%=;\n\tbra.uni WAIT_LOOP_%=;\n\tWAIT_DONE_%=:\n\t}" \
            :: "r"(_mbar), "r"(_parity) : "memory"); \
    } \
} while(0)

#ifdef TCGEN05_OK
#define TCGEN05_ALLOC(smem_addr, nCols) \
    asm volatile("tcgen05.alloc.cta_group::1.sync.aligned.shared::cta.b32 [%0], %1;" \
        :: "r"((uint32_t)(smem_addr)), "r"((uint32_t)(nCols)) : "memory")
#define TCGEN05_DEALLOC(tmem_addr, nCols) \
    asm volatile("tcgen05.dealloc.cta_group::1.sync.aligned.b32 %0, %1;" :: "r"(tmem_addr), "r"((uint32_t)(nCols)))
#define TCGEN05_RELINQUISH() \
    asm volatile("tcgen05.relinquish_alloc_permit.cta_group::1.sync.aligned;")
#define TCGEN05_COMMIT(mbar) \
    asm volatile("tcgen05.commit.cta_group::1.mbarrier::arrive::one.shared::cluster.b64 [%0];" \
        :: "r"((uint32_t)(mbar)) : "memory")
#define TCGEN05_FENCE_BEFORE() asm volatile("tcgen05.fence::before_thread_sync;" ::: "memory")
#define TCGEN05_FENCE_AFTER()  asm volatile("tcgen05.fence::after_thread_sync;" ::: "memory")
#define TCGEN05_WAIT_LD()      asm volatile("tcgen05.wait::ld.sync.aligned;" ::: "memory")

#define TCGEN05_LD_32X32B_X32(r, tmem_addr) \
    asm volatile("tcgen05.ld.sync.aligned.32x32b.x32.b32 " \
        "{%0, %1, %2, %3, %4, %5, %6, %7, %8, %9, %10, %11, %12, %13, %14, %15, " \
        " %16, %17, %18, %19, %20, %21, %22, %23, %24, %25, %26, %27, %28, %29, %30, %31}, [%32];" \
        : "=r"((r)[0]),  "=r"((r)[1]),  "=r"((r)[2]),  "=r"((r)[3]), \
          "=r"((r)[4]),  "=r"((r)[5]),  "=r"((r)[6]),  "=r"((r)[7]), \
          "=r"((r)[8]),  "=r"((r)[9]),  "=r"((r)[10]), "=r"((r)[11]), \
          "=r"((r)[12]), "=r"((r)[13]), "=r"((r)[14]), "=r"((r)[15]), \
          "=r"((r)[16]), "=r"((r)[17]), "=r"((r)[18]), "=r"((r)[19]), \
          "=r"((r)[20]), "=r"((r)[21]), "=r"((r)[22]), "=r"((r)[23]), \
          "=r"((r)[24]), "=r"((r)[25]), "=r"((r)[26]), "=r"((r)[27]), \
          "=r"((r)[28]), "=r"((r)[29]), "=r"((r)[30]), "=r"((r)[31]) \
        : "r"(tmem_addr))

__device__ __forceinline__ void mma_f16_ss_cg1(uint32_t d, uint64_t a, uint64_t b,
                                               uint32_t idesc, uint32_t en) {
    asm volatile(
        "{\n\t.reg .pred p;\n\tsetp.ne.u32 p, %5, 0;\n\t"
        "tcgen05.mma.cta_group::1.kind::f16 [%0], %1, %2, %3, {%4,%4,%4,%4}, p;\n\t}"
        :: "r"(d), "l"(a), "l"(b), "r"(idesc), "r"(0u), "r"(en) : "memory");
}
#endif // TCGEN05_OK

// K-major SW128 descriptor (LBO=1, SBO=64)
static constexpr uint64_t SMEM_DESC_BASE_SW128 =
    (uint64_t(2)  << 61) | (uint64_t(1) << 46) | (uint64_t(64) << 32) | (uint64_t(1) << 16);
#define MAKE_SMEM_DESC(base_addr) (SMEM_DESC_BASE_SW128 | ((uint64_t)((base_addr) >> 4) & 0x3FFF))

// idesc kind::f16 bf16/F32: S (M=128,N=128), PV (M=128,N=64) — both K-major, no transpose
#define IDESC_S  0x8200490u
#define IDESC_PV 0x8100490u

// ======================= tcgen05 GEMM (validated R4) ========================
#define NCHUNK 16
#define TILE_BYTES 16384
#define BUF_BYTES  (4*TILE_BYTES)
#define SMEM_HDR   1024
#define GEMM_SMEM  (SMEM_HDR + 2*BUF_BYTES)

__global__ __launch_bounds__(256, 1)
void gemm_tc_kernel(const __nv_bfloat16* __restrict__ Ahi,
                    const __nv_bfloat16* __restrict__ Alo,
                    const __nv_bfloat16* __restrict__ Bhi,
                    const __nv_bfloat16* __restrict__ Blo,
                    const float* __restrict__ bias,
                    float* __restrict__ C)
{
#ifdef TCGEN05_OK
    extern __shared__ char smem[];
    const uint32_t sbase = smem_to_u32(smem);
    const int tid = threadIdx.x;
    const int wid = tid >> 5;
    const int lid = tid & 31;
    const int bm = blockIdx.y * 128;
    const int bn = blockIdx.x * 128;

    if (wid == 0) TCGEN05_ALLOC(sbase + 0, 128);
    if (tid == 0) { MBARRIER_INIT(sbase + 16, 1); MBARRIER_INIT(sbase + 24, 1); }
    __syncthreads();
    uint32_t tmem;
    asm volatile("ld.shared.b32 %0, [%1];" : "=r"(tmem) : "r"(sbase + 0));

    for (int c = 0; c < NCHUNK; c++) {
        const int b = c & 1;
        if (c >= 2) MBARRIER_WAIT_PARITY(sbase + 16 + 8*b, ((c - 2) >> 1) & 1);
        const uint32_t buf = SMEM_HDR + b * BUF_BYTES;

#pragma unroll
        for (int t4 = 0; t4 < 4; t4++) {
            const __nv_bfloat16* src = (t4 == 0) ? Ahi : (t4 == 1) ? Alo : (t4 == 2) ? Bhi : Blo;
            const int rbase = (t4 < 2) ? bm : bn;
#pragma unroll
            for (int j = 0; j < 4; j++) {
                const int i = j * 256 + tid;
                const int r = i >> 3, g = i & 7;
                uint4 v = *reinterpret_cast<const uint4*>(
                    src + (((size_t)(rbase + r)) << 10) + c * 64 + g * 8);
                uint32_t off = (uint32_t)(r * 128 + g * 16);
                off ^= (off >> 3) & 0x70;
                *reinterpret_cast<uint4*>(smem + buf + t4 * TILE_BYTES + off) = v;
            }
        }
        __syncthreads();

        if (wid == 0) {
            TCGEN05_FENCE_AFTER();
            if (elect_one_pred()) {
                asm volatile("fence.proxy.async.shared::cta;" ::: "memory");
                const uint64_t dAh = MAKE_SMEM_DESC(sbase + buf + 0 * TILE_BYTES);
                const uint64_t dAl = MAKE_SMEM_DESC(sbase + buf + 1 * TILE_BYTES);
                const uint64_t dBh = MAKE_SMEM_DESC(sbase + buf + 2 * TILE_BYTES);
                const uint64_t dBl = MAKE_SMEM_DESC(sbase + buf + 3 * TILE_BYTES);
#pragma unroll
                for (int k = 0; k < 4; k++) {
                    mma_f16_ss_cg1(tmem, dAh + 2*k, dBh + 2*k, IDESC_S, (c > 0 || k > 0));
                    mma_f16_ss_cg1(tmem, dAh + 2*k, dBl + 2*k, IDESC_S, 1);
                    mma_f16_ss_cg1(tmem, dAl + 2*k, dBh + 2*k, IDESC_S, 1);
                }
                TCGEN05_COMMIT(sbase + 16 + 8*b);
            }
        }
    }

    MBARRIER_WAIT_PARITY(sbase + 16, 1);
    MBARRIER_WAIT_PARITY(sbase + 24, 1);
    TCGEN05_FENCE_AFTER();

    if (wid < 4) {
        const int row = bm + wid * 32 + lid;
#pragma unroll
        for (int base = 0; base < 128; base += 32) {
            uint32_t dreg[32];
            TCGEN05_LD_32X32B_X32(dreg, tmem + base);
            TCGEN05_WAIT_LD();
            float* cp = C + (size_t)row * EDIM + bn + base;
            const float* bp = bias + bn + base;
#pragma unroll
            for (int c4 = 0; c4 < 8; c4++) {
                float4 o;
                o.x = __uint_as_float(dreg[c4*4+0]) + bp[c4*4+0];
                o.y = __uint_as_float(dreg[c4*4+1]) + bp[c4*4+1];
                o.z = __uint_as_float(dreg[c4*4+2]) + bp[c4*4+2];
                o.w = __uint_as_float(dreg[c4*4+3]) + bp[c4*4+3];
                *reinterpret_cast<float4*>(cp + c4*4) = o;
            }
        }
    }
    __syncthreads();
    if (wid == 0) {
        TCGEN05_RELINQUISH();
        TCGEN05_DEALLOC(tmem, 128);
    }
#endif
}

// ======================= tensor-core flash attention ========================
// No online max (|S| <= 8 guaranteed: Q,K entries are cumprods of cos, |.|<=1).
// S = 3-term hi/lo Q@K^T (SS, validated). P = exp(S*scale) written to SMEM
// K-major blocked-atom layout; PV = SS with pre-transposed V^T tiles.
// O accumulates in TMEM across all 16 K-tiles; single epilogue.
#define AT_LPART 1024
#define AT_QHI   2048
#define AT_QLO   (AT_QHI + 16384)
#define AT_PHI   (AT_QLO + 16384)            // 34816 ; P: 128q x 128k bf16 = 32KB each
#define AT_PLO   (AT_PHI + 32768)            // 67584
#define AT_BUF0  (AT_PLO + 32768)            // 100352 ; per buf: Khi,Klo,Vthi,Vtlo (16KB each)
#define AT_BUFSZ 65536
#define AT_SMEM_TOTAL (AT_BUF0 + 2*AT_BUFSZ) // 231424
// TMEM: S0 @0 (128 cols), S1 @128, O @256 (64 cols); alloc 512

__device__ __forceinline__ void at_load_tile(const __nv_bfloat16* g, int tok0, int colb,
                                             char* sdst, int tid)
{
#pragma unroll
    for (int j = 0; j < 4; j++) {
        const int i = j * 256 + tid;
        const int r = i >> 3, c8 = i & 7;
        uint4 v = *reinterpret_cast<const uint4*>(
            g + (((size_t)(tok0 + r)) << 10) + colb + c8 * 8);
        uint32_t off = (uint32_t)(r * 128 + c8 * 16);
        off ^= (off >> 3) & 0x70;
        *reinterpret_cast<uint4*>(sdst + off) = v;
    }
}

// V^T tile: 64 rows (d) x 128 tok, 256B/row -> blocked atoms (8 atom-rows x 2 atom-cols)
__device__ __forceinline__ void at_load_vt(const __nv_bfloat16* vt, int bh, int kb,
                                           char* sdst, int tid)
{
#pragma unroll
    for (int j = 0; j < 4; j++) {
        const int i = j * 256 + tid;
        const int r = i >> 4, c16 = i & 15;
        uint4 v = *reinterpret_cast<const uint4*>(
            vt + ((size_t)(bh * HD + r)) * TQ + kb + c16 * 8);
        uint32_t off = (uint32_t)((r >> 3) * 1024 + (c16 >> 3) * 8192 + (r & 7) * 128 + (c16 & 7) * 16);
        off ^= (off >> 3) & 0x70;
        *reinterpret_cast<uint4*>(sdst + off) = v;
    }
}

__global__ __launch_bounds__(256, 1)
void attention_tc_kernel(const __nv_bfloat16* __restrict__ Qhi_g,
                         const __nv_bfloat16* __restrict__ Qlo_g,
                         const __nv_bfloat16* __restrict__ Khi_g,
                         const __nv_bfloat16* __restrict__ Klo_g,
                         const __nv_bfloat16* __restrict__ Vthi_g,
                         const __nv_bfloat16* __restrict__ Vtlo_g,
                         __nv_bfloat16* __restrict__ Ohi_g,
                         __nv_bfloat16* __restrict__ Olo_g)
{
#ifdef TCGEN05_OK
    extern __shared__ char smem[];
    const uint32_t sbase = smem_to_u32(smem);
    const int tid = threadIdx.x;
    const int wid = tid >> 5;
    const int lid = tid & 31;
    const int b = blockIdx.z, h = blockIdx.y;
    const int bh = b * NH + h;
    const int tok0 = b * TQ + blockIdx.x * 128;
    const int colb = h * HD;
    const uint32_t mbarS = sbase + 16, mbarO = sbase + 24;

    if (wid == 0) TCGEN05_ALLOC(sbase + 0, 512);
    if (tid == 0) { MBARRIER_INIT(mbarS, 1); MBARRIER_INIT(mbarO, 1); }
    __syncthreads();
    uint32_t tmem;
    asm volatile("ld.shared.b32 %0, [%1];" : "=r"(tmem) : "r"(sbase + 0));

    // Q tiles + KV(0) into buf0
    at_load_tile(Qhi_g, tok0, colb, smem + AT_QHI, tid);
    at_load_tile(Qlo_g, tok0, colb, smem + AT_QLO, tid);
    {
        char* bufp = smem + AT_BUF0;
        at_load_tile(Khi_g, b * TQ, colb, bufp + 0*16384, tid);
        at_load_tile(Klo_g, b * TQ, colb, bufp + 1*16384, tid);
        at_load_vt(Vthi_g, bh, 0, bufp + 2*16384, tid);
        at_load_vt(Vtlo_g, bh, 0, bufp + 3*16384, tid);
    }
    __syncthreads();

    const uint64_t dQh = MAKE_SMEM_DESC(sbase + AT_QHI);
    const uint64_t dQl = MAKE_SMEM_DESC(sbase + AT_QLO);

    // issue S(0)
    if (wid == 0) {
        TCGEN05_FENCE_AFTER();
        if (elect_one_pred()) {
            asm volatile("fence.proxy.async.shared::cta;" ::: "memory");
            const uint64_t dKh = MAKE_SMEM_DESC(sbase + AT_BUF0 + 0*16384);
            const uint64_t dKl = MAKE_SMEM_DESC(sbase + AT_BUF0 + 1*16384);
#pragma unroll
            for (int k = 0; k < 4; k++) {
                mma_f16_ss_cg1(tmem + 0, dQh + 2*k, dKh + 2*k, IDESC_S, (k > 0));
                mma_f16_ss_cg1(tmem + 0, dQh + 2*k, dKl + 2*k, IDESC_S, 1);
                mma_f16_ss_cg1(tmem + 0, dQl + 2*k, dKh + 2*k, IDESC_S, 1);
            }
            TCGEN05_COMMIT(mbarS);
        }
    }

    const int subp = wid & 3;
    const int half = wid >> 2;
    const int qrow = subp * 32 + lid;
    const uint32_t loff = (uint32_t)subp << 21;
    float l_part = 0.0f;
    const float CEX = 0.125f * 1.44269504f;   // scale * log2(e)

    for (int t = 0; t < 16; t++) {
        // PV(t-1) must be done before: (a) softmax(t) overwrites P, (b) loads overwrite V(t+1 buf)
        if (t >= 1) MBARRIER_WAIT_PARITY(mbarO, (t - 1) & 1);

        if (t + 1 < 16) {
            char* bufp = smem + AT_BUF0 + ((t + 1) & 1) * AT_BUFSZ;
            const int kb = (t + 1) * 128;
            at_load_tile(Khi_g, b * TQ + kb, colb, bufp + 0*16384, tid);
            at_load_tile(Klo_g, b * TQ + kb, colb, bufp + 1*16384, tid);
            at_load_vt(Vthi_g, bh, kb, bufp + 2*16384, tid);
            at_load_vt(Vtlo_g, bh, kb, bufp + 3*16384, tid);
        }
        __syncthreads();

        // issue S(t+1) into Sbuf[(t+1)&1] — overlaps softmax(t)
        if (t + 1 < 16 && wid == 0) {
            TCGEN05_FENCE_AFTER();
            if (elect_one_pred()) {
                asm volatile("fence.proxy.async.shared::cta;" ::: "memory");
                const uint32_t buf2 = AT_BUF0 + ((t + 1) & 1) * AT_BUFSZ;
                const uint64_t dKh = MAKE_SMEM_DESC(sbase + buf2 + 0*16384);
                const uint64_t dKl = MAKE_SMEM_DESC(sbase + buf2 + 1*16384);
                const uint32_t sdst = tmem + ((t + 1) & 1) * 128;
#pragma unroll
                for (int k = 0; k < 4; k++) {
                    mma_f16_ss_cg1(sdst, dQh + 2*k, dKh + 2*k, IDESC_S, (k > 0));
                    mma_f16_ss_cg1(sdst, dQh + 2*k, dKl + 2*k, IDESC_S, 1);
                    mma_f16_ss_cg1(sdst, dQl + 2*k, dKh + 2*k, IDESC_S, 1);
                }
                TCGEN05_COMMIT(mbarS);
            }
        }

        // wait S(t)
        MBARRIER_WAIT_PARITY(mbarS, t & 1);
        TCGEN05_FENCE_AFTER();

        // softmax: 8 warps, each thread owns row qrow, columns [half*64, half*64+64)
        {
            const uint32_t sb = tmem + (t & 1) * 128 + half * 64 + loff;
            uint32_t r0[32], r1[32];
            TCGEN05_LD_32X32B_X32(r0, sb);
            TCGEN05_LD_32X32B_X32(r1, sb + 32);
            TCGEN05_WAIT_LD();
            float p[64];
            float psum = 0.0f;
#pragma unroll
            for (int j = 0; j < 32; j++) {
                float a0 = __uint_as_float(r0[j]) * CEX;
                float a1 = __uint_as_float(r1[j]) * CEX;
                float e0, e1;
                asm("ex2.approx.f32 %0, %1;" : "=f"(e0) : "f"(a0));
                asm("ex2.approx.f32 %0, %1;" : "=f"(e1) : "f"(a1));
                p[j] = e0; p[32 + j] = e1;
                psum += e0 + e1;
            }
            l_part += psum;

            // pack P hi/lo and store to blocked/swizzled SMEM
            uint32_t hiw[32], low[32];
#pragma unroll
            for (int j2 = 0; j2 < 32; j2++) {
                float p0 = p[2*j2], p1 = p[2*j2 + 1];
                uint32_t wh;
                asm("cvt.rn.bf16x2.f32 %0, %1, %2;" : "=r"(wh) : "f"(p1), "f"(p0));
                float h0 = __uint_as_float(wh << 16);
                float h1 = __uint_as_float(wh & 0xffff0000u);
                float q0 = p0 - h0, q1 = p1 - h1;
                uint32_t wl;
                asm("cvt.rn.bf16x2.f32 %0, %1, %2;" : "=r"(wl) : "f"(q1), "f"(q0));
                hiw[j2] = wh; low[j2] = wl;
            }
            const uint32_t prow = (uint32_t)((qrow >> 3) * 1024 + half * 16384 + (qrow & 7) * 128);
#pragma unroll
            for (int g = 0; g < 8; g++) {
                uint32_t off = prow + g * 16;
                off ^= (off >> 3) & 0x70;
                *reinterpret_cast<uint4*>(smem + AT_PHI + off) =
                    *reinterpret_cast<uint4*>(&hiw[g * 4]);
                *reinterpret_cast<uint4*>(smem + AT_PLO + off) =
                    *reinterpret_cast<uint4*>(&low[g * 4]);
            }
            TCGEN05_FENCE_BEFORE();
        }
        __syncthreads();

        // PV(t): O += Phi@Vthi + Phi@Vtlo + Plo@Vthi  (SS, K-major both sides)
        if (wid == 0) {
            TCGEN05_FENCE_AFTER();
            if (elect_one_pred()) {
                asm volatile("fence.proxy.async.shared::cta;" ::: "memory");
                const uint32_t buf = AT_BUF0 + (t & 1) * AT_BUFSZ;
                const uint64_t dPh = MAKE_SMEM_DESC(sbase + AT_PHI);
                const uint64_t dPl = MAKE_SMEM_DESC(sbase + AT_PLO);
                const uint64_t dVh = MAKE_SMEM_DESC(sbase + buf + 2*16384);
                const uint64_t dVl = MAKE_SMEM_DESC(sbase + buf + 3*16384);
#pragma unroll
                for (int s = 0; s < 8; s++) {
                    const uint64_t pa = (uint64_t)((s & 3) * 2 + (s >> 2) * 1024);
                    const uint64_t vb = (uint64_t)((s & 3) * 2 + (s >> 2) * 512);
                    mma_f16_ss_cg1(tmem + 256, dPh + pa, dVh + vb, IDESC_PV, (t > 0 || s > 0));
                    mma_f16_ss_cg1(tmem + 256, dPh + pa, dVl + vb, IDESC_PV, 1);
                    mma_f16_ss_cg1(tmem + 256, dPl + pa, dVh + vb, IDESC_PV, 1);
                }
                TCGEN05_COMMIT(mbarO);
            }
        }
    }

    // merge l halves
    *reinterpret_cast<float*>(smem + AT_LPART + (qrow * 2 + half) * 4) = l_part;
    __syncthreads();

    MBARRIER_WAIT_PARITY(mbarO, 1);
    TCGEN05_FENCE_AFTER();

    if (wid < 4) {
        const float lsum =
            *reinterpret_cast<float*>(smem + AT_LPART + (qrow * 2 + 0) * 4) +
            *reinterpret_cast<float*>(smem + AT_LPART + (qrow * 2 + 1) * 4);
        const float inv = 1.0f / lsum;
        uint32_t o0[32], o1[32];
        TCGEN05_LD_32X32B_X32(o0, tmem + 256 + loff);
        TCGEN05_LD_32X32B_X32(o1, tmem + 288 + loff);
        TCGEN05_WAIT_LD();
        uint32_t hibuf[32], lobuf[32];
#pragma unroll
        for (int c = 0; c < 32; c++) {
            float f0 = __uint_as_float(c < 16 ? o0[2*c]   : o1[2*(c-16)])   * inv;
            float f1 = __uint_as_float(c < 16 ? o0[2*c+1] : o1[2*(c-16)+1]) * inv;
            uint32_t wh;
            asm("cvt.rn.bf16x2.f32 %0, %1, %2;" : "=r"(wh) : "f"(f1), "f"(f0));
            float h0 = __uint_as_float(wh << 16);
            float h1 = __uint_as_float(wh & 0xffff0000u);
            float q0 = f0 - h0, q1 = f1 - h1;
            uint32_t wl;
            asm("cvt.rn.bf16x2.f32 %0, %1, %2;" : "=r"(wl) : "f"(q1), "f"(q0));
            hibuf[c] = wh; lobuf[c] = wl;
        }
        const size_t rowoff = (((size_t)(tok0 + qrow)) << 10) + colb;
#pragma unroll
        for (int v4 = 0; v4 < 8; v4++) {
            *reinterpret_cast<uint4*>(Ohi_g + rowoff + v4 * 8) =
                *reinterpret_cast<uint4*>(&hibuf[v4 * 4]);
            *reinterpret_cast<uint4*>(Olo_g + rowoff + v4 * 8) =
                *reinterpret_cast<uint4*>(&lobuf[v4 * 4]);
        }
    }
    __syncthreads();
    if (wid == 0) {
        TCGEN05_RELINQUISH();
        TCGEN05_DEALLOC(tmem, 512);
    }
#endif
}

// ---------------- fp32 -> bf16 hi/lo split ----------------------------------
__global__ __launch_bounds__(256)
void split_bf16_kernel(const float4* __restrict__ in,
                       uint2* __restrict__ hi, uint2* __restrict__ lo, int n4)
{
    const int i = blockIdx.x * blockDim.x + threadIdx.x;
    if (i >= n4) return;
    float4 v = in[i];
    __nv_bfloat16 h0 = __float2bfloat16_rn(v.x);
    __nv_bfloat16 h1 = __float2bfloat16_rn(v.y);
    __nv_bfloat16 h2 = __float2bfloat16_rn(v.z);
    __nv_bfloat16 h3 = __float2bfloat16_rn(v.w);
    __nv_bfloat16 l0 = __float2bfloat16_rn(v.x - __bfloat162float(h0));
    __nv_bfloat16 l1 = __float2bfloat16_rn(v.y - __bfloat162float(h1));
    __nv_bfloat16 l2 = __float2bfloat16_rn(v.z - __bfloat162float(h2));
    __nv_bfloat16 l3 = __float2bfloat16_rn(v.w - __bfloat162float(h3));
    uint2 ph, pl;
    ph.x = ((uint32_t)__bfloat16_as_ushort(h1) << 16) | __bfloat16_as_ushort(h0);
    ph.y = ((uint32_t)__bfloat16_as_ushort(h3) << 16) | __bfloat16_as_ushort(h2);
    pl.x = ((uint32_t)__bfloat16_as_ushort(l1) << 16) | __bfloat16_as_ushort(l0);
    pl.y = ((uint32_t)__bfloat16_as_ushort(l3) << 16) | __bfloat16_as_ushort(l2);
    hi[i] = ph;
    lo[i] = pl;
}

// ---------------- W [K,N] -> W^T hi/lo bf16 [N,K] ---------------------------
__global__ __launch_bounds__(256)
void transpose_split_kernel(const float* __restrict__ W,
                            __nv_bfloat16* __restrict__ Thi,
                            __nv_bfloat16* __restrict__ Tlo)
{
    __shared__ float tile[32][33];
    const int bx = blockIdx.x * 32;
    const int by = blockIdx.y * 32;
    const int tx = threadIdx.x, ty = threadIdx.y;
#pragma unroll
    for (int j = ty; j < 32; j += 8)
        tile[j][tx] = W[(size_t)(by + j) * EDIM + bx + tx];
    __syncthreads();
#pragma unroll
    for (int j = ty; j < 32; j += 8) {
        float v = tile[tx][j];
        __nv_bfloat16 h = __float2bfloat16_rn(v);
        __nv_bfloat16 l = __float2bfloat16_rn(v - __bfloat162float(h));
        Thi[(size_t)(bx + j) * EDIM + by + tx] = h;
        Tlo[(size_t)(bx + j) * EDIM + by + tx] = l;
    }
}

// ---------------- V [tok, E] -> per-(b,h) V^T hi/lo [d, tok] -----------------
__global__ __launch_bounds__(256)
void transpose_v_kernel(const float* __restrict__ V,
                        __nv_bfloat16* __restrict__ Thi,
                        __nv_bfloat16* __restrict__ Tlo)
{
    __shared__ float tile[32][33];
    const int bhid = blockIdx.z;            // b*NH + h
    const int bb = bhid / NH, hh = bhid % NH;
    const int tokb = blockIdx.x * 32;
    const int db = blockIdx.y * 32;
    const int tx = threadIdx.x, ty = threadIdx.y;
#pragma unroll
    for (int j = ty; j < 32; j += 8)
        tile[j][tx] = V[(size_t)(bb * TQ + tokb + j) * EDIM + hh * HD + db + tx];
    __syncthreads();
#pragma unroll
    for (int j = ty; j < 32; j += 8) {
        float v = tile[tx][j];              // V[tok=tokb+tx][d=db+j]
        __nv_bfloat16 h = __float2bfloat16_rn(v);
        __nv_bfloat16 l = __float2bfloat16_rn(v - __bfloat162float(h));
        const size_t o = (size_t)(bhid * HD + db + j) * TQ + tokb + tx;
        Thi[o] = h;
        Tlo[o] = l;
    }
}

// ---------------- cumprod(cos(x)) -> bf16 hi/lo ------------------------------
__global__ __launch_bounds__(1024)
void cumprod_cos_split_kernel(const float* __restrict__ in,
                              __nv_bfloat16* __restrict__ hi,
                              __nv_bfloat16* __restrict__ lo)
{
    __shared__ float s[EDIM];
    const int row = blockIdx.x;
    const int t   = threadIdx.x;
    float v = cosf(in[(size_t)row * EDIM + t]);
    s[t] = v;
    __syncthreads();
#pragma unroll
    for (int off = 1; off < EDIM; off <<= 1) {
        float p = (t >= off) ? s[t - off] : 1.0f;
        __syncthreads();
        s[t] *= p;
        __syncthreads();
    }
    const float f = s[t];
    const __nv_bfloat16 hb = __float2bfloat16_rn(f);
    hi[(size_t)row * EDIM + t] = hb;
    lo[(size_t)row * EDIM + t] = __float2bfloat16_rn(f - __bfloat162float(hb));
}

// ---------------- launch ----------------------------------------------------
extern "C" void kernel_launch(void* const* d_in, const int* in_sizes, int n_in,
                              void* d_out, int out_size)
{
    const float* x  = (const float*)d_in[0];
    const float* Wq = (const float*)d_in[1];
    const float* bq = (const float*)d_in[2];
    const float* Wk = (const float*)d_in[3];
    const float* bk = (const float*)d_in[4];
    const float* Wv = (const float*)d_in[5];
    const float* bv = (const float*)d_in[6];
    const float* Wo = (const float*)d_in[7];
    const float* bo = (const float*)d_in[8];
    float* out = (float*)d_out;

    float *q, *k, *v;
    __nv_bfloat16 *xhi, *xlo, *qhi, *qlo, *khi, *klo, *vthi, *vtlo, *aohi, *aolo, *wthi, *wtlo;
    cudaGetSymbolAddress((void**)&q,    g_q);
    cudaGetSymbolAddress((void**)&k,    g_k);
    cudaGetSymbolAddress((void**)&v,    g_v);
    cudaGetSymbolAddress((void**)&xhi,  g_xhi);
    cudaGetSymbolAddress((void**)&xlo,  g_xlo);
    cudaGetSymbolAddress((void**)&qhi,  g_qhi);
    cudaGetSymbolAddress((void**)&qlo,  g_qlo);
    cudaGetSymbolAddress((void**)&khi,  g_khi);
    cudaGetSymbolAddress((void**)&klo,  g_klo);
    cudaGetSymbolAddress((void**)&vthi, g_vthi);
    cudaGetSymbolAddress((void**)&vtlo, g_vtlo);
    cudaGetSymbolAddress((void**)&aohi, g_aohi);
    cudaGetSymbolAddress((void**)&aolo, g_aolo);
    cudaGetSymbolAddress((void**)&wthi, g_wthi);
    cudaGetSymbolAddress((void**)&wtlo, g_wtlo);

    cudaFuncSetAttribute(gemm_tc_kernel, cudaFuncAttributeMaxDynamicSharedMemorySize, GEMM_SMEM);
    cudaFuncSetAttribute(attention_tc_kernel, cudaFuncAttributeMaxDynamicSharedMemorySize, AT_SMEM_TOTAL);

    const int n4 = MROWS * EDIM / 4;
    split_bf16_kernel<<<(n4 + 255) / 256, 256>>>((const float4*)x, (uint2*)xhi, (uint2*)xlo, n4);

    dim3 tb(32, 8), tg(32, 32);
    transpose_split_kernel<<<tg, tb>>>(Wq, wthi + 0*EDIM*EDIM, wtlo + 0*EDIM*EDIM);
    transpose_split_kernel<<<tg, tb>>>(Wk, wthi + 1*EDIM*EDIM, wtlo + 1*EDIM*EDIM);
    transpose_split_kernel<<<tg, tb>>>(Wv, wthi + 2*EDIM*EDIM, wtlo + 2*EDIM*EDIM);
    transpose_split_kernel<<<tg, tb>>>(Wo, wthi + 3*EDIM*EDIM, wtlo + 3*EDIM*EDIM);

    dim3 gg(EDIM / 128, MROWS / 128);
    gemm_tc_kernel<<<gg, 256, GEMM_SMEM>>>(xhi, xlo, wthi + 0*EDIM*EDIM, wtlo + 0*EDIM*EDIM, bq, q);
    gemm_tc_kernel<<<gg, 256, GEMM_SMEM>>>(xhi, xlo, wthi + 1*EDIM*EDIM, wtlo + 1*EDIM*EDIM, bk, k);
    gemm_tc_kernel<<<gg, 256, GEMM_SMEM>>>(xhi, xlo, wthi + 2*EDIM*EDIM, wtlo + 2*EDIM*EDIM, bv, v);

    cumprod_cos_split_kernel<<<MROWS, 1024>>>(q, qhi, qlo);
    cumprod_cos_split_kernel<<<MROWS, 1024>>>(k, khi, klo);

    dim3 tgv(TQ / 32, HD / 32, NB * NH);
    transpose_v_kernel<<<tgv, tb>>>(v, vthi, vtlo);

    // role swap: attention-Q = quantum(k-proj), attention-K = quantum(q-proj)
    dim3 ga(TQ / 128, NH, NB);
    attention_tc_kernel<<<ga, 256, AT_SMEM_TOTAL>>>(khi, klo, qhi, qlo, vthi, vtlo, aohi, aolo);

    gemm_tc_kernel<<<gg, 256, GEMM_SMEM>>>(aohi, aolo, wthi + 3*EDIM*EDIM, wtlo + 3*EDIM*EDIM, bo, out);
}

// round 10
// speedup vs baseline: 5.5603x; 1.0831x over previous
#include <cuda_runtime.h>
#include <cuda_bf16.h>
#include <math.h>
#include <stdint.h>

#define EDIM 1024
#define NH   16
#define HD   64
#define TQ   2048
#define NB   4
#define MROWS (NB*TQ)   // 8192

#if defined(__CUDA_ARCH_FEAT_SM103_ALL) || defined(__CUDA_ARCH_FEAT_SM100_ALL) || \
    defined(__CUDA_ARCH_FEAT_SM101_ALL) || defined(__CUDA_ARCH_SPECIFIC__)
#define TCGEN05_OK 1
#endif

// ---------------- scratch (device globals: no allocations allowed) ----------
__device__ float g_q [MROWS*EDIM];
__device__ float g_k [MROWS*EDIM];
__device__ __nv_bfloat16 g_xhi [MROWS*EDIM];
__device__ __nv_bfloat16 g_xlo [MROWS*EDIM];
__device__ __nv_bfloat16 g_qhi [MROWS*EDIM];
__device__ __nv_bfloat16 g_qlo [MROWS*EDIM];
__device__ __nv_bfloat16 g_khi [MROWS*EDIM];
__device__ __nv_bfloat16 g_klo [MROWS*EDIM];
__device__ __nv_bfloat16 g_vthi[MROWS*EDIM];   // V^T per (b,h): [64 d][2048 tok]
__device__ __nv_bfloat16 g_vtlo[MROWS*EDIM];
__device__ __nv_bfloat16 g_aohi[MROWS*EDIM];
__device__ __nv_bfloat16 g_aolo[MROWS*EDIM];
__device__ __nv_bfloat16 g_wthi[4*EDIM*EDIM];   // W^T (N-major rows, K contiguous)
__device__ __nv_bfloat16 g_wtlo[4*EDIM*EDIM];

// ======================= PTX helpers (sm_103a) ==============================
__device__ __forceinline__ uint32_t smem_to_u32(const void* p) {
    uint32_t a;
    asm("{ .reg .u64 t; cvta.to.shared.u64 t, %1; cvt.u32.u64 %0, t; }" : "=r"(a) : "l"(p));
    return a;
}
__device__ __forceinline__ uint32_t elect_one_pred() {
    uint32_t pred;
    asm volatile("{\n\t.reg .pred p;\n\telect.sync _|p, 0xFFFFFFFF;\n\tselp.b32 %0, 1, 0, p;\n\t}" : "=r"(pred));
    return pred;
}
#define MBARRIER_INIT(mbar, count) \
    asm volatile("mbarrier.init.shared.b64 [%0], %1;" :: "r"((uint32_t)(mbar)), "r"((uint32_t)(count)) : "memory")
#define MBARRIER_WAIT_PARITY(mbar_smem_addr, phase_parity) do { \
    uint32_t _mbar = (uint32_t)(mbar_smem_addr); \
    uint32_t _parity = (uint32_t)(phase_parity); \
    uint32_t _done; \
    asm volatile("{\n\t.reg .pred p;\n\tmbarrier.try_wait.parity.acquire.cta.shared::cta.b64 p, [%1], %2;\n\tselp.b32 %0, 1, 0, p;\n\t}" \
        : "=r"(_done) : "r"(_mbar), "r"(_parity) : "memory"); \
    if (!_done) { \
        asm volatile("{\n\t.reg .pred P1;\n\tWAIT_LOOP_%=:\n\t" \
            "mbarrier.try_wait.parity.acquire.cta.shared::cta.b64 P1, [%0], %1, 0x989680;\n\t" \
            "@P1 bra.uni WAIT_DONE_%=;\n\tbra.uni WAIT_LOOP_%=;\n\tWAIT_DONE_%=:\n\t}" \
            :: "r"(_mbar), "r"(_parity) : "memory"); \
    } \
} while(0)

#ifdef TCGEN05_OK
#define TCGEN05_ALLOC(smem_addr, nCols) \
    asm volatile("tcgen05.alloc.cta_group::1.sync.aligned.shared::cta.b32 [%0], %1;" \
        :: "r"((uint32_t)(smem_addr)), "r"((uint32_t)(nCols)) : "memory")
#define TCGEN05_DEALLOC(tmem_addr, nCols) \
    asm volatile("tcgen05.dealloc.cta_group::1.sync.aligned.b32 %0, %1;" :: "r"(tmem_addr), "r"((uint32_t)(nCols)))
#define TCGEN05_RELINQUISH() \
    asm volatile("tcgen05.relinquish_alloc_permit.cta_group::1.sync.aligned;")
#define TCGEN05_COMMIT(mbar) \
    asm volatile("tcgen05.commit.cta_group::1.mbarrier::arrive::one.shared::cluster.b64 [%0];" \
        :: "r"((uint32_t)(mbar)) : "memory")
#define TCGEN05_FENCE_BEFORE() asm volatile("tcgen05.fence::before_thread_sync;" ::: "memory")
#define TCGEN05_FENCE_AFTER()  asm volatile("tcgen05.fence::after_thread_sync;" ::: "memory")
#define TCGEN05_WAIT_LD()      asm volatile("tcgen05.wait::ld.sync.aligned;" ::: "memory")

#define TCGEN05_LD_32X32B_X32(r, tmem_addr) \
    asm volatile("tcgen05.ld.sync.aligned.32x32b.x32.b32 " \
        "{%0, %1, %2, %3, %4, %5, %6, %7, %8, %9, %10, %11, %12, %13, %14, %15, " \
        " %16, %17, %18, %19, %20, %21, %22, %23, %24, %25, %26, %27, %28, %29, %30, %31}, [%32];" \
        : "=r"((r)[0]),  "=r"((r)[1]),  "=r"((r)[2]),  "=r"((r)[3]), \
          "=r"((r)[4]),  "=r"((r)[5]),  "=r"((r)[6]),  "=r"((r)[7]), \
          "=r"((r)[8]),  "=r"((r)[9]),  "=r"((r)[10]), "=r"((r)[11]), \
          "=r"((r)[12]), "=r"((r)[13]), "=r"((r)[14]), "=r"((r)[15]), \
          "=r"((r)[16]), "=r"((r)[17]), "=r"((r)[18]), "=r"((r)[19]), \
          "=r"((r)[20]), "=r"((r)[21]), "=r"((r)[22]), "=r"((r)[23]), \
          "=r"((r)[24]), "=r"((r)[25]), "=r"((r)[26]), "=r"((r)[27]), \
          "=r"((r)[28]), "=r"((r)[29]), "=r"((r)[30]), "=r"((r)[31]) \
        : "r"(tmem_addr))

__device__ __forceinline__ void mma_f16_ss_cg1(uint32_t d, uint64_t a, uint64_t b,
                                               uint32_t idesc, uint32_t en) {
    asm volatile(
        "{\n\t.reg .pred p;\n\tsetp.ne.u32 p, %5, 0;\n\t"
        "tcgen05.mma.cta_group::1.kind::f16 [%0], %1, %2, %3, {%4,%4,%4,%4}, p;\n\t}"
        :: "r"(d), "l"(a), "l"(b), "r"(idesc), "r"(0u), "r"(en) : "memory");
}
#endif // TCGEN05_OK

// K-major SW128 descriptor (LBO=1, SBO=64)
static constexpr uint64_t SMEM_DESC_BASE_SW128 =
    (uint64_t(2)  << 61) | (uint64_t(1) << 46) | (uint64_t(64) << 32) | (uint64_t(1) << 16);
#define MAKE_SMEM_DESC(base_addr) (SMEM_DESC_BASE_SW128 | ((uint64_t)((base_addr) >> 4) & 0x3FFF))

// idesc kind::f16 bf16/F32: S (M=128,N=128), PV (M=128,N=64) — K-major, no transpose
#define IDESC_S  0x8200490u
#define IDESC_PV 0x8100490u

// ======================= tcgen05 GEMM (3-stage pipeline) ====================
#define NCHUNK 16
#define TILE_BYTES 16384
#define BUF_BYTES  (4*TILE_BYTES)
#define SMEM_HDR   1024
#define NSTAGE 3
#define GEMM_SMEM  (SMEM_HDR + NSTAGE*BUF_BYTES)   // 197632

// VT=0: C = A@B^T + bias (fp32). VT=1: V-mode — write V^T bf16 hi/lo instead.
template<int VT>
__global__ __launch_bounds__(256, 1)
void gemm_tc_kernel(const __nv_bfloat16* __restrict__ Ahi,
                    const __nv_bfloat16* __restrict__ Alo,
                    const __nv_bfloat16* __restrict__ Bhi,
                    const __nv_bfloat16* __restrict__ Blo,
                    const float* __restrict__ bias,
                    float* __restrict__ C,
                    __nv_bfloat16* __restrict__ Vthi,
                    __nv_bfloat16* __restrict__ Vtlo)
{
#ifdef TCGEN05_OK
    extern __shared__ char smem[];
    const uint32_t sbase = smem_to_u32(smem);
    const int tid = threadIdx.x;
    const int wid = tid >> 5;
    const int lid = tid & 31;
    const int bm = blockIdx.y * 128;
    const int bn = blockIdx.x * 128;

    if (wid == 0) TCGEN05_ALLOC(sbase + 0, 128);
    if (tid == 0) {
        MBARRIER_INIT(sbase + 16, 1);
        MBARRIER_INIT(sbase + 24, 1);
        MBARRIER_INIT(sbase + 32, 1);
    }
    __syncthreads();
    uint32_t tmem;
    asm volatile("ld.shared.b32 %0, [%1];" : "=r"(tmem) : "r"(sbase + 0));

    int ph0 = 0, ph1 = 0, ph2 = 0;
    for (int c = 0; c < NCHUNK; c++) {
        const int b = c % NSTAGE;
        if (c >= NSTAGE) {
            if (b == 0)      { MBARRIER_WAIT_PARITY(sbase + 16, ph0); ph0 ^= 1; }
            else if (b == 1) { MBARRIER_WAIT_PARITY(sbase + 24, ph1); ph1 ^= 1; }
            else             { MBARRIER_WAIT_PARITY(sbase + 32, ph2); ph2 ^= 1; }
        }
        const uint32_t buf = SMEM_HDR + b * BUF_BYTES;

#pragma unroll
        for (int t4 = 0; t4 < 4; t4++) {
            const __nv_bfloat16* src = (t4 == 0) ? Ahi : (t4 == 1) ? Alo : (t4 == 2) ? Bhi : Blo;
            const int rbase = (t4 < 2) ? bm : bn;
#pragma unroll
            for (int j = 0; j < 4; j++) {
                const int i = j * 256 + tid;
                const int r = i >> 3, g = i & 7;
                uint4 v = *reinterpret_cast<const uint4*>(
                    src + (((size_t)(rbase + r)) << 10) + c * 64 + g * 8);
                uint32_t off = (uint32_t)(r * 128 + g * 16);
                off ^= (off >> 3) & 0x70;
                *reinterpret_cast<uint4*>(smem + buf + t4 * TILE_BYTES + off) = v;
            }
        }
        __syncthreads();

        if (wid == 0) {
            TCGEN05_FENCE_AFTER();
            if (elect_one_pred()) {
                asm volatile("fence.proxy.async.shared::cta;" ::: "memory");
                const uint64_t dAh = MAKE_SMEM_DESC(sbase + buf + 0 * TILE_BYTES);
                const uint64_t dAl = MAKE_SMEM_DESC(sbase + buf + 1 * TILE_BYTES);
                const uint64_t dBh = MAKE_SMEM_DESC(sbase + buf + 2 * TILE_BYTES);
                const uint64_t dBl = MAKE_SMEM_DESC(sbase + buf + 3 * TILE_BYTES);
#pragma unroll
                for (int k = 0; k < 4; k++) {
                    mma_f16_ss_cg1(tmem, dAh + 2*k, dBh + 2*k, IDESC_S, (c > 0 || k > 0));
                    mma_f16_ss_cg1(tmem, dAh + 2*k, dBl + 2*k, IDESC_S, 1);
                    mma_f16_ss_cg1(tmem, dAl + 2*k, dBh + 2*k, IDESC_S, 1);
                }
                TCGEN05_COMMIT(sbase + 16 + 8*b);
            }
        }
    }

    // drain outstanding commits (one per buffer)
    MBARRIER_WAIT_PARITY(sbase + 16, ph0);
    MBARRIER_WAIT_PARITY(sbase + 24, ph1);
    MBARRIER_WAIT_PARITY(sbase + 32, ph2);
    TCGEN05_FENCE_AFTER();

    if (wid < 4) {
        const int row = bm + wid * 32 + lid;
#pragma unroll
        for (int base = 0; base < 128; base += 32) {
            uint32_t dreg[32];
            TCGEN05_LD_32X32B_X32(dreg, tmem + base);
            TCGEN05_WAIT_LD();
            if (VT == 0) {
                float* cp = C + (size_t)row * EDIM + bn + base;
                const float* bp = bias + bn + base;
#pragma unroll
                for (int c4 = 0; c4 < 8; c4++) {
                    float4 o;
                    o.x = __uint_as_float(dreg[c4*4+0]) + bp[c4*4+0];
                    o.y = __uint_as_float(dreg[c4*4+1]) + bp[c4*4+1];
                    o.z = __uint_as_float(dreg[c4*4+2]) + bp[c4*4+2];
                    o.w = __uint_as_float(dreg[c4*4+3]) + bp[c4*4+3];
                    *reinterpret_cast<float4*>(cp + c4*4) = o;
                }
            } else {
                const int bb  = row >> 11;
                const int tok = row & (TQ - 1);
#pragma unroll
                for (int j = 0; j < 32; j++) {
                    const int colg = bn + base + j;
                    const float f = __uint_as_float(dreg[j]) + bias[colg];
                    const __nv_bfloat16 hh = __float2bfloat16_rn(f);
                    const __nv_bfloat16 ll = __float2bfloat16_rn(f - __bfloat162float(hh));
                    const size_t dst = ((size_t)((bb * NH + (colg >> 6)) * HD + (colg & 63))) * TQ + tok;
                    Vthi[dst] = hh;
                    Vtlo[dst] = ll;
                }
            }
        }
    }
    __syncthreads();
    if (wid == 0) {
        TCGEN05_RELINQUISH();
        TCGEN05_DEALLOC(tmem, 128);
    }
#endif
}

// ======================= tensor-core flash attention (R7, validated) ========
#define AT_LPART 1024
#define AT_QHI   2048
#define AT_QLO   (AT_QHI + 16384)
#define AT_PHI   (AT_QLO + 16384)
#define AT_PLO   (AT_PHI + 32768)
#define AT_BUF0  (AT_PLO + 32768)
#define AT_BUFSZ 65536
#define AT_SMEM_TOTAL (AT_BUF0 + 2*AT_BUFSZ)   // 231424

__device__ __forceinline__ void at_load_tile(const __nv_bfloat16* g, int tok0, int colb,
                                             char* sdst, int tid)
{
#pragma unroll
    for (int j = 0; j < 4; j++) {
        const int i = j * 256 + tid;
        const int r = i >> 3, c8 = i & 7;
        uint4 v = *reinterpret_cast<const uint4*>(
            g + (((size_t)(tok0 + r)) << 10) + colb + c8 * 8);
        uint32_t off = (uint32_t)(r * 128 + c8 * 16);
        off ^= (off >> 3) & 0x70;
        *reinterpret_cast<uint4*>(sdst + off) = v;
    }
}

__device__ __forceinline__ void at_load_vt(const __nv_bfloat16* vt, int bh, int kb,
                                           char* sdst, int tid)
{
#pragma unroll
    for (int j = 0; j < 4; j++) {
        const int i = j * 256 + tid;
        const int r = i >> 4, c16 = i & 15;
        uint4 v = *reinterpret_cast<const uint4*>(
            vt + ((size_t)(bh * HD + r)) * TQ + kb + c16 * 8);
        uint32_t off = (uint32_t)((r >> 3) * 1024 + (c16 >> 3) * 8192 + (r & 7) * 128 + (c16 & 7) * 16);
        off ^= (off >> 3) & 0x70;
        *reinterpret_cast<uint4*>(sdst + off) = v;
    }
}

__global__ __launch_bounds__(256, 1)
void attention_tc_kernel(const __nv_bfloat16* __restrict__ Qhi_g,
                         const __nv_bfloat16* __restrict__ Qlo_g,
                         const __nv_bfloat16* __restrict__ Khi_g,
                         const __nv_bfloat16* __restrict__ Klo_g,
                         const __nv_bfloat16* __restrict__ Vthi_g,
                         const __nv_bfloat16* __restrict__ Vtlo_g,
                         __nv_bfloat16* __restrict__ Ohi_g,
                         __nv_bfloat16* __restrict__ Olo_g)
{
#ifdef TCGEN05_OK
    extern __shared__ char smem[];
    const uint32_t sbase = smem_to_u32(smem);
    const int tid = threadIdx.x;
    const int wid = tid >> 5;
    const int lid = tid & 31;
    const int b = blockIdx.z, h = blockIdx.y;
    const int bh = b * NH + h;
    const int tok0 = b * TQ + blockIdx.x * 128;
    const int colb = h * HD;
    const uint32_t mbarS = sbase + 16, mbarO = sbase + 24;

    if (wid == 0) TCGEN05_ALLOC(sbase + 0, 512);
    if (tid == 0) { MBARRIER_INIT(mbarS, 1); MBARRIER_INIT(mbarO, 1); }
    __syncthreads();
    uint32_t tmem;
    asm volatile("ld.shared.b32 %0, [%1];" : "=r"(tmem) : "r"(sbase + 0));

    at_load_tile(Qhi_g, tok0, colb, smem + AT_QHI, tid);
    at_load_tile(Qlo_g, tok0, colb, smem + AT_QLO, tid);
    {
        char* bufp = smem + AT_BUF0;
        at_load_tile(Khi_g, b * TQ, colb, bufp + 0*16384, tid);
        at_load_tile(Klo_g, b * TQ, colb, bufp + 1*16384, tid);
        at_load_vt(Vthi_g, bh, 0, bufp + 2*16384, tid);
        at_load_vt(Vtlo_g, bh, 0, bufp + 3*16384, tid);
    }
    __syncthreads();

    const uint64_t dQh = MAKE_SMEM_DESC(sbase + AT_QHI);
    const uint64_t dQl = MAKE_SMEM_DESC(sbase + AT_QLO);

    if (wid == 0) {
        TCGEN05_FENCE_AFTER();
        if (elect_one_pred()) {
            asm volatile("fence.proxy.async.shared::cta;" ::: "memory");
            const uint64_t dKh = MAKE_SMEM_DESC(sbase + AT_BUF0 + 0*16384);
            const uint64_t dKl = MAKE_SMEM_DESC(sbase + AT_BUF0 + 1*16384);
#pragma unroll
            for (int k = 0; k < 4; k++) {
                mma_f16_ss_cg1(tmem + 0, dQh + 2*k, dKh + 2*k, IDESC_S, (k > 0));
                mma_f16_ss_cg1(tmem + 0, dQh + 2*k, dKl + 2*k, IDESC_S, 1);
                mma_f16_ss_cg1(tmem + 0, dQl + 2*k, dKh + 2*k, IDESC_S, 1);
            }
            TCGEN05_COMMIT(mbarS);
        }
    }

    const int subp = wid & 3;
    const int half = wid >> 2;
    const int qrow = subp * 32 + lid;
    const uint32_t loff = (uint32_t)subp << 21;
    float l_part = 0.0f;
    const float CEX = 0.125f * 1.44269504f;

    for (int t = 0; t < 16; t++) {
        if (t >= 1) MBARRIER_WAIT_PARITY(mbarO, (t - 1) & 1);

        if (t + 1 < 16) {
            char* bufp = smem + AT_BUF0 + ((t + 1) & 1) * AT_BUFSZ;
            const int kb = (t + 1) * 128;
            at_load_tile(Khi_g, b * TQ + kb, colb, bufp + 0*16384, tid);
            at_load_tile(Klo_g, b * TQ + kb, colb, bufp + 1*16384, tid);
            at_load_vt(Vthi_g, bh, kb, bufp + 2*16384, tid);
            at_load_vt(Vtlo_g, bh, kb, bufp + 3*16384, tid);
        }
        __syncthreads();

        if (t + 1 < 16 && wid == 0) {
            TCGEN05_FENCE_AFTER();
            if (elect_one_pred()) {
                asm volatile("fence.proxy.async.shared::cta;" ::: "memory");
                const uint32_t buf2 = AT_BUF0 + ((t + 1) & 1) * AT_BUFSZ;
                const uint64_t dKh = MAKE_SMEM_DESC(sbase + buf2 + 0*16384);
                const uint64_t dKl = MAKE_SMEM_DESC(sbase + buf2 + 1*16384);
                const uint32_t sdst = tmem + ((t + 1) & 1) * 128;
#pragma unroll
                for (int k = 0; k < 4; k++) {
                    mma_f16_ss_cg1(sdst, dQh + 2*k, dKh + 2*k, IDESC_S, (k > 0));
                    mma_f16_ss_cg1(sdst, dQh + 2*k, dKl + 2*k, IDESC_S, 1);
                    mma_f16_ss_cg1(sdst, dQl + 2*k, dKh + 2*k, IDESC_S, 1);
                }
                TCGEN05_COMMIT(mbarS);
            }
        }

        MBARRIER_WAIT_PARITY(mbarS, t & 1);
        TCGEN05_FENCE_AFTER();

        {
            const uint32_t sb = tmem + (t & 1) * 128 + half * 64 + loff;
            uint32_t r0[32], r1[32];
            TCGEN05_LD_32X32B_X32(r0, sb);
            TCGEN05_LD_32X32B_X32(r1, sb + 32);
            TCGEN05_WAIT_LD();
            float p[64];
            float psum = 0.0f;
#pragma unroll
            for (int j = 0; j < 32; j++) {
                float a0 = __uint_as_float(r0[j]) * CEX;
                float a1 = __uint_as_float(r1[j]) * CEX;
                float e0, e1;
                asm("ex2.approx.f32 %0, %1;" : "=f"(e0) : "f"(a0));
                asm("ex2.approx.f32 %0, %1;" : "=f"(e1) : "f"(a1));
                p[j] = e0; p[32 + j] = e1;
                psum += e0 + e1;
            }
            l_part += psum;

            uint32_t hiw[32], low[32];
#pragma unroll
            for (int j2 = 0; j2 < 32; j2++) {
                float p0 = p[2*j2], p1 = p[2*j2 + 1];
                uint32_t wh;
                asm("cvt.rn.bf16x2.f32 %0, %1, %2;" : "=r"(wh) : "f"(p1), "f"(p0));
                float h0 = __uint_as_float(wh << 16);
                float h1 = __uint_as_float(wh & 0xffff0000u);
                float q0 = p0 - h0, q1 = p1 - h1;
                uint32_t wl;
                asm("cvt.rn.bf16x2.f32 %0, %1, %2;" : "=r"(wl) : "f"(q1), "f"(q0));
                hiw[j2] = wh; low[j2] = wl;
            }
            const uint32_t prow = (uint32_t)((qrow >> 3) * 1024 + half * 16384 + (qrow & 7) * 128);
#pragma unroll
            for (int g = 0; g < 8; g++) {
                uint32_t off = prow + g * 16;
                off ^= (off >> 3) & 0x70;
                *reinterpret_cast<uint4*>(smem + AT_PHI + off) =
                    *reinterpret_cast<uint4*>(&hiw[g * 4]);
                *reinterpret_cast<uint4*>(smem + AT_PLO + off) =
                    *reinterpret_cast<uint4*>(&low[g * 4]);
            }
            TCGEN05_FENCE_BEFORE();
        }
        __syncthreads();

        if (wid == 0) {
            TCGEN05_FENCE_AFTER();
            if (elect_one_pred()) {
                asm volatile("fence.proxy.async.shared::cta;" ::: "memory");
                const uint32_t buf = AT_BUF0 + (t & 1) * AT_BUFSZ;
                const uint64_t dPh = MAKE_SMEM_DESC(sbase + AT_PHI);
                const uint64_t dPl = MAKE_SMEM_DESC(sbase + AT_PLO);
                const uint64_t dVh = MAKE_SMEM_DESC(sbase + buf + 2*16384);
                const uint64_t dVl = MAKE_SMEM_DESC(sbase + buf + 3*16384);
#pragma unroll
                for (int s = 0; s < 8; s++) {
                    const uint64_t pa = (uint64_t)((s & 3) * 2 + (s >> 2) * 1024);
                    const uint64_t vb = (uint64_t)((s & 3) * 2 + (s >> 2) * 512);
                    mma_f16_ss_cg1(tmem + 256, dPh + pa, dVh + vb, IDESC_PV, (t > 0 || s > 0));
                    mma_f16_ss_cg1(tmem + 256, dPh + pa, dVl + vb, IDESC_PV, 1);
                    mma_f16_ss_cg1(tmem + 256, dPl + pa, dVh + vb, IDESC_PV, 1);
                }
                TCGEN05_COMMIT(mbarO);
            }
        }
    }

    *reinterpret_cast<float*>(smem + AT_LPART + (qrow * 2 + half) * 4) = l_part;
    __syncthreads();

    MBARRIER_WAIT_PARITY(mbarO, 1);
    TCGEN05_FENCE_AFTER();

    if (wid < 4) {
        const float lsum =
            *reinterpret_cast<float*>(smem + AT_LPART + (qrow * 2 + 0) * 4) +
            *reinterpret_cast<float*>(smem + AT_LPART + (qrow * 2 + 1) * 4);
        const float inv = 1.0f / lsum;
        uint32_t o0[32], o1[32];
        TCGEN05_LD_32X32B_X32(o0, tmem + 256 + loff);
        TCGEN05_LD_32X32B_X32(o1, tmem + 288 + loff);
        TCGEN05_WAIT_LD();
        uint32_t hibuf[32], lobuf[32];
#pragma unroll
        for (int c = 0; c < 32; c++) {
            float f0 = __uint_as_float(c < 16 ? o0[2*c]   : o1[2*(c-16)])   * inv;
            float f1 = __uint_as_float(c < 16 ? o0[2*c+1] : o1[2*(c-16)+1]) * inv;
            uint32_t wh;
            asm("cvt.rn.bf16x2.f32 %0, %1, %2;" : "=r"(wh) : "f"(f1), "f"(f0));
            float h0 = __uint_as_float(wh << 16);
            float h1 = __uint_as_float(wh & 0xffff0000u);
            float q0 = f0 - h0, q1 = f1 - h1;
            uint32_t wl;
            asm("cvt.rn.bf16x2.f32 %0, %1, %2;" : "=r"(wl) : "f"(q1), "f"(q0));
            hibuf[c] = wh; lobuf[c] = wl;
        }
        const size_t rowoff = (((size_t)(tok0 + qrow)) << 10) + colb;
#pragma unroll
        for (int v4 = 0; v4 < 8; v4++) {
            *reinterpret_cast<uint4*>(Ohi_g + rowoff + v4 * 8) =
                *reinterpret_cast<uint4*>(&hibuf[v4 * 4]);
            *reinterpret_cast<uint4*>(Olo_g + rowoff + v4 * 8) =
                *reinterpret_cast<uint4*>(&lobuf[v4 * 4]);
        }
    }
    __syncthreads();
    if (wid == 0) {
        TCGEN05_RELINQUISH();
        TCGEN05_DEALLOC(tmem, 512);
    }
#endif
}

// ---------------- fp32 -> bf16 hi/lo split ----------------------------------
__global__ __launch_bounds__(256)
void split_bf16_kernel(const float4* __restrict__ in,
                       uint2* __restrict__ hi, uint2* __restrict__ lo, int n4)
{
    const int i = blockIdx.x * blockDim.x + threadIdx.x;
    if (i >= n4) return;
    float4 v = in[i];
    __nv_bfloat16 h0 = __float2bfloat16_rn(v.x);
    __nv_bfloat16 h1 = __float2bfloat16_rn(v.y);
    __nv_bfloat16 h2 = __float2bfloat16_rn(v.z);
    __nv_bfloat16 h3 = __float2bfloat16_rn(v.w);
    __nv_bfloat16 l0 = __float2bfloat16_rn(v.x - __bfloat162float(h0));
    __nv_bfloat16 l1 = __float2bfloat16_rn(v.y - __bfloat162float(h1));
    __nv_bfloat16 l2 = __float2bfloat16_rn(v.z - __bfloat162float(h2));
    __nv_bfloat16 l3 = __float2bfloat16_rn(v.w - __bfloat162float(h3));
    uint2 ph, pl;
    ph.x = ((uint32_t)__bfloat16_as_ushort(h1) << 16) | __bfloat16_as_ushort(h0);
    ph.y = ((uint32_t)__bfloat16_as_ushort(h3) << 16) | __bfloat16_as_ushort(h2);
    pl.x = ((uint32_t)__bfloat16_as_ushort(l1) << 16) | __bfloat16_as_ushort(l0);
    pl.y = ((uint32_t)__bfloat16_as_ushort(l3) << 16) | __bfloat16_as_ushort(l2);
    hi[i] = ph;
    lo[i] = pl;
}

// ---------------- W [K,N] -> W^T hi/lo bf16 [N,K], all 4 weights ------------
__global__ __launch_bounds__(256)
void transpose_split4_kernel(const float* __restrict__ W0,
                             const float* __restrict__ W1,
                             const float* __restrict__ W2,
                             const float* __restrict__ W3,
                             __nv_bfloat16* __restrict__ Thi,
                             __nv_bfloat16* __restrict__ Tlo)
{
    __shared__ float tile[32][33];
    const int w = blockIdx.z;
    const float* W = (w == 0) ? W0 : (w == 1) ? W1 : (w == 2) ? W2 : W3;
    __nv_bfloat16* thi = Thi + (size_t)w * EDIM * EDIM;
    __nv_bfloat16* tlo = Tlo + (size_t)w * EDIM * EDIM;
    const int bx = blockIdx.x * 32;
    const int by = blockIdx.y * 32;
    const int tx = threadIdx.x & 31, ty = threadIdx.x >> 5;
#pragma unroll
    for (int j = ty; j < 32; j += 8)
        tile[j][tx] = W[(size_t)(by + j) * EDIM + bx + tx];
    __syncthreads();
#pragma unroll
    for (int j = ty; j < 32; j += 8) {
        float v = tile[tx][j];
        __nv_bfloat16 h = __float2bfloat16_rn(v);
        __nv_bfloat16 l = __float2bfloat16_rn(v - __bfloat162float(h));
        thi[(size_t)(bx + j) * EDIM + by + tx] = h;
        tlo[(size_t)(bx + j) * EDIM + by + tx] = l;
    }
}

// ---------------- cumprod(cos(x)) -> bf16 hi/lo, warp-per-row ----------------
__global__ __launch_bounds__(256)
void cumprod_cos_split_kernel(const float* __restrict__ in,
                              __nv_bfloat16* __restrict__ hi,
                              __nv_bfloat16* __restrict__ lo)
{
    const int row  = blockIdx.x * 8 + (threadIdx.x >> 5);
    const int lane = threadIdx.x & 31;
    const float* rp = in + (size_t)row * EDIM + lane * 32;

    float v[32];
#pragma unroll
    for (int i = 0; i < 8; i++) {
        float4 f = reinterpret_cast<const float4*>(rp)[i];
        v[4*i+0] = f.x; v[4*i+1] = f.y; v[4*i+2] = f.z; v[4*i+3] = f.w;
    }
    // serial cumprod of cos within lane segment
    float c = 1.0f;
#pragma unroll
    for (int i = 0; i < 32; i++) { c *= cosf(v[i]); v[i] = c; }
    // inclusive warp scan of segment totals, then shift for exclusive prefix
    float p = c;
#pragma unroll
    for (int off = 1; off < 32; off <<= 1) {
        float t = __shfl_up_sync(0xffffffffu, p, off);
        if (lane >= off) p *= t;
    }
    float excl = __shfl_up_sync(0xffffffffu, p, 1);
    if (lane == 0) excl = 1.0f;

    uint32_t hiw[16], low[16];
#pragma unroll
    for (int j = 0; j < 16; j++) {
        float f0 = v[2*j] * excl;
        float f1 = v[2*j + 1] * excl;
        uint32_t wh;
        asm("cvt.rn.bf16x2.f32 %0, %1, %2;" : "=r"(wh) : "f"(f1), "f"(f0));
        float h0 = __uint_as_float(wh << 16);
        float h1 = __uint_as_float(wh & 0xffff0000u);
        float q0 = f0 - h0, q1 = f1 - h1;
        uint32_t wl;
        asm("cvt.rn.bf16x2.f32 %0, %1, %2;" : "=r"(wl) : "f"(q1), "f"(q0));
        hiw[j] = wh; low[j] = wl;
    }
    __nv_bfloat16* hp = hi + (size_t)row * EDIM + lane * 32;
    __nv_bfloat16* lp = lo + (size_t)row * EDIM + lane * 32;
#pragma unroll
    for (int j4 = 0; j4 < 4; j4++) {
        *reinterpret_cast<uint4*>(hp + j4 * 8) = *reinterpret_cast<uint4*>(&hiw[j4 * 4]);
        *reinterpret_cast<uint4*>(lp + j4 * 8) = *reinterpret_cast<uint4*>(&low[j4 * 4]);
    }
}

// ---------------- launch ----------------------------------------------------
extern "C" void kernel_launch(void* const* d_in, const int* in_sizes, int n_in,
                              void* d_out, int out_size)
{
    const float* x  = (const float*)d_in[0];
    const float* Wq = (const float*)d_in[1];
    const float* bq = (const float*)d_in[2];
    const float* Wk = (const float*)d_in[3];
    const float* bk = (const float*)d_in[4];
    const float* Wv = (const float*)d_in[5];
    const float* bv = (const float*)d_in[6];
    const float* Wo = (const float*)d_in[7];
    const float* bo = (const float*)d_in[8];
    float* out = (float*)d_out;

    float *q, *k;
    __nv_bfloat16 *xhi, *xlo, *qhi, *qlo, *khi, *klo, *vthi, *vtlo, *aohi, *aolo, *wthi, *wtlo;
    cudaGetSymbolAddress((void**)&q,    g_q);
    cudaGetSymbolAddress((void**)&k,    g_k);
    cudaGetSymbolAddress((void**)&xhi,  g_xhi);
    cudaGetSymbolAddress((void**)&xlo,  g_xlo);
    cudaGetSymbolAddress((void**)&qhi,  g_qhi);
    cudaGetSymbolAddress((void**)&qlo,  g_qlo);
    cudaGetSymbolAddress((void**)&khi,  g_khi);
    cudaGetSymbolAddress((void**)&klo,  g_klo);
    cudaGetSymbolAddress((void**)&vthi, g_vthi);
    cudaGetSymbolAddress((void**)&vtlo, g_vtlo);
    cudaGetSymbolAddress((void**)&aohi, g_aohi);
    cudaGetSymbolAddress((void**)&aolo, g_aolo);
    cudaGetSymbolAddress((void**)&wthi, g_wthi);
    cudaGetSymbolAddress((void**)&wtlo, g_wtlo);

    cudaFuncSetAttribute(gemm_tc_kernel<0>, cudaFuncAttributeMaxDynamicSharedMemorySize, GEMM_SMEM);
    cudaFuncSetAttribute(gemm_tc_kernel<1>, cudaFuncAttributeMaxDynamicSharedMemorySize, GEMM_SMEM);
    cudaFuncSetAttribute(attention_tc_kernel, cudaFuncAttributeMaxDynamicSharedMemorySize, AT_SMEM_TOTAL);

    const int n4 = MROWS * EDIM / 4;
    split_bf16_kernel<<<(n4 + 255) / 256, 256>>>((const float4*)x, (uint2*)xhi, (uint2*)xlo, n4);

    dim3 tg4(32, 32, 4);
    transpose_split4_kernel<<<tg4, 256>>>(Wq, Wk, Wv, Wo, wthi, wtlo);

    dim3 gg(EDIM / 128, MROWS / 128);
    gemm_tc_kernel<0><<<gg, 256, GEMM_SMEM>>>(xhi, xlo, wthi + 0*EDIM*EDIM, wtlo + 0*EDIM*EDIM, bq, q,   nullptr, nullptr);
    gemm_tc_kernel<0><<<gg, 256, GEMM_SMEM>>>(xhi, xlo, wthi + 1*EDIM*EDIM, wtlo + 1*EDIM*EDIM, bk, k,   nullptr, nullptr);
    gemm_tc_kernel<1><<<gg, 256, GEMM_SMEM>>>(xhi, xlo, wthi + 2*EDIM*EDIM, wtlo + 2*EDIM*EDIM, bv, nullptr, vthi, vtlo);

    cumprod_cos_split_kernel<<<MROWS / 8, 256>>>(q, qhi, qlo);
    cumprod_cos_split_kernel<<<MROWS / 8, 256>>>(k, khi, klo);

    // role swap: attention-Q = quantum(k-proj), attention-K = quantum(q-proj)
    dim3 ga(TQ / 128, NH, NB);
    attention_tc_kernel<<<ga, 256, AT_SMEM_TOTAL>>>(khi, klo, qhi, qlo, vthi, vtlo, aohi, aolo);

    gemm_tc_kernel<0><<<gg, 256, GEMM_SMEM>>>(aohi, aolo, wthi + 3*EDIM*EDIM, wtlo + 3*EDIM*EDIM, bo, out, nullptr, nullptr);
}

// round 11
// speedup vs baseline: 8.0748x; 1.4522x over previous
#include <cuda_runtime.h>
#include <cuda_bf16.h>
#include <math.h>
#include <stdint.h>

#define EDIM 1024
#define NH   16
#define HD   64
#define TQ   2048
#define NB   4
#define MROWS (NB*TQ)   // 8192

#if defined(__CUDA_ARCH_FEAT_SM103_ALL) || defined(__CUDA_ARCH_FEAT_SM100_ALL) || \
    defined(__CUDA_ARCH_FEAT_SM101_ALL) || defined(__CUDA_ARCH_SPECIFIC__)
#define TCGEN05_OK 1
#endif

// ---------------- scratch (device globals: no allocations allowed) ----------
__device__ float g_q [MROWS*EDIM];
__device__ float g_k [MROWS*EDIM];
__device__ __nv_bfloat16 g_xhi [MROWS*EDIM];
__device__ __nv_bfloat16 g_xlo [MROWS*EDIM];
__device__ __nv_bfloat16 g_qhi [MROWS*EDIM];
__device__ __nv_bfloat16 g_qlo [MROWS*EDIM];
__device__ __nv_bfloat16 g_khi [MROWS*EDIM];
__device__ __nv_bfloat16 g_klo [MROWS*EDIM];
__device__ __nv_bfloat16 g_vthi[MROWS*EDIM];   // V^T per (b,h): [64 d][2048 tok]
__device__ __nv_bfloat16 g_vtlo[MROWS*EDIM];
__device__ __nv_bfloat16 g_aohi[MROWS*EDIM];
__device__ __nv_bfloat16 g_aolo[MROWS*EDIM];
__device__ __nv_bfloat16 g_wthi[4*EDIM*EDIM];   // W^T (N-major rows, K contiguous)
__device__ __nv_bfloat16 g_wtlo[4*EDIM*EDIM];

// ======================= PTX helpers (sm_103a) ==============================
__device__ __forceinline__ uint32_t smem_to_u32(const void* p) {
    uint32_t a;
    asm("{ .reg .u64 t; cvta.to.shared.u64 t, %1; cvt.u32.u64 %0, t; }" : "=r"(a) : "l"(p));
    return a;
}
__device__ __forceinline__ uint32_t elect_one_pred() {
    uint32_t pred;
    asm volatile("{\n\t.reg .pred p;\n\telect.sync _|p, 0xFFFFFFFF;\n\tselp.b32 %0, 1, 0, p;\n\t}" : "=r"(pred));
    return pred;
}
#define MBARRIER_INIT(mbar, count) \
    asm volatile("mbarrier.init.shared.b64 [%0], %1;" :: "r"((uint32_t)(mbar)), "r"((uint32_t)(count)) : "memory")
#define MBARRIER_WAIT_PARITY(mbar_smem_addr, phase_parity) do { \
    uint32_t _mbar = (uint32_t)(mbar_smem_addr); \
    uint32_t _parity = (uint32_t)(phase_parity); \
    uint32_t _done; \
    asm volatile("{\n\t.reg .pred p;\n\tmbarrier.try_wait.parity.acquire.cta.shared::cta.b64 p, [%1], %2;\n\tselp.b32 %0, 1, 0, p;\n\t}" \
        : "=r"(_done) : "r"(_mbar), "r"(_parity) : "memory"); \
    if (!_done) { \
        asm volatile("{\n\t.reg .pred P1;\n\tWAIT_LOOP_%=:\n\t" \
            "mbarrier.try_wait.parity.acquire.cta.shared::cta.b64 P1, [%0], %1, 0x989680;\n\t" \
            "@P1 bra.uni WAIT_DONE_%=;\n\tbra.uni WAIT_LOOP_%=;\n\tWAIT_DONE_%=:\n\t}" \
            :: "r"(_mbar), "r"(_parity) : "memory"); \
    } \
} while(0)

#define CP_ASYNC16(dst, src) \
    asm volatile("cp.async.cg.shared.global [%0], [%1], 16;" :: "r"((uint32_t)(dst)), "l"(src) : "memory")
#define CP_COMMIT() asm volatile("cp.async.commit_group;" ::: "memory")
#define CP_WAIT0()  asm volatile("cp.async.wait_group 0;" ::: "memory")
#define CP_WAIT1()  asm volatile("cp.async.wait_group 1;" ::: "memory")

#ifdef TCGEN05_OK
#define TCGEN05_ALLOC(smem_addr, nCols) \
    asm volatile("tcgen05.alloc.cta_group::1.sync.aligned.shared::cta.b32 [%0], %1;" \
        :: "r"((uint32_t)(smem_addr)), "r"((uint32_t)(nCols)) : "memory")
#define TCGEN05_DEALLOC(tmem_addr, nCols) \
    asm volatile("tcgen05.dealloc.cta_group::1.sync.aligned.b32 %0, %1;" :: "r"(tmem_addr), "r"((uint32_t)(nCols)))
#define TCGEN05_RELINQUISH() \
    asm volatile("tcgen05.relinquish_alloc_permit.cta_group::1.sync.aligned;")
#define TCGEN05_COMMIT(mbar) \
    asm volatile("tcgen05.commit.cta_group::1.mbarrier::arrive::one.shared::cluster.b64 [%0];" \
        :: "r"((uint32_t)(mbar)) : "memory")
#define TCGEN05_FENCE_BEFORE() asm volatile("tcgen05.fence::before_thread_sync;" ::: "memory")
#define TCGEN05_FENCE_AFTER()  asm volatile("tcgen05.fence::after_thread_sync;" ::: "memory")
#define TCGEN05_WAIT_LD()      asm volatile("tcgen05.wait::ld.sync.aligned;" ::: "memory")

#define TCGEN05_LD_32X32B_X32(r, tmem_addr) \
    asm volatile("tcgen05.ld.sync.aligned.32x32b.x32.b32 " \
        "{%0, %1, %2, %3, %4, %5, %6, %7, %8, %9, %10, %11, %12, %13, %14, %15, " \
        " %16, %17, %18, %19, %20, %21, %22, %23, %24, %25, %26, %27, %28, %29, %30, %31}, [%32];" \
        : "=r"((r)[0]),  "=r"((r)[1]),  "=r"((r)[2]),  "=r"((r)[3]), \
          "=r"((r)[4]),  "=r"((r)[5]),  "=r"((r)[6]),  "=r"((r)[7]), \
          "=r"((r)[8]),  "=r"((r)[9]),  "=r"((r)[10]), "=r"((r)[11]), \
          "=r"((r)[12]), "=r"((r)[13]), "=r"((r)[14]), "=r"((r)[15]), \
          "=r"((r)[16]), "=r"((r)[17]), "=r"((r)[18]), "=r"((r)[19]), \
          "=r"((r)[20]), "=r"((r)[21]), "=r"((r)[22]), "=r"((r)[23]), \
          "=r"((r)[24]), "=r"((r)[25]), "=r"((r)[26]), "=r"((r)[27]), \
          "=r"((r)[28]), "=r"((r)[29]), "=r"((r)[30]), "=r"((r)[31]) \
        : "r"(tmem_addr))

__device__ __forceinline__ void mma_f16_ss_cg1(uint32_t d, uint64_t a, uint64_t b,
                                               uint32_t idesc, uint32_t en) {
    asm volatile(
        "{\n\t.reg .pred p;\n\tsetp.ne.u32 p, %5, 0;\n\t"
        "tcgen05.mma.cta_group::1.kind::f16 [%0], %1, %2, %3, {%4,%4,%4,%4}, p;\n\t}"
        :: "r"(d), "l"(a), "l"(b), "r"(idesc), "r"(0u), "r"(en) : "memory");
}
#endif // TCGEN05_OK

// K-major SW128 descriptor (LBO=1, SBO=64)
static constexpr uint64_t SMEM_DESC_BASE_SW128 =
    (uint64_t(2)  << 61) | (uint64_t(1) << 46) | (uint64_t(64) << 32) | (uint64_t(1) << 16);
#define MAKE_SMEM_DESC(base_addr) (SMEM_DESC_BASE_SW128 | ((uint64_t)((base_addr) >> 4) & 0x3FFF))

// idesc kind::f16 bf16/F32: M=128 N=128 and M=128 N=64
#define IDESC_S  0x8200490u
#define IDESC_PV 0x8100490u

// ======================= tcgen05 GEMM v2 (cp.async, 128x256 tile) ===========
// grid (EDIM/256, MROWS/128, nz) ; 512 threads ; 2-stage 96KB buffers.
// per chunk (K=64): Ahi/Alo 16KB each, Bhi/Blo 32KB each (N=256 rows).
#define G2_STAGE_BYTES 98304
#define G2_HDR 1024
#define GEMM_SMEM (G2_HDR + 2*G2_STAGE_BYTES)   // 197632

__device__ __forceinline__ void gemm_cp_stage(
    uint32_t sdst, const __nv_bfloat16* Ahi, const __nv_bfloat16* Alo,
    const __nv_bfloat16* Bhi, const __nv_bfloat16* Blo,
    int bm, int bnw, int c, int tid)
{
#pragma unroll
    for (int j = 0; j < 2; j++) {
        const int i = j * 512 + tid;
        const int r = i >> 3, g = i & 7;
        uint32_t off = (uint32_t)(r * 128 + g * 16);
        off ^= (off >> 3) & 0x70;
        const size_t go = (((size_t)(bm + r)) << 10) + c * 64 + g * 8;
        CP_ASYNC16(sdst + off,         Ahi + go);
        CP_ASYNC16(sdst + 16384 + off, Alo + go);
    }
#pragma unroll
    for (int j = 0; j < 4; j++) {
        const int i = j * 512 + tid;
        const int r = i >> 3, g = i & 7;
        uint32_t off = (uint32_t)(r * 128 + g * 16);
        off ^= (off >> 3) & 0x70;
        const size_t go = (((size_t)(bnw + r)) << 10) + c * 64 + g * 8;
        CP_ASYNC16(sdst + 32768 + off, Bhi + go);
        CP_ASYNC16(sdst + 65536 + off, Blo + go);
    }
}

__global__ __launch_bounds__(512, 1)
void gemm_tc2_kernel(const __nv_bfloat16* __restrict__ Ahi,
                     const __nv_bfloat16* __restrict__ Alo,
                     const __nv_bfloat16* __restrict__ WThi,
                     const __nv_bfloat16* __restrict__ WTlo,
                     int wbase,
                     const float* __restrict__ b0,
                     const float* __restrict__ b1,
                     const float* __restrict__ b2,
                     float* __restrict__ C0,
                     float* __restrict__ C1,
                     __nv_bfloat16* __restrict__ Vthi,
                     __nv_bfloat16* __restrict__ Vtlo,
                     int vz)
{
#ifdef TCGEN05_OK
    extern __shared__ char smem[];
    const uint32_t sbase = smem_to_u32(smem);
    const int tid = threadIdx.x;
    const int wid = tid >> 5;
    const int lid = tid & 31;
    const int bm = blockIdx.y * 128;
    const int bn = blockIdx.x * 256;
    const int z  = blockIdx.z;
    const int w  = wbase + z;
    const float* bias = (z == 0) ? b0 : (z == 1) ? b1 : b2;
    float* Cout = (z == 0) ? C0 : C1;
    const bool vmode = (z == vz);
    const int bnw = w * 1024 + bn;

    if (wid == 0) TCGEN05_ALLOC(sbase + 0, 256);
    if (tid == 0) {
        MBARRIER_INIT(sbase + 16, 1);   // done[0]
        MBARRIER_INIT(sbase + 24, 1);   // done[1]
        MBARRIER_INIT(sbase + 32, 1);   // final
    }
    __syncthreads();
    uint32_t tmem;
    asm volatile("ld.shared.b32 %0, [%1];" : "=r"(tmem) : "r"(sbase + 0));

    gemm_cp_stage(sbase + G2_HDR, Ahi, Alo, WThi, WTlo, bm, bnw, 0, tid);
    CP_COMMIT();

    int phD0 = 0, phD1 = 0;
    for (int c = 0; c < 16; c++) {
        if (c + 1 < 16) {
            const int b2s = (c + 1) & 1;
            if (c + 1 >= 2) {
                if (b2s == 0) { MBARRIER_WAIT_PARITY(sbase + 16, phD0); phD0 ^= 1; }
                else          { MBARRIER_WAIT_PARITY(sbase + 24, phD1); phD1 ^= 1; }
            }
            gemm_cp_stage(sbase + G2_HDR + b2s * G2_STAGE_BYTES,
                          Ahi, Alo, WThi, WTlo, bm, bnw, c + 1, tid);
            CP_COMMIT();
            CP_WAIT1();
        } else {
            CP_WAIT0();
        }
        __syncthreads();

        if (wid == 0) {
            TCGEN05_FENCE_AFTER();
            if (elect_one_pred()) {
                asm volatile("fence.proxy.async.shared::cta;" ::: "memory");
                const uint32_t stg = sbase + G2_HDR + (c & 1) * G2_STAGE_BYTES;
                const uint64_t dAh = MAKE_SMEM_DESC(stg + 0);
                const uint64_t dAl = MAKE_SMEM_DESC(stg + 16384);
                const uint64_t dBh = MAKE_SMEM_DESC(stg + 32768);
                const uint64_t dBl = MAKE_SMEM_DESC(stg + 65536);
#pragma unroll
                for (int k = 0; k < 4; k++) {
#pragma unroll
                    for (int hf = 0; hf < 2; hf++) {
                        const uint64_t hb = (uint64_t)(hf * 1024);
                        const uint32_t dd = tmem + hf * 128;
                        mma_f16_ss_cg1(dd, dAh + 2*k, dBh + 2*k + hb, IDESC_S, (c > 0 || k > 0));
                        mma_f16_ss_cg1(dd, dAh + 2*k, dBl + 2*k + hb, IDESC_S, 1);
                        mma_f16_ss_cg1(dd, dAl + 2*k, dBh + 2*k + hb, IDESC_S, 1);
                    }
                }
                TCGEN05_COMMIT(sbase + 16 + 8 * (c & 1));
            }
        }
    }

    if (wid == 0) {
        if (elect_one_pred()) TCGEN05_COMMIT(sbase + 32);
    }
    MBARRIER_WAIT_PARITY(sbase + 32, 0);
    TCGEN05_FENCE_AFTER();

    // epilogue: 16 warps = 4 subpartitions x 4 col-chunks of 64
    {
        const int subp = wid & 3;
        const int colq = wid >> 2;
        const int row  = bm + subp * 32 + lid;
        const uint32_t woff = (uint32_t)subp << 21;
        uint32_t d0[32], d1[32];
        TCGEN05_LD_32X32B_X32(d0, tmem + woff + colq * 64);
        TCGEN05_LD_32X32B_X32(d1, tmem + woff + colq * 64 + 32);
        TCGEN05_WAIT_LD();
        if (!vmode) {
            float* cp = Cout + (size_t)row * EDIM + bn + colq * 64;
            const float* bp = bias + bn + colq * 64;
#pragma unroll
            for (int c4 = 0; c4 < 8; c4++) {
                float4 o;
                o.x = __uint_as_float(d0[c4*4+0]) + bp[c4*4+0];
                o.y = __uint_as_float(d0[c4*4+1]) + bp[c4*4+1];
                o.z = __uint_as_float(d0[c4*4+2]) + bp[c4*4+2];
                o.w = __uint_as_float(d0[c4*4+3]) + bp[c4*4+3];
                *reinterpret_cast<float4*>(cp + c4*4) = o;
            }
#pragma unroll
            for (int c4 = 0; c4 < 8; c4++) {
                float4 o;
                o.x = __uint_as_float(d1[c4*4+0]) + bp[32 + c4*4+0];
                o.y = __uint_as_float(d1[c4*4+1]) + bp[32 + c4*4+1];
                o.z = __uint_as_float(d1[c4*4+2]) + bp[32 + c4*4+2];
                o.w = __uint_as_float(d1[c4*4+3]) + bp[32 + c4*4+3];
                *reinterpret_cast<float4*>(cp + 32 + c4*4) = o;
            }
        } else {
            const int bb  = row >> 11;
            const int tok = row & (TQ - 1);
#pragma unroll
            for (int j = 0; j < 64; j++) {
                const int colg = bn + colq * 64 + j;
                const float f = __uint_as_float(j < 32 ? d0[j] : d1[j - 32]) + bias[colg];
                const __nv_bfloat16 hh = __float2bfloat16_rn(f);
                const __nv_bfloat16 ll = __float2bfloat16_rn(f - __bfloat162float(hh));
                const size_t dst = ((size_t)((bb * NH + (colg >> 6)) * HD + (colg & 63))) * TQ + tok;
                Vthi[dst] = hh;
                Vtlo[dst] = ll;
            }
        }
    }
    __syncthreads();
    if (wid == 0) {
        TCGEN05_RELINQUISH();
        TCGEN05_DEALLOC(tmem, 256);
    }
#endif
}

// ======================= tensor-core flash attention ========================
#define AT_LPART 1024
#define AT_QHI   2048
#define AT_QLO   (AT_QHI + 16384)
#define AT_PHI   (AT_QLO + 16384)
#define AT_PLO   (AT_PHI + 32768)
#define AT_BUF0  (AT_PLO + 32768)
#define AT_BUFSZ 65536
#define AT_SMEM_TOTAL (AT_BUF0 + 2*AT_BUFSZ)   // 231424

__device__ __forceinline__ void at_cp_tile(const __nv_bfloat16* g, int tok0, int colb,
                                           uint32_t sdst, int tid)
{
#pragma unroll
    for (int j = 0; j < 4; j++) {
        const int i = j * 256 + tid;
        const int r = i >> 3, c8 = i & 7;
        uint32_t off = (uint32_t)(r * 128 + c8 * 16);
        off ^= (off >> 3) & 0x70;
        CP_ASYNC16(sdst + off, g + (((size_t)(tok0 + r)) << 10) + colb + c8 * 8);
    }
}

__device__ __forceinline__ void at_cp_vt(const __nv_bfloat16* vt, int bh, int kb,
                                         uint32_t sdst, int tid)
{
#pragma unroll
    for (int j = 0; j < 4; j++) {
        const int i = j * 256 + tid;
        const int r = i >> 4, c16 = i & 15;
        uint32_t off = (uint32_t)((r >> 3) * 1024 + (c16 >> 3) * 8192 + (r & 7) * 128 + (c16 & 7) * 16);
        off ^= (off >> 3) & 0x70;
        CP_ASYNC16(sdst + off, vt + ((size_t)(bh * HD + r)) * TQ + kb + c16 * 8);
    }
}

__global__ __launch_bounds__(256, 1)
void attention_tc_kernel(const __nv_bfloat16* __restrict__ Qhi_g,
                         const __nv_bfloat16* __restrict__ Qlo_g,
                         const __nv_bfloat16* __restrict__ Khi_g,
                         const __nv_bfloat16* __restrict__ Klo_g,
                         const __nv_bfloat16* __restrict__ Vthi_g,
                         const __nv_bfloat16* __restrict__ Vtlo_g,
                         __nv_bfloat16* __restrict__ Ohi_g,
                         __nv_bfloat16* __restrict__ Olo_g)
{
#ifdef TCGEN05_OK
    extern __shared__ char smem[];
    const uint32_t sbase = smem_to_u32(smem);
    const int tid = threadIdx.x;
    const int wid = tid >> 5;
    const int lid = tid & 31;
    const int b = blockIdx.z, h = blockIdx.y;
    const int bh = b * NH + h;
    const int tok0 = b * TQ + blockIdx.x * 128;
    const int colb = h * HD;
    const uint32_t mbarS = sbase + 16, mbarO = sbase + 24;

    if (wid == 0) TCGEN05_ALLOC(sbase + 0, 512);
    if (tid == 0) { MBARRIER_INIT(mbarS, 1); MBARRIER_INIT(mbarO, 1); }
    __syncthreads();
    uint32_t tmem;
    asm volatile("ld.shared.b32 %0, [%1];" : "=r"(tmem) : "r"(sbase + 0));

    at_cp_tile(Qhi_g, tok0, colb, sbase + AT_QHI, tid);
    at_cp_tile(Qlo_g, tok0, colb, sbase + AT_QLO, tid);
    at_cp_tile(Khi_g, b * TQ, colb, sbase + AT_BUF0 + 0*16384, tid);
    at_cp_tile(Klo_g, b * TQ, colb, sbase + AT_BUF0 + 1*16384, tid);
    at_cp_vt(Vthi_g, bh, 0, sbase + AT_BUF0 + 2*16384, tid);
    at_cp_vt(Vtlo_g, bh, 0, sbase + AT_BUF0 + 3*16384, tid);
    CP_COMMIT();
    CP_WAIT0();
    __syncthreads();

    const uint64_t dQh = MAKE_SMEM_DESC(sbase + AT_QHI);
    const uint64_t dQl = MAKE_SMEM_DESC(sbase + AT_QLO);

    if (wid == 0) {
        TCGEN05_FENCE_AFTER();
        if (elect_one_pred()) {
            asm volatile("fence.proxy.async.shared::cta;" ::: "memory");
            const uint64_t dKh = MAKE_SMEM_DESC(sbase + AT_BUF0 + 0*16384);
            const uint64_t dKl = MAKE_SMEM_DESC(sbase + AT_BUF0 + 1*16384);
#pragma unroll
            for (int k = 0; k < 4; k++) {
                mma_f16_ss_cg1(tmem + 0, dQh + 2*k, dKh + 2*k, IDESC_S, (k > 0));
                mma_f16_ss_cg1(tmem + 0, dQh + 2*k, dKl + 2*k, IDESC_S, 1);
                mma_f16_ss_cg1(tmem + 0, dQl + 2*k, dKh + 2*k, IDESC_S, 1);
            }
            TCGEN05_COMMIT(mbarS);
        }
    }

    const int subp = wid & 3;
    const int half = wid >> 2;
    const int qrow = subp * 32 + lid;
    const uint32_t loff = (uint32_t)subp << 21;
    float l_part = 0.0f;
    const float CEX = 0.125f * 1.44269504f;

    for (int t = 0; t < 16; t++) {
        // PV(t-1) done: frees P smem + the buffer we're about to refill
        if (t >= 1) MBARRIER_WAIT_PARITY(mbarO, (t - 1) & 1);

        // fire-and-forget loads for tile t+1 (overlap softmax below)
        if (t + 1 < 16) {
            const uint32_t bufp = sbase + AT_BUF0 + ((t + 1) & 1) * AT_BUFSZ;
            const int kb = (t + 1) * 128;
            at_cp_tile(Khi_g, b * TQ + kb, colb, bufp + 0*16384, tid);
            at_cp_tile(Klo_g, b * TQ + kb, colb, bufp + 1*16384, tid);
            at_cp_vt(Vthi_g, bh, kb, bufp + 2*16384, tid);
            at_cp_vt(Vtlo_g, bh, kb, bufp + 3*16384, tid);
            CP_COMMIT();
        }

        MBARRIER_WAIT_PARITY(mbarS, t & 1);
        TCGEN05_FENCE_AFTER();

        // softmax on S(t): 8 warps, thread owns row qrow, cols [half*64, +64)
        {
            const uint32_t sb = tmem + (t & 1) * 128 + half * 64 + loff;
            uint32_t r0[32], r1[32];
            TCGEN05_LD_32X32B_X32(r0, sb);
            TCGEN05_LD_32X32B_X32(r1, sb + 32);
            TCGEN05_WAIT_LD();
            float p[64];
            float psum = 0.0f;
#pragma unroll
            for (int j = 0; j < 32; j++) {
                float a0 = __uint_as_float(r0[j]) * CEX;
                float a1 = __uint_as_float(r1[j]) * CEX;
                float e0, e1;
                asm("ex2.approx.f32 %0, %1;" : "=f"(e0) : "f"(a0));
                asm("ex2.approx.f32 %0, %1;" : "=f"(e1) : "f"(a1));
                p[j] = e0; p[32 + j] = e1;
                psum += e0 + e1;
            }
            l_part += psum;

            uint32_t hiw[32], low[32];
#pragma unroll
            for (int j2 = 0; j2 < 32; j2++) {
                float p0 = p[2*j2], p1 = p[2*j2 + 1];
                uint32_t wh;
                asm("cvt.rn.bf16x2.f32 %0, %1, %2;" : "=r"(wh) : "f"(p1), "f"(p0));
                float h0 = __uint_as_float(wh << 16);
                float h1 = __uint_as_float(wh & 0xffff0000u);
                float q0 = p0 - h0, q1 = p1 - h1;
                uint32_t wl;
                asm("cvt.rn.bf16x2.f32 %0, %1, %2;" : "=r"(wl) : "f"(q1), "f"(q0));
                hiw[j2] = wh; low[j2] = wl;
            }
            const uint32_t prow = (uint32_t)((qrow >> 3) * 1024 + half * 16384 + (qrow & 7) * 128);
#pragma unroll
            for (int g = 0; g < 8; g++) {
                uint32_t off = prow + g * 16;
                off ^= (off >> 3) & 0x70;
                *reinterpret_cast<uint4*>(smem + AT_PHI + off) =
                    *reinterpret_cast<uint4*>(&hiw[g * 4]);
                *reinterpret_cast<uint4*>(smem + AT_PLO + off) =
                    *reinterpret_cast<uint4*>(&low[g * 4]);
            }
            TCGEN05_FENCE_BEFORE();
        }

        CP_WAIT0();
        __syncthreads();

        // issue S(t+1) then PV(t)
        if (wid == 0) {
            TCGEN05_FENCE_AFTER();
            if (elect_one_pred()) {
                asm volatile("fence.proxy.async.shared::cta;" ::: "memory");
                if (t + 1 < 16) {
                    const uint32_t buf2 = sbase + AT_BUF0 + ((t + 1) & 1) * AT_BUFSZ;
                    const uint64_t dKh = MAKE_SMEM_DESC(buf2 + 0*16384);
                    const uint64_t dKl = MAKE_SMEM_DESC(buf2 + 1*16384);
                    const uint32_t sdst = tmem + ((t + 1) & 1) * 128;
#pragma unroll
                    for (int k = 0; k < 4; k++) {
                        mma_f16_ss_cg1(sdst, dQh + 2*k, dKh + 2*k, IDESC_S, (k > 0));
                        mma_f16_ss_cg1(sdst, dQh + 2*k, dKl + 2*k, IDESC_S, 1);
                        mma_f16_ss_cg1(sdst, dQl + 2*k, dKh + 2*k, IDESC_S, 1);
                    }
                    TCGEN05_COMMIT(mbarS);
                }
                const uint32_t buf = sbase + AT_BUF0 + (t & 1) * AT_BUFSZ;
                const uint64_t dPh = MAKE_SMEM_DESC(sbase + AT_PHI);
                const uint64_t dPl = MAKE_SMEM_DESC(sbase + AT_PLO);
                const uint64_t dVh = MAKE_SMEM_DESC(buf + 2*16384);
                const uint64_t dVl = MAKE_SMEM_DESC(buf + 3*16384);
#pragma unroll
                for (int s = 0; s < 8; s++) {
                    const uint64_t pa = (uint64_t)((s & 3) * 2 + (s >> 2) * 1024);
                    const uint64_t vb = (uint64_t)((s & 3) * 2 + (s >> 2) * 512);
                    mma_f16_ss_cg1(tmem + 256, dPh + pa, dVh + vb, IDESC_PV, (t > 0 || s > 0));
                    mma_f16_ss_cg1(tmem + 256, dPh + pa, dVl + vb, IDESC_PV, 1);
                    mma_f16_ss_cg1(tmem + 256, dPl + pa, dVh + vb, IDESC_PV, 1);
                }
                TCGEN05_COMMIT(mbarO);
            }
        }
    }

    *reinterpret_cast<float*>(smem + AT_LPART + (qrow * 2 + half) * 4) = l_part;
    __syncthreads();

    MBARRIER_WAIT_PARITY(mbarO, 1);
    TCGEN05_FENCE_AFTER();

    if (wid < 4) {
        const float lsum =
            *reinterpret_cast<float*>(smem + AT_LPART + (qrow * 2 + 0) * 4) +
            *reinterpret_cast<float*>(smem + AT_LPART + (qrow * 2 + 1) * 4);
        const float inv = 1.0f / lsum;
        uint32_t o0[32], o1[32];
        TCGEN05_LD_32X32B_X32(o0, tmem + 256 + loff);
        TCGEN05_LD_32X32B_X32(o1, tmem + 288 + loff);
        TCGEN05_WAIT_LD();
        uint32_t hibuf[32], lobuf[32];
#pragma unroll
        for (int c = 0; c < 32; c++) {
            float f0 = __uint_as_float(c < 16 ? o0[2*c]   : o1[2*(c-16)])   * inv;
            float f1 = __uint_as_float(c < 16 ? o0[2*c+1] : o1[2*(c-16)+1]) * inv;
            uint32_t wh;
            asm("cvt.rn.bf16x2.f32 %0, %1, %2;" : "=r"(wh) : "f"(f1), "f"(f0));
            float h0 = __uint_as_float(wh << 16);
            float h1 = __uint_as_float(wh & 0xffff0000u);
            float q0 = f0 - h0, q1 = f1 - h1;
            uint32_t wl;
            asm("cvt.rn.bf16x2.f32 %0, %1, %2;" : "=r"(wl) : "f"(q1), "f"(q0));
            hibuf[c] = wh; lobuf[c] = wl;
        }
        const size_t rowoff = (((size_t)(tok0 + qrow)) << 10) + colb;
#pragma unroll
        for (int v4 = 0; v4 < 8; v4++) {
            *reinterpret_cast<uint4*>(Ohi_g + rowoff + v4 * 8) =
                *reinterpret_cast<uint4*>(&hibuf[v4 * 4]);
            *reinterpret_cast<uint4*>(Olo_g + rowoff + v4 * 8) =
                *reinterpret_cast<uint4*>(&lobuf[v4 * 4]);
        }
    }
    __syncthreads();
    if (wid == 0) {
        TCGEN05_RELINQUISH();
        TCGEN05_DEALLOC(tmem, 512);
    }
#endif
}

// ---------------- fp32 -> bf16 hi/lo split ----------------------------------
__global__ __launch_bounds__(256)
void split_bf16_kernel(const float4* __restrict__ in,
                       uint2* __restrict__ hi, uint2* __restrict__ lo, int n4)
{
    const int i = blockIdx.x * blockDim.x + threadIdx.x;
    if (i >= n4) return;
    float4 v = in[i];
    __nv_bfloat16 h0 = __float2bfloat16_rn(v.x);
    __nv_bfloat16 h1 = __float2bfloat16_rn(v.y);
    __nv_bfloat16 h2 = __float2bfloat16_rn(v.z);
    __nv_bfloat16 h3 = __float2bfloat16_rn(v.w);
    __nv_bfloat16 l0 = __float2bfloat16_rn(v.x - __bfloat162float(h0));
    __nv_bfloat16 l1 = __float2bfloat16_rn(v.y - __bfloat162float(h1));
    __nv_bfloat16 l2 = __float2bfloat16_rn(v.z - __bfloat162float(h2));
    __nv_bfloat16 l3 = __float2bfloat16_rn(v.w - __bfloat162float(h3));
    uint2 ph, pl;
    ph.x = ((uint32_t)__bfloat16_as_ushort(h1) << 16) | __bfloat16_as_ushort(h0);
    ph.y = ((uint32_t)__bfloat16_as_ushort(h3) << 16) | __bfloat16_as_ushort(h2);
    pl.x = ((uint32_t)__bfloat16_as_ushort(l1) << 16) | __bfloat16_as_ushort(l0);
    pl.y = ((uint32_t)__bfloat16_as_ushort(l3) << 16) | __bfloat16_as_ushort(l2);
    hi[i] = ph;
    lo[i] = pl;
}

// ---------------- W [K,N] -> W^T hi/lo bf16 [N,K], all 4 weights ------------
__global__ __launch_bounds__(256)
void transpose_split4_kernel(const float* __restrict__ W0,
                             const float* __restrict__ W1,
                             const float* __restrict__ W2,
                             const float* __restrict__ W3,
                             __nv_bfloat16* __restrict__ Thi,
                             __nv_bfloat16* __restrict__ Tlo)
{
    __shared__ float tile[32][33];
    const int w = blockIdx.z;
    const float* W = (w == 0) ? W0 : (w == 1) ? W1 : (w == 2) ? W2 : W3;
    __nv_bfloat16* thi = Thi + (size_t)w * EDIM * EDIM;
    __nv_bfloat16* tlo = Tlo + (size_t)w * EDIM * EDIM;
    const int bx = blockIdx.x * 32;
    const int by = blockIdx.y * 32;
    const int tx = threadIdx.x & 31, ty = threadIdx.x >> 5;
#pragma unroll
    for (int j = ty; j < 32; j += 8)
        tile[j][tx] = W[(size_t)(by + j) * EDIM + bx + tx];
    __syncthreads();
#pragma unroll
    for (int j = ty; j < 32; j += 8) {
        float v = tile[tx][j];
        __nv_bfloat16 h = __float2bfloat16_rn(v);
        __nv_bfloat16 l = __float2bfloat16_rn(v - __bfloat162float(h));
        thi[(size_t)(bx + j) * EDIM + by + tx] = h;
        tlo[(size_t)(bx + j) * EDIM + by + tx] = l;
    }
}

// ---------------- cumprod(cos(x)) -> bf16 hi/lo, warp-per-row ----------------
__global__ __launch_bounds__(256)
void cumprod_cos_split_kernel(const float* __restrict__ in,
                              __nv_bfloat16* __restrict__ hi,
                              __nv_bfloat16* __restrict__ lo)
{
    const int row  = blockIdx.x * 8 + (threadIdx.x >> 5);
    const int lane = threadIdx.x & 31;
    const float* rp = in + (size_t)row * EDIM + lane * 32;

    float v[32];
#pragma unroll
    for (int i = 0; i < 8; i++) {
        float4 f = reinterpret_cast<const float4*>(rp)[i];
        v[4*i+0] = f.x; v[4*i+1] = f.y; v[4*i+2] = f.z; v[4*i+3] = f.w;
    }
    float c = 1.0f;
#pragma unroll
    for (int i = 0; i < 32; i++) { c *= cosf(v[i]); v[i] = c; }
    float p = c;
#pragma unroll
    for (int off = 1; off < 32; off <<= 1) {
        float t = __shfl_up_sync(0xffffffffu, p, off);
        if (lane >= off) p *= t;
    }
    float excl = __shfl_up_sync(0xffffffffu, p, 1);
    if (lane == 0) excl = 1.0f;

    uint32_t hiw[16], low[16];
#pragma unroll
    for (int j = 0; j < 16; j++) {
        float f0 = v[2*j] * excl;
        float f1 = v[2*j + 1] * excl;
        uint32_t wh;
        asm("cvt.rn.bf16x2.f32 %0, %1, %2;" : "=r"(wh) : "f"(f1), "f"(f0));
        float h0 = __uint_as_float(wh << 16);
        float h1 = __uint_as_float(wh & 0xffff0000u);
        float q0 = f0 - h0, q1 = f1 - h1;
        uint32_t wl;
        asm("cvt.rn.bf16x2.f32 %0, %1, %2;" : "=r"(wl) : "f"(q1), "f"(q0));
        hiw[j] = wh; low[j] = wl;
    }
    __nv_bfloat16* hp = hi + (size_t)row * EDIM + lane * 32;
    __nv_bfloat16* lp = lo + (size_t)row * EDIM + lane * 32;
#pragma unroll
    for (int j4 = 0; j4 < 4; j4++) {
        *reinterpret_cast<uint4*>(hp + j4 * 8) = *reinterpret_cast<uint4*>(&hiw[j4 * 4]);
        *reinterpret_cast<uint4*>(lp + j4 * 8) = *reinterpret_cast<uint4*>(&low[j4 * 4]);
    }
}

// ---------------- launch ----------------------------------------------------
extern "C" void kernel_launch(void* const* d_in, const int* in_sizes, int n_in,
                              void* d_out, int out_size)
{
    const float* x  = (const float*)d_in[0];
    const float* Wq = (const float*)d_in[1];
    const float* bq = (const float*)d_in[2];
    const float* Wk = (const float*)d_in[3];
    const float* bk = (const float*)d_in[4];
    const float* Wv = (const float*)d_in[5];
    const float* bv = (const float*)d_in[6];
    const float* Wo = (const float*)d_in[7];
    const float* bo = (const float*)d_in[8];
    float* out = (float*)d_out;

    float *q, *k;
    __nv_bfloat16 *xhi, *xlo, *qhi, *qlo, *khi, *klo, *vthi, *vtlo, *aohi, *aolo, *wthi, *wtlo;
    cudaGetSymbolAddress((void**)&q,    g_q);
    cudaGetSymbolAddress((void**)&k,    g_k);
    cudaGetSymbolAddress((void**)&xhi,  g_xhi);
    cudaGetSymbolAddress((void**)&xlo,  g_xlo);
    cudaGetSymbolAddress((void**)&qhi,  g_qhi);
    cudaGetSymbolAddress((void**)&qlo,  g_qlo);
    cudaGetSymbolAddress((void**)&khi,  g_khi);
    cudaGetSymbolAddress((void**)&klo,  g_klo);
    cudaGetSymbolAddress((void**)&vthi, g_vthi);
    cudaGetSymbolAddress((void**)&vtlo, g_vtlo);
    cudaGetSymbolAddress((void**)&aohi, g_aohi);
    cudaGetSymbolAddress((void**)&aolo, g_aolo);
    cudaGetSymbolAddress((void**)&wthi, g_wthi);
    cudaGetSymbolAddress((void**)&wtlo, g_wtlo);

    cudaFuncSetAttribute(gemm_tc2_kernel, cudaFuncAttributeMaxDynamicSharedMemorySize, GEMM_SMEM);
    cudaFuncSetAttribute(attention_tc_kernel, cudaFuncAttributeMaxDynamicSharedMemorySize, AT_SMEM_TOTAL);

    const int n4 = MROWS * EDIM / 4;
    split_bf16_kernel<<<(n4 + 255) / 256, 256>>>((const float4*)x, (uint2*)xhi, (uint2*)xlo, n4);

    dim3 tg4(32, 32, 4);
    transpose_split4_kernel<<<tg4, 256>>>(Wq, Wk, Wv, Wo, wthi, wtlo);

    // fused Q/K/V projection (z=0: q, z=1: k, z=2: V^T epilogue)
    dim3 gqkv(EDIM / 256, MROWS / 128, 3);
    gemm_tc2_kernel<<<gqkv, 512, GEMM_SMEM>>>(xhi, xlo, wthi, wtlo, 0,
                                              bq, bk, bv, q, k, vthi, vtlo, 2);

    cumprod_cos_split_kernel<<<MROWS / 8, 256>>>(q, qhi, qlo);
    cumprod_cos_split_kernel<<<MROWS / 8, 256>>>(k, khi, klo);

    // role swap: attention-Q = quantum(k-proj), attention-K = quantum(q-proj)
    dim3 ga(TQ / 128, NH, NB);
    attention_tc_kernel<<<ga, 256, AT_SMEM_TOTAL>>>(khi, klo, qhi, qlo, vthi, vtlo, aohi, aolo);

    // output projection
    dim3 go(EDIM / 256, MROWS / 128, 1);
    gemm_tc2_kernel<<<go, 512, GEMM_SMEM>>>(aohi, aolo, wthi, wtlo, 3,
                                            bo, bo, bo, out, out, nullptr, nullptr, -1);
}

// round 15
// speedup vs baseline: 9.1541x; 1.1337x over previous
#include <cuda_runtime.h>
#include <cuda_bf16.h>
#include <math.h>
#include <stdint.h>

#define EDIM 1024
#define NH   16
#define HD   64
#define TQ   2048
#define NB   4
#define MROWS (NB*TQ)   // 8192

#if defined(__CUDA_ARCH_FEAT_SM103_ALL) || defined(__CUDA_ARCH_FEAT_SM100_ALL) || \
    defined(__CUDA_ARCH_FEAT_SM101_ALL) || defined(__CUDA_ARCH_SPECIFIC__)
#define TCGEN05_OK 1
#endif

// ---------------- scratch (device globals: no allocations allowed) ----------
__device__ float g_q [MROWS*EDIM];
__device__ float g_k [MROWS*EDIM];
__device__ __nv_bfloat16 g_xhi [MROWS*EDIM];
__device__ __nv_bfloat16 g_xlo [MROWS*EDIM];
__device__ __nv_bfloat16 g_qhi [MROWS*EDIM];
__device__ __nv_bfloat16 g_qlo [MROWS*EDIM];
__device__ __nv_bfloat16 g_khi [MROWS*EDIM];
__device__ __nv_bfloat16 g_klo [MROWS*EDIM];
__device__ __nv_bfloat16 g_vthi[MROWS*EDIM];   // V^T per (b,h): [64 d][2048 tok]
__device__ __nv_bfloat16 g_vtlo[MROWS*EDIM];
__device__ __nv_bfloat16 g_aohi[MROWS*EDIM];
__device__ __nv_bfloat16 g_aolo[MROWS*EDIM];
__device__ __nv_bfloat16 g_wthi[4*EDIM*EDIM];   // W^T (N-major rows, K contiguous)
__device__ __nv_bfloat16 g_wtlo[4*EDIM*EDIM];

// ======================= PTX helpers (sm_103a) ==============================
__device__ __forceinline__ uint32_t smem_to_u32(const void* p) {
    uint32_t a;
    asm("{ .reg .u64 t; cvta.to.shared.u64 t, %1; cvt.u32.u64 %0, t; }" : "=r"(a) : "l"(p));
    return a;
}
__device__ __forceinline__ uint32_t elect_one_pred() {
    uint32_t pred;
    asm volatile("{\n\t.reg .pred p;\n\telect.sync _|p, 0xFFFFFFFF;\n\tselp.b32 %0, 1, 0, p;\n\t}" : "=r"(pred));
    return pred;
}
#define MBARRIER_INIT(mbar, count) \
    asm volatile("mbarrier.init.shared.b64 [%0], %1;" :: "r"((uint32_t)(mbar)), "r"((uint32_t)(count)) : "memory")
#define MBARRIER_WAIT_PARITY(mbar_smem_addr, phase_parity) do { \
    uint32_t _mbar = (uint32_t)(mbar_smem_addr); \
    uint32_t _parity = (uint32_t)(phase_parity); \
    uint32_t _done; \
    asm volatile("{\n\t.reg .pred p;\n\tmbarrier.try_wait.parity.acquire.cta.shared::cta.b64 p, [%1], %2;\n\tselp.b32 %0, 1, 0, p;\n\t}" \
        : "=r"(_done) : "r"(_mbar), "r"(_parity) : "memory"); \
    if (!_done) { \
        asm volatile("{\n\t.reg .pred P1;\n\tWAIT_LOOP_%=:\n\t" \
            "mbarrier.try_wait.parity.acquire.cta.shared::cta.b64 P1, [%0], %1, 0x989680;\n\t" \
            "@P1 bra.uni WAIT_DONE_%=;\n\tbra.uni WAIT_LOOP_%=;\n\tWAIT_DONE_%=:\n\t}" \
            :: "r"(_mbar), "r"(_parity) : "memory"); \
    } \
} while(0)

#define CP_ASYNC16(dst, src) \
    asm volatile("cp.async.cg.shared.global [%0], [%1], 16;" :: "r"((uint32_t)(dst)), "l"(src) : "memory")
#define CP_COMMIT() asm volatile("cp.async.commit_group;" ::: "memory")
#define CP_WAIT0()  asm volatile("cp.async.wait_group 0;" ::: "memory")
#define CP_WAIT1()  asm volatile("cp.async.wait_group 1;" ::: "memory")

#ifdef TCGEN05_OK
#define TCGEN05_ALLOC(smem_addr, nCols) \
    asm volatile("tcgen05.alloc.cta_group::1.sync.aligned.shared::cta.b32 [%0], %1;" \
        :: "r"((uint32_t)(smem_addr)), "r"((uint32_t)(nCols)) : "memory")
#define TCGEN05_DEALLOC(tmem_addr, nCols) \
    asm volatile("tcgen05.dealloc.cta_group::1.sync.aligned.b32 %0, %1;" :: "r"(tmem_addr), "r"((uint32_t)(nCols)))
#define TCGEN05_RELINQUISH() \
    asm volatile("tcgen05.relinquish_alloc_permit.cta_group::1.sync.aligned;")
#define TCGEN05_COMMIT(mbar) \
    asm volatile("tcgen05.commit.cta_group::1.mbarrier::arrive::one.shared::cluster.b64 [%0];" \
        :: "r"((uint32_t)(mbar)) : "memory")
#define TCGEN05_FENCE_BEFORE() asm volatile("tcgen05.fence::before_thread_sync;" ::: "memory")
#define TCGEN05_FENCE_AFTER()  asm volatile("tcgen05.fence::after_thread_sync;" ::: "memory")
#define TCGEN05_WAIT_LD()      asm volatile("tcgen05.wait::ld.sync.aligned;" ::: "memory")
#define TCGEN05_WAIT_ST()      asm volatile("tcgen05.wait::st.sync.aligned;" ::: "memory")

#define TCGEN05_LD_32X32B_X32(r, tmem_addr) \
    asm volatile("tcgen05.ld.sync.aligned.32x32b.x32.b32 " \
        "{%0, %1, %2, %3, %4, %5, %6, %7, %8, %9, %10, %11, %12, %13, %14, %15, " \
        " %16, %17, %18, %19, %20, %21, %22, %23, %24, %25, %26, %27, %28, %29, %30, %31}, [%32];" \
        : "=r"((r)[0]),  "=r"((r)[1]),  "=r"((r)[2]),  "=r"((r)[3]), \
          "=r"((r)[4]),  "=r"((r)[5]),  "=r"((r)[6]),  "=r"((r)[7]), \
          "=r"((r)[8]),  "=r"((r)[9]),  "=r"((r)[10]), "=r"((r)[11]), \
          "=r"((r)[12]), "=r"((r)[13]), "=r"((r)[14]), "=r"((r)[15]), \
          "=r"((r)[16]), "=r"((r)[17]), "=r"((r)[18]), "=r"((r)[19]), \
          "=r"((r)[20]), "=r"((r)[21]), "=r"((r)[22]), "=r"((r)[23]), \
          "=r"((r)[24]), "=r"((r)[25]), "=r"((r)[26]), "=r"((r)[27]), \
          "=r"((r)[28]), "=r"((r)[29]), "=r"((r)[30]), "=r"((r)[31]) \
        : "r"(tmem_addr))

#define TCGEN05_ST_32X32B_X32(tmem_addr, r) \
    asm volatile("tcgen05.st.sync.aligned.32x32b.x32.b32 [%0], " \
        "{%1, %2, %3, %4, %5, %6, %7, %8, %9, %10, %11, %12, %13, %14, %15, %16, " \
        " %17, %18, %19, %20, %21, %22, %23, %24, %25, %26, %27, %28, %29, %30, %31, %32};" \
        :: "r"(tmem_addr), \
           "r"((r)[0]),  "r"((r)[1]),  "r"((r)[2]),  "r"((r)[3]), \
           "r"((r)[4]),  "r"((r)[5]),  "r"((r)[6]),  "r"((r)[7]), \
           "r"((r)[8]),  "r"((r)[9]),  "r"((r)[10]), "r"((r)[11]), \
           "r"((r)[12]), "r"((r)[13]), "r"((r)[14]), "r"((r)[15]), \
           "r"((r)[16]), "r"((r)[17]), "r"((r)[18]), "r"((r)[19]), \
           "r"((r)[20]), "r"((r)[21]), "r"((r)[22]), "r"((r)[23]), \
           "r"((r)[24]), "r"((r)[25]), "r"((r)[26]), "r"((r)[27]), \
           "r"((r)[28]), "r"((r)[29]), "r"((r)[30]), "r"((r)[31]) \
        : "memory")

__device__ __forceinline__ void mma_f16_ss_cg1(uint32_t d, uint64_t a, uint64_t b,
                                               uint32_t idesc, uint32_t en) {
    asm volatile(
        "{\n\t.reg .pred p;\n\tsetp.ne.u32 p, %5, 0;\n\t"
        "tcgen05.mma.cta_group::1.kind::f16 [%0], %1, %2, %3, {%4,%4,%4,%4}, p;\n\t}"
        :: "r"(d), "l"(a), "l"(b), "r"(idesc), "r"(0u), "r"(en) : "memory");
}
// TS form: A resident in TMEM (validated by test_mma.cu / test_mma_iter.cu)
__device__ __forceinline__ void mma_f16_ts_cg1(uint32_t d, uint32_t a_tmem, uint64_t b,
                                               uint32_t idesc, uint32_t en) {
    asm volatile(
        "{\n\t.reg .pred p;\n\tsetp.ne.u32 p, %5, 0;\n\t"
        "tcgen05.mma.cta_group::1.kind::f16 [%0], [%1], %2, %3, {%4,%4,%4,%4}, p;\n\t}"
        :: "r"(d), "r"(a_tmem), "l"(b), "r"(idesc), "r"(0u), "r"(en) : "memory");
}
#endif // TCGEN05_OK

// K-major SW128 descriptor (LBO=1, SBO=64)
static constexpr uint64_t SMEM_DESC_BASE_SW128 =
    (uint64_t(2)  << 61) | (uint64_t(1) << 46) | (uint64_t(64) << 32) | (uint64_t(1) << 16);
#define MAKE_SMEM_DESC(base_addr) (SMEM_DESC_BASE_SW128 | ((uint64_t)((base_addr) >> 4) & 0x3FFF))

// idesc kind::f16 bf16/F32: M=128 N=128 and M=128 N=64
#define IDESC_S  0x8200490u
#define IDESC_PV 0x8100490u

// ======================= tcgen05 GEMM v2 (cp.async, 128x256 tile) ===========
#define G2_STAGE_BYTES 98304
#define G2_HDR 1024
#define GEMM_SMEM (G2_HDR + 2*G2_STAGE_BYTES)   // 197632

__device__ __forceinline__ void gemm_cp_stage(
    uint32_t sdst, const __nv_bfloat16* Ahi, const __nv_bfloat16* Alo,
    const __nv_bfloat16* Bhi, const __nv_bfloat16* Blo,
    int bm, int bnw, int c, int tid)
{
#pragma unroll
    for (int j = 0; j < 2; j++) {
        const int i = j * 512 + tid;
        const int r = i >> 3, g = i & 7;
        uint32_t off = (uint32_t)(r * 128 + g * 16);
        off ^= (off >> 3) & 0x70;
        const size_t go = (((size_t)(bm + r)) << 10) + c * 64 + g * 8;
        CP_ASYNC16(sdst + off,         Ahi + go);
        CP_ASYNC16(sdst + 16384 + off, Alo + go);
    }
#pragma unroll
    for (int j = 0; j < 4; j++) {
        const int i = j * 512 + tid;
        const int r = i >> 3, g = i & 7;
        uint32_t off = (uint32_t)(r * 128 + g * 16);
        off ^= (off >> 3) & 0x70;
        const size_t go = (((size_t)(bnw + r)) << 10) + c * 64 + g * 8;
        CP_ASYNC16(sdst + 32768 + off, Bhi + go);
        CP_ASYNC16(sdst + 65536 + off, Blo + go);
    }
}

__global__ __launch_bounds__(512, 1)
void gemm_tc2_kernel(const __nv_bfloat16* __restrict__ Ahi,
                     const __nv_bfloat16* __restrict__ Alo,
                     const __nv_bfloat16* __restrict__ WThi,
                     const __nv_bfloat16* __restrict__ WTlo,
                     int wbase,
                     const float* __restrict__ b0,
                     const float* __restrict__ b1,
                     const float* __restrict__ b2,
                     float* __restrict__ C0,
                     float* __restrict__ C1,
                     __nv_bfloat16* __restrict__ Vthi,
                     __nv_bfloat16* __restrict__ Vtlo,
                     int vz)
{
#ifdef TCGEN05_OK
    extern __shared__ char smem[];
    const uint32_t sbase = smem_to_u32(smem);
    const int tid = threadIdx.x;
    const int wid = tid >> 5;
    const int lid = tid & 31;
    const int bm = blockIdx.y * 128;
    const int bn = blockIdx.x * 256;
    const int z  = blockIdx.z;
    const int w  = wbase + z;
    const float* bias = (z == 0) ? b0 : (z == 1) ? b1 : b2;
    float* Cout = (z == 0) ? C0 : C1;
    const bool vmode = (z == vz);
    const int bnw = w * 1024 + bn;

    if (wid == 0) TCGEN05_ALLOC(sbase + 0, 256);
    if (tid == 0) {
        MBARRIER_INIT(sbase + 16, 1);
        MBARRIER_INIT(sbase + 24, 1);
        MBARRIER_INIT(sbase + 32, 1);
    }
    __syncthreads();
    uint32_t tmem;
    asm volatile("ld.shared.b32 %0, [%1];" : "=r"(tmem) : "r"(sbase + 0));

    gemm_cp_stage(sbase + G2_HDR, Ahi, Alo, WThi, WTlo, bm, bnw, 0, tid);
    CP_COMMIT();

    int phD0 = 0, phD1 = 0;
    for (int c = 0; c < 16; c++) {
        if (c + 1 < 16) {
            const int b2s = (c + 1) & 1;
            if (c + 1 >= 2) {
                if (b2s == 0) { MBARRIER_WAIT_PARITY(sbase + 16, phD0); phD0 ^= 1; }
                else          { MBARRIER_WAIT_PARITY(sbase + 24, phD1); phD1 ^= 1; }
            }
            gemm_cp_stage(sbase + G2_HDR + b2s * G2_STAGE_BYTES,
                          Ahi, Alo, WThi, WTlo, bm, bnw, c + 1, tid);
            CP_COMMIT();
            CP_WAIT1();
        } else {
            CP_WAIT0();
        }
        __syncthreads();

        if (wid == 0) {
            TCGEN05_FENCE_AFTER();
            if (elect_one_pred()) {
                asm volatile("fence.proxy.async.shared::cta;" ::: "memory");
                const uint32_t stg = sbase + G2_HDR + (c & 1) * G2_STAGE_BYTES;
                const uint64_t dAh = MAKE_SMEM_DESC(stg + 0);
                const uint64_t dAl = MAKE_SMEM_DESC(stg + 16384);
                const uint64_t dBh = MAKE_SMEM_DESC(stg + 32768);
                const uint64_t dBl = MAKE_SMEM_DESC(stg + 65536);
#pragma unroll
                for (int k = 0; k < 4; k++) {
#pragma unroll
                    for (int hf = 0; hf < 2; hf++) {
                        const uint64_t hb = (uint64_t)(hf * 1024);
                        const uint32_t dd = tmem + hf * 128;
                        mma_f16_ss_cg1(dd, dAh + 2*k, dBh + 2*k + hb, IDESC_S, (c > 0 || k > 0));
                        mma_f16_ss_cg1(dd, dAh + 2*k, dBl + 2*k + hb, IDESC_S, 1);
                        mma_f16_ss_cg1(dd, dAl + 2*k, dBh + 2*k + hb, IDESC_S, 1);
                    }
                }
                TCGEN05_COMMIT(sbase + 16 + 8 * (c & 1));
            }
        }
    }

    if (wid == 0) {
        if (elect_one_pred()) TCGEN05_COMMIT(sbase + 32);
    }
    MBARRIER_WAIT_PARITY(sbase + 32, 0);
    TCGEN05_FENCE_AFTER();

    {
        const int subp = wid & 3;
        const int colq = wid >> 2;
        const int row  = bm + subp * 32 + lid;
        const uint32_t woff = (uint32_t)subp << 21;
        uint32_t d0[32], d1[32];
        TCGEN05_LD_32X32B_X32(d0, tmem + woff + colq * 64);
        TCGEN05_LD_32X32B_X32(d1, tmem + woff + colq * 64 + 32);
        TCGEN05_WAIT_LD();
        if (!vmode) {
            float* cp = Cout + (size_t)row * EDIM + bn + colq * 64;
            const float* bp = bias + bn + colq * 64;
#pragma unroll
            for (int c4 = 0; c4 < 8; c4++) {
                float4 o;
                o.x = __uint_as_float(d0[c4*4+0]) + bp[c4*4+0];
                o.y = __uint_as_float(d0[c4*4+1]) + bp[c4*4+1];
                o.z = __uint_as_float(d0[c4*4+2]) + bp[c4*4+2];
                o.w = __uint_as_float(d0[c4*4+3]) + bp[c4*4+3];
                *reinterpret_cast<float4*>(cp + c4*4) = o;
            }
#pragma unroll
            for (int c4 = 0; c4 < 8; c4++) {
                float4 o;
                o.x = __uint_as_float(d1[c4*4+0]) + bp[32 + c4*4+0];
                o.y = __uint_as_float(d1[c4*4+1]) + bp[32 + c4*4+1];
                o.z = __uint_as_float(d1[c4*4+2]) + bp[32 + c4*4+2];
                o.w = __uint_as_float(d1[c4*4+3]) + bp[32 + c4*4+3];
                *reinterpret_cast<float4*>(cp + 32 + c4*4) = o;
            }
        } else {
            const int bb  = row >> 11;
            const int tok = row & (TQ - 1);
#pragma unroll
            for (int j = 0; j < 64; j++) {
                const int colg = bn + colq * 64 + j;
                const float f = __uint_as_float(j < 32 ? d0[j] : d1[j - 32]) + bias[colg];
                const __nv_bfloat16 hh = __float2bfloat16_rn(f);
                const __nv_bfloat16 ll = __float2bfloat16_rn(f - __bfloat162float(hh));
                const size_t dst = ((size_t)((bb * NH + (colg >> 6)) * HD + (colg & 63))) * TQ + tok;
                Vthi[dst] = hh;
                Vtlo[dst] = ll;
            }
        }
    }
    __syncthreads();
    if (wid == 0) {
        TCGEN05_RELINQUISH();
        TCGEN05_DEALLOC(tmem, 256);
    }
#endif
}

// ======================= tensor-core flash attention v3 =====================
// P in TMEM (TS-mode PV), V ring 3-deep, K ring 2-deep.
// TMEM cols: S0 @0, S1 @128, O @256, Phi @320 (64), Plo @384 (64). Alloc 512.
#define AT_LPART 1024
#define AT_QHI   2048
#define AT_QLO   (AT_QHI + 16384)
#define AT_K0    (AT_QLO + 16384)         // 34816 ; 2 slots x 32KB (hi +0, lo +16384)
#define AT_V0    (AT_K0 + 2*32768)        // 100352 ; 3 slots x 32KB
#define AT_SMEM_TOTAL (AT_V0 + 3*32768)   // 198656

__device__ __forceinline__ void at_cp_tile(const __nv_bfloat16* g, int tok0, int colb,
                                           uint32_t sdst, int tid)
{
#pragma unroll
    for (int j = 0; j < 4; j++) {
        const int i = j * 256 + tid;
        const int r = i >> 3, c8 = i & 7;
        uint32_t off = (uint32_t)(r * 128 + c8 * 16);
        off ^= (off >> 3) & 0x70;
        CP_ASYNC16(sdst + off, g + (((size_t)(tok0 + r)) << 10) + colb + c8 * 8);
    }
}

__device__ __forceinline__ void at_cp_vt(const __nv_bfloat16* vt, int bh, int kb,
                                         uint32_t sdst, int tid)
{
#pragma unroll
    for (int j = 0; j < 4; j++) {
        const int i = j * 256 + tid;
        const int r = i >> 4, c16 = i & 15;
        uint32_t off = (uint32_t)((r >> 3) * 1024 + (c16 >> 3) * 8192 + (r & 7) * 128 + (c16 & 7) * 16);
        off ^= (off >> 3) & 0x70;
        CP_ASYNC16(sdst + off, vt + ((size_t)(bh * HD + r)) * TQ + kb + c16 * 8);
    }
}

__global__ __launch_bounds__(256, 1)
void attention_tc_kernel(const __nv_bfloat16* __restrict__ Qhi_g,
                         const __nv_bfloat16* __restrict__ Qlo_g,
                         const __nv_bfloat16* __restrict__ Khi_g,
                         const __nv_bfloat16* __restrict__ Klo_g,
                         const __nv_bfloat16* __restrict__ Vthi_g,
                         const __nv_bfloat16* __restrict__ Vtlo_g,
                         __nv_bfloat16* __restrict__ Ohi_g,
                         __nv_bfloat16* __restrict__ Olo_g)
{
#ifdef TCGEN05_OK
    extern __shared__ char smem[];
    const uint32_t sbase = smem_to_u32(smem);
    const int tid = threadIdx.x;
    const int wid = tid >> 5;
    const int lid = tid & 31;
    const int b = blockIdx.z, h = blockIdx.y;
    const int bh = b * NH + h;
    const int tok0 = b * TQ + blockIdx.x * 128;
    const int colb = h * HD;
    const uint32_t mbarS = sbase + 16, mbarO = sbase + 24;

    if (wid == 0) TCGEN05_ALLOC(sbase + 0, 512);
    if (tid == 0) { MBARRIER_INIT(mbarS, 1); MBARRIER_INIT(mbarO, 1); }
    __syncthreads();
    uint32_t tmem;
    asm volatile("ld.shared.b32 %0, [%1];" : "=r"(tmem) : "r"(sbase + 0));

    at_cp_tile(Qhi_g, tok0, colb, sbase + AT_QHI, tid);
    at_cp_tile(Qlo_g, tok0, colb, sbase + AT_QLO, tid);
    at_cp_tile(Khi_g, b * TQ, colb, sbase + AT_K0, tid);
    at_cp_tile(Klo_g, b * TQ, colb, sbase + AT_K0 + 16384, tid);
    at_cp_vt(Vthi_g, bh, 0, sbase + AT_V0, tid);
    at_cp_vt(Vtlo_g, bh, 0, sbase + AT_V0 + 16384, tid);
    CP_COMMIT();
    CP_WAIT0();
    __syncthreads();

    const uint64_t dQh = MAKE_SMEM_DESC(sbase + AT_QHI);
    const uint64_t dQl = MAKE_SMEM_DESC(sbase + AT_QLO);

    // issue S(0)
    if (wid == 0) {
        TCGEN05_FENCE_AFTER();
        if (elect_one_pred()) {
            asm volatile("fence.proxy.async.shared::cta;" ::: "memory");
            const uint64_t dKh = MAKE_SMEM_DESC(sbase + AT_K0);
            const uint64_t dKl = MAKE_SMEM_DESC(sbase + AT_K0 + 16384);
#pragma unroll
            for (int k = 0; k < 4; k++) {
                mma_f16_ss_cg1(tmem + 0, dQh + 2*k, dKh + 2*k, IDESC_S, (k > 0));
                mma_f16_ss_cg1(tmem + 0, dQh + 2*k, dKl + 2*k, IDESC_S, 1);
                mma_f16_ss_cg1(tmem + 0, dQl + 2*k, dKh + 2*k, IDESC_S, 1);
            }
            TCGEN05_COMMIT(mbarS);
        }
    }

    const int subp = wid & 3;
    const int half = wid >> 2;
    const int qrow = subp * 32 + lid;
    const uint32_t loff = (uint32_t)subp << 21;
    float l_part = 0.0f;
    const float CEX = 0.125f * 1.44269504f;

    for (int t = 0; t < 16; t++) {
        // fire loads(t+1): K slot (t+1)&1 (freed: S(t-1) done), V slot (t+1)%3
        // (freed: PV(t-2) done — observed during iter t-1's pre-STTM wait)
        if (t + 1 < 16) {
            const int kb = (t + 1) * 128;
            const uint32_t ks = sbase + AT_K0 + ((t + 1) & 1) * 32768;
            const uint32_t vs = sbase + AT_V0 + ((t + 1) % 3) * 32768;
            at_cp_tile(Khi_g, b * TQ + kb, colb, ks, tid);
            at_cp_tile(Klo_g, b * TQ + kb, colb, ks + 16384, tid);
            at_cp_vt(Vthi_g, bh, kb, vs, tid);
            at_cp_vt(Vtlo_g, bh, kb, vs + 16384, tid);
            CP_COMMIT();
        }

        // wait S(t), softmax into registers
        MBARRIER_WAIT_PARITY(mbarS, t & 1);
        TCGEN05_FENCE_AFTER();

        uint32_t hiw[32], low[32];
        {
            const uint32_t sb = tmem + (t & 1) * 128 + half * 64 + loff;
            uint32_t r0[32], r1[32];
            TCGEN05_LD_32X32B_X32(r0, sb);
            TCGEN05_LD_32X32B_X32(r1, sb + 32);
            TCGEN05_WAIT_LD();
            float p[64];
            float psum = 0.0f;
#pragma unroll
            for (int j = 0; j < 32; j++) {
                float a0 = __uint_as_float(r0[j]) * CEX;
                float a1 = __uint_as_float(r1[j]) * CEX;
                float e0, e1;
                asm("ex2.approx.f32 %0, %1;" : "=f"(e0) : "f"(a0));
                asm("ex2.approx.f32 %0, %1;" : "=f"(e1) : "f"(a1));
                p[j] = e0; p[32 + j] = e1;
                psum += e0 + e1;
            }
            l_part += psum;
#pragma unroll
            for (int j2 = 0; j2 < 32; j2++) {
                float p0 = p[2*j2], p1 = p[2*j2 + 1];
                uint32_t wh;
                asm("cvt.rn.bf16x2.f32 %0, %1, %2;" : "=r"(wh) : "f"(p1), "f"(p0));
                float h0 = __uint_as_float(wh << 16);
                float h1 = __uint_as_float(wh & 0xffff0000u);
                float q0 = p0 - h0, q1 = p1 - h1;
                uint32_t wl;
                asm("cvt.rn.bf16x2.f32 %0, %1, %2;" : "=r"(wl) : "f"(q1), "f"(q0));
                hiw[j2] = wh; low[j2] = wl;
            }
        }

        // P TMEM is single-buffered: PV(t-1) must be done before overwrite
        if (t >= 1) { MBARRIER_WAIT_PARITY(mbarO, (t - 1) & 1); TCGEN05_FENCE_AFTER(); }

        // STTM P hi/lo: warp(subp,half) writes rows subp*32.., bf16x2 cols half*32..
        TCGEN05_ST_32X32B_X32(tmem + 320 + half * 32 + loff, hiw);
        TCGEN05_ST_32X32B_X32(tmem + 384 + half * 32 + loff, low);
        TCGEN05_WAIT_ST();
        TCGEN05_FENCE_BEFORE();
        __syncthreads();

        // PV(t): TS-mode, A = P in TMEM, B = V^T K-major (validated layout)
        if (wid == 0) {
            TCGEN05_FENCE_AFTER();
            if (elect_one_pred()) {
                const uint32_t vs = sbase + AT_V0 + (t % 3) * 32768;
                const uint64_t dVh = MAKE_SMEM_DESC(vs);
                const uint64_t dVl = MAKE_SMEM_DESC(vs + 16384);
#pragma unroll
                for (int s = 0; s < 8; s++) {
                    const uint64_t vb = (uint64_t)((s & 3) * 2 + (s >> 2) * 512);
                    const uint32_t pah = tmem + 320 + s * 8;
                    const uint32_t pal = tmem + 384 + s * 8;
                    mma_f16_ts_cg1(tmem + 256, pah, dVh + vb, IDESC_PV, (t > 0 || s > 0));
                    mma_f16_ts_cg1(tmem + 256, pah, dVl + vb, IDESC_PV, 1);
                    mma_f16_ts_cg1(tmem + 256, pal, dVh + vb, IDESC_PV, 1);
                }
                TCGEN05_COMMIT(mbarO);
            }
        }

        // loads(t+1) done -> issue S(t+1) (overlaps PV(t))
        if (t + 1 < 16) {
            CP_WAIT0();
            __syncthreads();
            if (wid == 0) {
                if (elect_one_pred()) {
                    asm volatile("fence.proxy.async.shared::cta;" ::: "memory");
                    const uint32_t ks = sbase + AT_K0 + ((t + 1) & 1) * 32768;
                    const uint64_t dKh = MAKE_SMEM_DESC(ks);
                    const uint64_t dKl = MAKE_SMEM_DESC(ks + 16384);
                    const uint32_t sdst = tmem + ((t + 1) & 1) * 128;
#pragma unroll
                    for (int k = 0; k < 4; k++) {
                        mma_f16_ss_cg1(sdst, dQh + 2*k, dKh + 2*k, IDESC_S, (k > 0));
                        mma_f16_ss_cg1(sdst, dQh + 2*k, dKl + 2*k, IDESC_S, 1);
                        mma_f16_ss_cg1(sdst, dQl + 2*k, dKh + 2*k, IDESC_S, 1);
                    }
                    TCGEN05_COMMIT(mbarS);
                }
            }
        }
    }

    *reinterpret_cast<float*>(smem + AT_LPART + (qrow * 2 + half) * 4) = l_part;
    __syncthreads();

    MBARRIER_WAIT_PARITY(mbarO, 1);
    TCGEN05_FENCE_AFTER();

    if (wid < 4) {
        const float lsum =
            *reinterpret_cast<float*>(smem + AT_LPART + (qrow * 2 + 0) * 4) +
            *reinterpret_cast<float*>(smem + AT_LPART + (qrow * 2 + 1) * 4);
        const float inv = 1.0f / lsum;
        uint32_t o0[32], o1[32];
        TCGEN05_LD_32X32B_X32(o0, tmem + 256 + loff);
        TCGEN05_LD_32X32B_X32(o1, tmem + 288 + loff);
        TCGEN05_WAIT_LD();
        uint32_t hibuf[32], lobuf[32];
#pragma unroll
        for (int c = 0; c < 32; c++) {
            float f0 = __uint_as_float(c < 16 ? o0[2*c]   : o1[2*(c-16)])   * inv;
            float f1 = __uint_as_float(c < 16 ? o0[2*c+1] : o1[2*(c-16)+1]) * inv;
            uint32_t wh;
            asm("cvt.rn.bf16x2.f32 %0, %1, %2;" : "=r"(wh) : "f"(f1), "f"(f0));
            float h0 = __uint_as_float(wh << 16);
            float h1 = __uint_as_float(wh & 0xffff0000u);
            float q0 = f0 - h0, q1 = f1 - h1;
            uint32_t wl;
            asm("cvt.rn.bf16x2.f32 %0, %1, %2;" : "=r"(wl) : "f"(q1), "f"(q0));
            hibuf[c] = wh; lobuf[c] = wl;
        }
        const size_t rowoff = (((size_t)(tok0 + qrow)) << 10) + colb;
#pragma unroll
        for (int v4 = 0; v4 < 8; v4++) {
            *reinterpret_cast<uint4*>(Ohi_g + rowoff + v4 * 8) =
                *reinterpret_cast<uint4*>(&hibuf[v4 * 4]);
            *reinterpret_cast<uint4*>(Olo_g + rowoff + v4 * 8) =
                *reinterpret_cast<uint4*>(&lobuf[v4 * 4]);
        }
    }
    __syncthreads();
    if (wid == 0) {
        TCGEN05_RELINQUISH();
        TCGEN05_DEALLOC(tmem, 512);
    }
#endif
}

// ---------------- fp32 -> bf16 hi/lo split ----------------------------------
__global__ __launch_bounds__(256)
void split_bf16_kernel(const float4* __restrict__ in,
                       uint2* __restrict__ hi, uint2* __restrict__ lo, int n4)
{
    const int i = blockIdx.x * blockDim.x + threadIdx.x;
    if (i >= n4) return;
    float4 v = in[i];
    __nv_bfloat16 h0 = __float2bfloat16_rn(v.x);
    __nv_bfloat16 h1 = __float2bfloat16_rn(v.y);
    __nv_bfloat16 h2 = __float2bfloat16_rn(v.z);
    __nv_bfloat16 h3 = __float2bfloat16_rn(v.w);
    __nv_bfloat16 l0 = __float2bfloat16_rn(v.x - __bfloat162float(h0));
    __nv_bfloat16 l1 = __float2bfloat16_rn(v.y - __bfloat162float(h1));
    __nv_bfloat16 l2 = __float2bfloat16_rn(v.z - __bfloat162float(h2));
    __nv_bfloat16 l3 = __float2bfloat16_rn(v.w - __bfloat162float(h3));
    uint2 ph, pl;
    ph.x = ((uint32_t)__bfloat16_as_ushort(h1) << 16) | __bfloat16_as_ushort(h0);
    ph.y = ((uint32_t)__bfloat16_as_ushort(h3) << 16) | __bfloat16_as_ushort(h2);
    pl.x = ((uint32_t)__bfloat16_as_ushort(l1) << 16) | __bfloat16_as_ushort(l0);
    pl.y = ((uint32_t)__bfloat16_as_ushort(l3) << 16) | __bfloat16_as_ushort(l2);
    hi[i] = ph;
    lo[i] = pl;
}

// ---------------- W [K,N] -> W^T hi/lo bf16 [N,K], all 4 weights ------------
__global__ __launch_bounds__(256)
void transpose_split4_kernel(const float* __restrict__ W0,
                             const float* __restrict__ W1,
                             const float* __restrict__ W2,
                             const float* __restrict__ W3,
                             __nv_bfloat16* __restrict__ Thi,
                             __nv_bfloat16* __restrict__ Tlo)
{
    __shared__ float tile[32][33];
    const int w = blockIdx.z;
    const float* W = (w == 0) ? W0 : (w == 1) ? W1 : (w == 2) ? W2 : W3;
    __nv_bfloat16* thi = Thi + (size_t)w * EDIM * EDIM;
    __nv_bfloat16* tlo = Tlo + (size_t)w * EDIM * EDIM;
    const int bx = blockIdx.x * 32;
    const int by = blockIdx.y * 32;
    const int tx = threadIdx.x & 31, ty = threadIdx.x >> 5;
#pragma unroll
    for (int j = ty; j < 32; j += 8)
        tile[j][tx] = W[(size_t)(by + j) * EDIM + bx + tx];
    __syncthreads();
#pragma unroll
    for (int j = ty; j < 32; j += 8) {
        float v = tile[tx][j];
        __nv_bfloat16 h = __float2bfloat16_rn(v);
        __nv_bfloat16 l = __float2bfloat16_rn(v - __bfloat162float(h));
        thi[(size_t)(bx + j) * EDIM + by + tx] = h;
        tlo[(size_t)(bx + j) * EDIM + by + tx] = l;
    }
}

// ---------------- cumprod(cos(x)) -> bf16 hi/lo, warp-per-row, z picks q/k --
__global__ __launch_bounds__(256)
void cumprod_cos_split_kernel(const float* __restrict__ in0,
                              __nv_bfloat16* __restrict__ hi0,
                              __nv_bfloat16* __restrict__ lo0,
                              const float* __restrict__ in1,
                              __nv_bfloat16* __restrict__ hi1,
                              __nv_bfloat16* __restrict__ lo1)
{
    const float* in = blockIdx.z ? in1 : in0;
    __nv_bfloat16* hi = blockIdx.z ? hi1 : hi0;
    __nv_bfloat16* lo = blockIdx.z ? lo1 : lo0;
    const int row  = blockIdx.x * 8 + (threadIdx.x >> 5);
    const int lane = threadIdx.x & 31;
    const float* rp = in + (size_t)row * EDIM + lane * 32;

    float v[32];
#pragma unroll
    for (int i = 0; i < 8; i++) {
        float4 f = reinterpret_cast<const float4*>(rp)[i];
        v[4*i+0] = f.x; v[4*i+1] = f.y; v[4*i+2] = f.z; v[4*i+3] = f.w;
    }
    float c = 1.0f;
#pragma unroll
    for (int i = 0; i < 32; i++) { c *= cosf(v[i]); v[i] = c; }
    float p = c;
#pragma unroll
    for (int off = 1; off < 32; off <<= 1) {
        float t = __shfl_up_sync(0xffffffffu, p, off);
        if (lane >= off) p *= t;
    }
    float excl = __shfl_up_sync(0xffffffffu, p, 1);
    if (lane == 0) excl = 1.0f;

    uint32_t hiw[16], low[16];
#pragma unroll
    for (int j = 0; j < 16; j++) {
        float f0 = v[2*j] * excl;
        float f1 = v[2*j + 1] * excl;
        uint32_t wh;
        asm("cvt.rn.bf16x2.f32 %0, %1, %2;" : "=r"(wh) : "f"(f1), "f"(f0));
        float h0 = __uint_as_float(wh << 16);
        float h1 = __uint_as_float(wh & 0xffff0000u);
        float q0 = f0 - h0, q1 = f1 - h1;
        uint32_t wl;
        asm("cvt.rn.bf16x2.f32 %0, %1, %2;" : "=r"(wl) : "f"(q1), "f"(q0));
        hiw[j] = wh; low[j] = wl;
    }
    __nv_bfloat16* hp = hi + (size_t)row * EDIM + lane * 32;
    __nv_bfloat16* lp = lo + (size_t)row * EDIM + lane * 32;
#pragma unroll
    for (int j4 = 0; j4 < 4; j4++) {
        *reinterpret_cast<uint4*>(hp + j4 * 8) = *reinterpret_cast<uint4*>(&hiw[j4 * 4]);
        *reinterpret_cast<uint4*>(lp + j4 * 8) = *reinterpret_cast<uint4*>(&low[j4 * 4]);
    }
}

// ---------------- launch ----------------------------------------------------
extern "C" void kernel_launch(void* const* d_in, const int* in_sizes, int n_in,
                              void* d_out, int out_size)
{
    const float* x  = (const float*)d_in[0];
    const float* Wq = (const float*)d_in[1];
    const float* bq = (const float*)d_in[2];
    const float* Wk = (const float*)d_in[3];
    const float* bk = (const float*)d_in[4];
    const float* Wv = (const float*)d_in[5];
    const float* bv = (const float*)d_in[6];
    const float* Wo = (const float*)d_in[7];
    const float* bo = (const float*)d_in[8];
    float* out = (float*)d_out;

    float *q, *k;
    __nv_bfloat16 *xhi, *xlo, *qhi, *qlo, *khi, *klo, *vthi, *vtlo, *aohi, *aolo, *wthi, *wtlo;
    cudaGetSymbolAddress((void**)&q,    g_q);
    cudaGetSymbolAddress((void**)&k,    g_k);
    cudaGetSymbolAddress((void**)&xhi,  g_xhi);
    cudaGetSymbolAddress((void**)&xlo,  g_xlo);
    cudaGetSymbolAddress((void**)&qhi,  g_qhi);
    cudaGetSymbolAddress((void**)&qlo,  g_qlo);
    cudaGetSymbolAddress((void**)&khi,  g_khi);
    cudaGetSymbolAddress((void**)&klo,  g_klo);
    cudaGetSymbolAddress((void**)&vthi, g_vthi);
    cudaGetSymbolAddress((void**)&vtlo, g_vtlo);
    cudaGetSymbolAddress((void**)&aohi, g_aohi);
    cudaGetSymbolAddress((void**)&aolo, g_aolo);
    cudaGetSymbolAddress((void**)&wthi, g_wthi);
    cudaGetSymbolAddress((void**)&wtlo, g_wtlo);

    cudaFuncSetAttribute(gemm_tc2_kernel, cudaFuncAttributeMaxDynamicSharedMemorySize, GEMM_SMEM);
    cudaFuncSetAttribute(attention_tc_kernel, cudaFuncAttributeMaxDynamicSharedMemorySize, AT_SMEM_TOTAL);

    const int n4 = MROWS * EDIM / 4;
    split_bf16_kernel<<<(n4 + 255) / 256, 256>>>((const float4*)x, (uint2*)xhi, (uint2*)xlo, n4);

    dim3 tg4(32, 32, 4);
    transpose_split4_kernel<<<tg4, 256>>>(Wq, Wk, Wv, Wo, wthi, wtlo);

    // fused Q/K/V projection (z=0: q, z=1: k, z=2: V^T epilogue)
    dim3 gqkv(EDIM / 256, MROWS / 128, 3);
    gemm_tc2_kernel<<<gqkv, 512, GEMM_SMEM>>>(xhi, xlo, wthi, wtlo, 0,
                                              bq, bk, bv, q, k, vthi, vtlo, 2);

    dim3 gc(MROWS / 8, 1, 2);
    cumprod_cos_split_kernel<<<gc, 256>>>(q, qhi, qlo, k, khi, klo);

    // role swap: attention-Q = quantum(k-proj), attention-K = quantum(q-proj)
    dim3 ga(TQ / 128, NH, NB);
    attention_tc_kernel<<<ga, 256, AT_SMEM_TOTAL>>>(khi, klo, qhi, qlo, vthi, vtlo, aohi, aolo);

    // output projection
    dim3 go(EDIM / 256, MROWS / 128, 1);
    gemm_tc2_kernel<<<go, 512, GEMM_SMEM>>>(aohi, aolo, wthi, wtlo, 3,
                                            bo, bo, bo, out, out, nullptr, nullptr, -1);
}

// round 16
// speedup vs baseline: 9.1635x; 1.0010x over previous
#include <cuda_runtime.h>
#include <cuda_bf16.h>
#include <math.h>
#include <stdint.h>

#define EDIM 1024
#define NH   16
#define HD   64
#define TQ   2048
#define NB   4
#define MROWS (NB*TQ)   // 8192

#if defined(__CUDA_ARCH_FEAT_SM103_ALL) || defined(__CUDA_ARCH_FEAT_SM100_ALL) || \
    defined(__CUDA_ARCH_FEAT_SM101_ALL) || defined(__CUDA_ARCH_SPECIFIC__)
#define TCGEN05_OK 1
#endif

// ---------------- scratch (device globals: no allocations allowed) ----------
__device__ float g_q [MROWS*EDIM];
__device__ float g_k [MROWS*EDIM];
__device__ __nv_bfloat16 g_xhi [MROWS*EDIM];
__device__ __nv_bfloat16 g_xlo [MROWS*EDIM];
__device__ __nv_bfloat16 g_qhi [MROWS*EDIM];
__device__ __nv_bfloat16 g_qlo [MROWS*EDIM];
__device__ __nv_bfloat16 g_khi [MROWS*EDIM];
__device__ __nv_bfloat16 g_klo [MROWS*EDIM];
__device__ __nv_bfloat16 g_vthi[MROWS*EDIM];   // V^T per (b,h): [64 d][2048 tok]
__device__ __nv_bfloat16 g_vtlo[MROWS*EDIM];
__device__ __nv_bfloat16 g_aohi[MROWS*EDIM];
__device__ __nv_bfloat16 g_aolo[MROWS*EDIM];
__device__ __nv_bfloat16 g_wthi[4*EDIM*EDIM];   // W^T (N-major rows, K contiguous)
__device__ __nv_bfloat16 g_wtlo[4*EDIM*EDIM];

// ======================= PTX helpers (sm_103a) ==============================
__device__ __forceinline__ uint32_t smem_to_u32(const void* p) {
    uint32_t a;
    asm("{ .reg .u64 t; cvta.to.shared.u64 t, %1; cvt.u32.u64 %0, t; }" : "=r"(a) : "l"(p));
    return a;
}
__device__ __forceinline__ uint32_t elect_one_pred() {
    uint32_t pred;
    asm volatile("{\n\t.reg .pred p;\n\telect.sync _|p, 0xFFFFFFFF;\n\tselp.b32 %0, 1, 0, p;\n\t}" : "=r"(pred));
    return pred;
}
#define MBARRIER_INIT(mbar, count) \
    asm volatile("mbarrier.init.shared.b64 [%0], %1;" :: "r"((uint32_t)(mbar)), "r"((uint32_t)(count)) : "memory")
#define MBARRIER_WAIT_PARITY(mbar_smem_addr, phase_parity) do { \
    uint32_t _mbar = (uint32_t)(mbar_smem_addr); \
    uint32_t _parity = (uint32_t)(phase_parity); \
    uint32_t _done; \
    asm volatile("{\n\t.reg .pred p;\n\tmbarrier.try_wait.parity.acquire.cta.shared::cta.b64 p, [%1], %2;\n\tselp.b32 %0, 1, 0, p;\n\t}" \
        : "=r"(_done) : "r"(_mbar), "r"(_parity) : "memory"); \
    if (!_done) { \
        asm volatile("{\n\t.reg .pred P1;\n\tWAIT_LOOP_%=:\n\t" \
            "mbarrier.try_wait.parity.acquire.cta.shared::cta.b64 P1, [%0], %1, 0x989680;\n\t" \
            "@P1 bra.uni WAIT_DONE_%=;\n\tbra.uni WAIT_LOOP_%=;\n\tWAIT_DONE_%=:\n\t}" \
            :: "r"(_mbar), "r"(_parity) : "memory"); \
    } \
} while(0)

#define CP_ASYNC16(dst, src) \
    asm volatile("cp.async.cg.shared.global [%0], [%1], 16;" :: "r"((uint32_t)(dst)), "l"(src) : "memory")
#define CP_COMMIT() asm volatile("cp.async.commit_group;" ::: "memory")
#define CP_WAIT0()  asm volatile("cp.async.wait_group 0;" ::: "memory")
#define CP_WAIT1()  asm volatile("cp.async.wait_group 1;" ::: "memory")

#ifdef TCGEN05_OK
#define TCGEN05_ALLOC(smem_addr, nCols) \
    asm volatile("tcgen05.alloc.cta_group::1.sync.aligned.shared::cta.b32 [%0], %1;" \
        :: "r"((uint32_t)(smem_addr)), "r"((uint32_t)(nCols)) : "memory")
#define TCGEN05_DEALLOC(tmem_addr, nCols) \
    asm volatile("tcgen05.dealloc.cta_group::1.sync.aligned.b32 %0, %1;" :: "r"(tmem_addr), "r"((uint32_t)(nCols)))
#define TCGEN05_RELINQUISH() \
    asm volatile("tcgen05.relinquish_alloc_permit.cta_group::1.sync.aligned;")
#define TCGEN05_COMMIT(mbar) \
    asm volatile("tcgen05.commit.cta_group::1.mbarrier::arrive::one.shared::cluster.b64 [%0];" \
        :: "r"((uint32_t)(mbar)) : "memory")
#define TCGEN05_FENCE_BEFORE() asm volatile("tcgen05.fence::before_thread_sync;" ::: "memory")
#define TCGEN05_FENCE_AFTER()  asm volatile("tcgen05.fence::after_thread_sync;" ::: "memory")
#define TCGEN05_WAIT_LD()      asm volatile("tcgen05.wait::ld.sync.aligned;" ::: "memory")
#define TCGEN05_WAIT_ST()      asm volatile("tcgen05.wait::st.sync.aligned;" ::: "memory")

#define TCGEN05_LD_32X32B_X32(r, tmem_addr) \
    asm volatile("tcgen05.ld.sync.aligned.32x32b.x32.b32 " \
        "{%0, %1, %2, %3, %4, %5, %6, %7, %8, %9, %10, %11, %12, %13, %14, %15, " \
        " %16, %17, %18, %19, %20, %21, %22, %23, %24, %25, %26, %27, %28, %29, %30, %31}, [%32];" \
        : "=r"((r)[0]),  "=r"((r)[1]),  "=r"((r)[2]),  "=r"((r)[3]), \
          "=r"((r)[4]),  "=r"((r)[5]),  "=r"((r)[6]),  "=r"((r)[7]), \
          "=r"((r)[8]),  "=r"((r)[9]),  "=r"((r)[10]), "=r"((r)[11]), \
          "=r"((r)[12]), "=r"((r)[13]), "=r"((r)[14]), "=r"((r)[15]), \
          "=r"((r)[16]), "=r"((r)[17]), "=r"((r)[18]), "=r"((r)[19]), \
          "=r"((r)[20]), "=r"((r)[21]), "=r"((r)[22]), "=r"((r)[23]), \
          "=r"((r)[24]), "=r"((r)[25]), "=r"((r)[26]), "=r"((r)[27]), \
          "=r"((r)[28]), "=r"((r)[29]), "=r"((r)[30]), "=r"((r)[31]) \
        : "r"(tmem_addr))

#define TCGEN05_ST_32X32B_X32(tmem_addr, r) \
    asm volatile("tcgen05.st.sync.aligned.32x32b.x32.b32 [%0], " \
        "{%1, %2, %3, %4, %5, %6, %7, %8, %9, %10, %11, %12, %13, %14, %15, %16, " \
        " %17, %18, %19, %20, %21, %22, %23, %24, %25, %26, %27, %28, %29, %30, %31, %32};" \
        :: "r"(tmem_addr), \
           "r"((r)[0]),  "r"((r)[1]),  "r"((r)[2]),  "r"((r)[3]), \
           "r"((r)[4]),  "r"((r)[5]),  "r"((r)[6]),  "r"((r)[7]), \
           "r"((r)[8]),  "r"((r)[9]),  "r"((r)[10]), "r"((r)[11]), \
           "r"((r)[12]), "r"((r)[13]), "r"((r)[14]), "r"((r)[15]), \
           "r"((r)[16]), "r"((r)[17]), "r"((r)[18]), "r"((r)[19]), \
           "r"((r)[20]), "r"((r)[21]), "r"((r)[22]), "r"((r)[23]), \
           "r"((r)[24]), "r"((r)[25]), "r"((r)[26]), "r"((r)[27]), \
           "r"((r)[28]), "r"((r)[29]), "r"((r)[30]), "r"((r)[31]) \
        : "memory")

__device__ __forceinline__ void mma_f16_ss_cg1(uint32_t d, uint64_t a, uint64_t b,
                                               uint32_t idesc, uint32_t en) {
    asm volatile(
        "{\n\t.reg .pred p;\n\tsetp.ne.u32 p, %5, 0;\n\t"
        "tcgen05.mma.cta_group::1.kind::f16 [%0], %1, %2, %3, {%4,%4,%4,%4}, p;\n\t}"
        :: "r"(d), "l"(a), "l"(b), "r"(idesc), "r"(0u), "r"(en) : "memory");
}
__device__ __forceinline__ void mma_f16_ts_cg1(uint32_t d, uint32_t a_tmem, uint64_t b,
                                               uint32_t idesc, uint32_t en) {
    asm volatile(
        "{\n\t.reg .pred p;\n\tsetp.ne.u32 p, %5, 0;\n\t"
        "tcgen05.mma.cta_group::1.kind::f16 [%0], [%1], %2, %3, {%4,%4,%4,%4}, p;\n\t}"
        :: "r"(d), "r"(a_tmem), "l"(b), "r"(idesc), "r"(0u), "r"(en) : "memory");
}
#endif // TCGEN05_OK

// K-major SW128 descriptor (LBO=1, SBO=64)
static constexpr uint64_t SMEM_DESC_BASE_SW128 =
    (uint64_t(2)  << 61) | (uint64_t(1) << 46) | (uint64_t(64) << 32) | (uint64_t(1) << 16);
#define MAKE_SMEM_DESC(base_addr) (SMEM_DESC_BASE_SW128 | ((uint64_t)((base_addr) >> 4) & 0x3FFF))

#define IDESC_S  0x8200490u
#define IDESC_PV 0x8100490u

// ======================= tcgen05 GEMM v2 (cp.async, 128x256 tile) ===========
#define G2_STAGE_BYTES 98304
#define G2_HDR 1024
#define GEMM_SMEM (G2_HDR + 2*G2_STAGE_BYTES)   // 197632

__device__ __forceinline__ void gemm_cp_stage(
    uint32_t sdst, const __nv_bfloat16* Ahi, const __nv_bfloat16* Alo,
    const __nv_bfloat16* Bhi, const __nv_bfloat16* Blo,
    int bm, int bnw, int c, int tid)
{
#pragma unroll
    for (int j = 0; j < 2; j++) {
        const int i = j * 512 + tid;
        const int r = i >> 3, g = i & 7;
        uint32_t off = (uint32_t)(r * 128 + g * 16);
        off ^= (off >> 3) & 0x70;
        const size_t go = (((size_t)(bm + r)) << 10) + c * 64 + g * 8;
        CP_ASYNC16(sdst + off,         Ahi + go);
        CP_ASYNC16(sdst + 16384 + off, Alo + go);
    }
#pragma unroll
    for (int j = 0; j < 4; j++) {
        const int i = j * 512 + tid;
        const int r = i >> 3, g = i & 7;
        uint32_t off = (uint32_t)(r * 128 + g * 16);
        off ^= (off >> 3) & 0x70;
        const size_t go = (((size_t)(bnw + r)) << 10) + c * 64 + g * 8;
        CP_ASYNC16(sdst + 32768 + off, Bhi + go);
        CP_ASYNC16(sdst + 65536 + off, Blo + go);
    }
}

__global__ __launch_bounds__(512, 1)
void gemm_tc2_kernel(const __nv_bfloat16* __restrict__ Ahi,
                     const __nv_bfloat16* __restrict__ Alo,
                     const __nv_bfloat16* __restrict__ WThi,
                     const __nv_bfloat16* __restrict__ WTlo,
                     int wbase,
                     const float* __restrict__ b0,
                     const float* __restrict__ b1,
                     const float* __restrict__ b2,
                     float* __restrict__ C0,
                     float* __restrict__ C1,
                     __nv_bfloat16* __restrict__ Vthi,
                     __nv_bfloat16* __restrict__ Vtlo,
                     int vz)
{
#ifdef TCGEN05_OK
    extern __shared__ char smem[];
    const uint32_t sbase = smem_to_u32(smem);
    const int tid = threadIdx.x;
    const int wid = tid >> 5;
    const int lid = tid & 31;
    const int bm = blockIdx.y * 128;
    const int bn = blockIdx.x * 256;
    const int z  = blockIdx.z;
    const int w  = wbase + z;
    const float* bias = (z == 0) ? b0 : (z == 1) ? b1 : b2;
    float* Cout = (z == 0) ? C0 : C1;
    const bool vmode = (z == vz);
    const int bnw = w * 1024 + bn;

    if (wid == 0) TCGEN05_ALLOC(sbase + 0, 256);
    if (tid == 0) {
        MBARRIER_INIT(sbase + 16, 1);
        MBARRIER_INIT(sbase + 24, 1);
        MBARRIER_INIT(sbase + 32, 1);
    }
    __syncthreads();
    uint32_t tmem;
    asm volatile("ld.shared.b32 %0, [%1];" : "=r"(tmem) : "r"(sbase + 0));

    gemm_cp_stage(sbase + G2_HDR, Ahi, Alo, WThi, WTlo, bm, bnw, 0, tid);
    CP_COMMIT();

    int phD0 = 0, phD1 = 0;
    for (int c = 0; c < 16; c++) {
        if (c + 1 < 16) {
            const int b2s = (c + 1) & 1;
            if (c + 1 >= 2) {
                if (b2s == 0) { MBARRIER_WAIT_PARITY(sbase + 16, phD0); phD0 ^= 1; }
                else          { MBARRIER_WAIT_PARITY(sbase + 24, phD1); phD1 ^= 1; }
            }
            gemm_cp_stage(sbase + G2_HDR + b2s * G2_STAGE_BYTES,
                          Ahi, Alo, WThi, WTlo, bm, bnw, c + 1, tid);
            CP_COMMIT();
            CP_WAIT1();
        } else {
            CP_WAIT0();
        }
        __syncthreads();

        if (wid == 0) {
            TCGEN05_FENCE_AFTER();
            if (elect_one_pred()) {
                asm volatile("fence.proxy.async.shared::cta;" ::: "memory");
                const uint32_t stg = sbase + G2_HDR + (c & 1) * G2_STAGE_BYTES;
                const uint64_t dAh = MAKE_SMEM_DESC(stg + 0);
                const uint64_t dAl = MAKE_SMEM_DESC(stg + 16384);
                const uint64_t dBh = MAKE_SMEM_DESC(stg + 32768);
                const uint64_t dBl = MAKE_SMEM_DESC(stg + 65536);
#pragma unroll
                for (int k = 0; k < 4; k++) {
#pragma unroll
                    for (int hf = 0; hf < 2; hf++) {
                        const uint64_t hb = (uint64_t)(hf * 1024);
                        const uint32_t dd = tmem + hf * 128;
                        mma_f16_ss_cg1(dd, dAh + 2*k, dBh + 2*k + hb, IDESC_S, (c > 0 || k > 0));
                        mma_f16_ss_cg1(dd, dAh + 2*k, dBl + 2*k + hb, IDESC_S, 1);
                        mma_f16_ss_cg1(dd, dAl + 2*k, dBh + 2*k + hb, IDESC_S, 1);
                    }
                }
                TCGEN05_COMMIT(sbase + 16 + 8 * (c & 1));
            }
        }
    }

    if (wid == 0) {
        if (elect_one_pred()) TCGEN05_COMMIT(sbase + 32);
    }
    MBARRIER_WAIT_PARITY(sbase + 32, 0);
    TCGEN05_FENCE_AFTER();

    {
        const int subp = wid & 3;
        const int colq = wid >> 2;
        const int row  = bm + subp * 32 + lid;
        const uint32_t woff = (uint32_t)subp << 21;
        uint32_t d0[32], d1[32];
        TCGEN05_LD_32X32B_X32(d0, tmem + woff + colq * 64);
        TCGEN05_LD_32X32B_X32(d1, tmem + woff + colq * 64 + 32);
        TCGEN05_WAIT_LD();
        if (!vmode) {
            float* cp = Cout + (size_t)row * EDIM + bn + colq * 64;
            const float* bp = bias + bn + colq * 64;
#pragma unroll
            for (int c4 = 0; c4 < 8; c4++) {
                float4 o;
                o.x = __uint_as_float(d0[c4*4+0]) + bp[c4*4+0];
                o.y = __uint_as_float(d0[c4*4+1]) + bp[c4*4+1];
                o.z = __uint_as_float(d0[c4*4+2]) + bp[c4*4+2];
                o.w = __uint_as_float(d0[c4*4+3]) + bp[c4*4+3];
                *reinterpret_cast<float4*>(cp + c4*4) = o;
            }
#pragma unroll
            for (int c4 = 0; c4 < 8; c4++) {
                float4 o;
                o.x = __uint_as_float(d1[c4*4+0]) + bp[32 + c4*4+0];
                o.y = __uint_as_float(d1[c4*4+1]) + bp[32 + c4*4+1];
                o.z = __uint_as_float(d1[c4*4+2]) + bp[32 + c4*4+2];
                o.w = __uint_as_float(d1[c4*4+3]) + bp[32 + c4*4+3];
                *reinterpret_cast<float4*>(cp + 32 + c4*4) = o;
            }
        } else {
            const int bb  = row >> 11;
            const int tok = row & (TQ - 1);
#pragma unroll
            for (int j = 0; j < 64; j++) {
                const int colg = bn + colq * 64 + j;
                const float f = __uint_as_float(j < 32 ? d0[j] : d1[j - 32]) + bias[colg];
                const __nv_bfloat16 hh = __float2bfloat16_rn(f);
                const __nv_bfloat16 ll = __float2bfloat16_rn(f - __bfloat162float(hh));
                const size_t dst = ((size_t)((bb * NH + (colg >> 6)) * HD + (colg & 63))) * TQ + tok;
                Vthi[dst] = hh;
                Vtlo[dst] = ll;
            }
        }
    }
    __syncthreads();
    if (wid == 0) {
        TCGEN05_RELINQUISH();
        TCGEN05_DEALLOC(tmem, 256);
    }
#endif
}

// ======================= tensor-core flash attention v4 =====================
// P in TMEM (TS-mode PV), V ring 3-deep, K ring 2-deep, K/V in SEPARATE
// cp.async groups so S(t+1) issues right after softmax (wait_group 1).
#define AT_LPART 1024
#define AT_QHI   2048
#define AT_QLO   (AT_QHI + 16384)
#define AT_K0    (AT_QLO + 16384)
#define AT_V0    (AT_K0 + 2*32768)
#define AT_SMEM_TOTAL (AT_V0 + 3*32768)   // 198656

__device__ __forceinline__ void at_cp_tile(const __nv_bfloat16* g, int tok0, int colb,
                                           uint32_t sdst, int tid)
{
#pragma unroll
    for (int j = 0; j < 4; j++) {
        const int i = j * 256 + tid;
        const int r = i >> 3, c8 = i & 7;
        uint32_t off = (uint32_t)(r * 128 + c8 * 16);
        off ^= (off >> 3) & 0x70;
        CP_ASYNC16(sdst + off, g + (((size_t)(tok0 + r)) << 10) + colb + c8 * 8);
    }
}

__device__ __forceinline__ void at_cp_vt(const __nv_bfloat16* vt, int bh, int kb,
                                         uint32_t sdst, int tid)
{
#pragma unroll
    for (int j = 0; j < 4; j++) {
        const int i = j * 256 + tid;
        const int r = i >> 4, c16 = i & 15;
        uint32_t off = (uint32_t)((r >> 3) * 1024 + (c16 >> 3) * 8192 + (r & 7) * 128 + (c16 & 7) * 16);
        off ^= (off >> 3) & 0x70;
        CP_ASYNC16(sdst + off, vt + ((size_t)(bh * HD + r)) * TQ + kb + c16 * 8);
    }
}

__global__ __launch_bounds__(256, 1)
void attention_tc_kernel(const __nv_bfloat16* __restrict__ Qhi_g,
                         const __nv_bfloat16* __restrict__ Qlo_g,
                         const __nv_bfloat16* __restrict__ Khi_g,
                         const __nv_bfloat16* __restrict__ Klo_g,
                         const __nv_bfloat16* __restrict__ Vthi_g,
                         const __nv_bfloat16* __restrict__ Vtlo_g,
                         __nv_bfloat16* __restrict__ Ohi_g,
                         __nv_bfloat16* __restrict__ Olo_g)
{
#ifdef TCGEN05_OK
    extern __shared__ char smem[];
    const uint32_t sbase = smem_to_u32(smem);
    const int tid = threadIdx.x;
    const int wid = tid >> 5;
    const int lid = tid & 31;
    const int b = blockIdx.z, h = blockIdx.y;
    const int bh = b * NH + h;
    const int tok0 = b * TQ + blockIdx.x * 128;
    const int colb = h * HD;
    const uint32_t mbarS = sbase + 16, mbarO = sbase + 24;

    if (wid == 0) TCGEN05_ALLOC(sbase + 0, 512);
    if (tid == 0) { MBARRIER_INIT(mbarS, 1); MBARRIER_INIT(mbarO, 1); }
    __syncthreads();
    uint32_t tmem;
    asm volatile("ld.shared.b32 %0, [%1];" : "=r"(tmem) : "r"(sbase + 0));

    at_cp_tile(Qhi_g, tok0, colb, sbase + AT_QHI, tid);
    at_cp_tile(Qlo_g, tok0, colb, sbase + AT_QLO, tid);
    at_cp_tile(Khi_g, b * TQ, colb, sbase + AT_K0, tid);
    at_cp_tile(Klo_g, b * TQ, colb, sbase + AT_K0 + 16384, tid);
    at_cp_vt(Vthi_g, bh, 0, sbase + AT_V0, tid);
    at_cp_vt(Vtlo_g, bh, 0, sbase + AT_V0 + 16384, tid);
    CP_COMMIT();
    CP_WAIT0();
    __syncthreads();

    const uint64_t dQh = MAKE_SMEM_DESC(sbase + AT_QHI);
    const uint64_t dQl = MAKE_SMEM_DESC(sbase + AT_QLO);

    // issue S(0)
    if (wid == 0) {
        TCGEN05_FENCE_AFTER();
        if (elect_one_pred()) {
            asm volatile("fence.proxy.async.shared::cta;" ::: "memory");
            const uint64_t dKh = MAKE_SMEM_DESC(sbase + AT_K0);
            const uint64_t dKl = MAKE_SMEM_DESC(sbase + AT_K0 + 16384);
#pragma unroll
            for (int k = 0; k < 4; k++) {
                mma_f16_ss_cg1(tmem + 0, dQh + 2*k, dKh + 2*k, IDESC_S, (k > 0));
                mma_f16_ss_cg1(tmem + 0, dQh + 2*k, dKl + 2*k, IDESC_S, 1);
                mma_f16_ss_cg1(tmem + 0, dQl + 2*k, dKh + 2*k, IDESC_S, 1);
            }
            TCGEN05_COMMIT(mbarS);
        }
    }

    const int subp = wid & 3;
    const int half = wid >> 2;
    const int qrow = subp * 32 + lid;
    const uint32_t loff = (uint32_t)subp << 21;
    float l_part = 0.0f;
    const float CEX = 0.125f * 1.44269504f;

    for (int t = 0; t < 16; t++) {
        // fire loads(t+1): K group first, then V group (separate commits)
        if (t + 1 < 16) {
            const int kb = (t + 1) * 128;
            const uint32_t ks = sbase + AT_K0 + ((t + 1) & 1) * 32768;
            const uint32_t vs = sbase + AT_V0 + ((t + 1) % 3) * 32768;
            at_cp_tile(Khi_g, b * TQ + kb, colb, ks, tid);
            at_cp_tile(Klo_g, b * TQ + kb, colb, ks + 16384, tid);
            CP_COMMIT();                         // group: K(t+1)
            at_cp_vt(Vthi_g, bh, kb, vs, tid);
            at_cp_vt(Vtlo_g, bh, kb, vs + 16384, tid);
            CP_COMMIT();                         // group: V(t+1)
        }

        // wait S(t), softmax into registers
        MBARRIER_WAIT_PARITY(mbarS, t & 1);
        TCGEN05_FENCE_AFTER();

        uint32_t hiw[32], low[32];
        {
            const uint32_t sb = tmem + (t & 1) * 128 + half * 64 + loff;
            uint32_t r0[32], r1[32];
            TCGEN05_LD_32X32B_X32(r0, sb);
            TCGEN05_LD_32X32B_X32(r1, sb + 32);
            TCGEN05_WAIT_LD();
            float p[64];
            float psum = 0.0f;
#pragma unroll
            for (int j = 0; j < 32; j++) {
                float a0 = __uint_as_float(r0[j]) * CEX;
                float a1 = __uint_as_float(r1[j]) * CEX;
                float e0, e1;
                asm("ex2.approx.f32 %0, %1;" : "=f"(e0) : "f"(a0));
                asm("ex2.approx.f32 %0, %1;" : "=f"(e1) : "f"(a1));
                p[j] = e0; p[32 + j] = e1;
                psum += e0 + e1;
            }
            l_part += psum;
#pragma unroll
            for (int j2 = 0; j2 < 32; j2++) {
                float p0 = p[2*j2], p1 = p[2*j2 + 1];
                uint32_t wh;
                asm("cvt.rn.bf16x2.f32 %0, %1, %2;" : "=r"(wh) : "f"(p1), "f"(p0));
                float h0 = __uint_as_float(wh << 16);
                float h1 = __uint_as_float(wh & 0xffff0000u);
                float q0 = p0 - h0, q1 = p1 - h1;
                uint32_t wl;
                asm("cvt.rn.bf16x2.f32 %0, %1, %2;" : "=r"(wl) : "f"(q1), "f"(q0));
                hiw[j2] = wh; low[j2] = wl;
            }
        }

        // K(t+1) ready (V(t+1) may still fly); also guarantees V(t) is ready.
        if (t + 1 < 16) CP_WAIT1(); else CP_WAIT0();
        __syncthreads();

        // issue S(t+1) EARLY — overlaps mbarO wait + STTM + PV issue below
        if (t + 1 < 16 && wid == 0) {
            if (elect_one_pred()) {
                asm volatile("fence.proxy.async.shared::cta;" ::: "memory");
                const uint32_t ks = sbase + AT_K0 + ((t + 1) & 1) * 32768;
                const uint64_t dKh = MAKE_SMEM_DESC(ks);
                const uint64_t dKl = MAKE_SMEM_DESC(ks + 16384);
                const uint32_t sdst = tmem + ((t + 1) & 1) * 128;
#pragma unroll
                for (int k = 0; k < 4; k++) {
                    mma_f16_ss_cg1(sdst, dQh + 2*k, dKh + 2*k, IDESC_S, (k > 0));
                    mma_f16_ss_cg1(sdst, dQh + 2*k, dKl + 2*k, IDESC_S, 1);
                    mma_f16_ss_cg1(sdst, dQl + 2*k, dKh + 2*k, IDESC_S, 1);
                }
                TCGEN05_COMMIT(mbarS);
            }
        }

        // P TMEM single-buffered: PV(t-1) must be done before overwrite
        if (t >= 1) { MBARRIER_WAIT_PARITY(mbarO, (t - 1) & 1); TCGEN05_FENCE_AFTER(); }

        TCGEN05_ST_32X32B_X32(tmem + 320 + half * 32 + loff, hiw);
        TCGEN05_ST_32X32B_X32(tmem + 384 + half * 32 + loff, low);
        TCGEN05_WAIT_ST();
        TCGEN05_FENCE_BEFORE();
        __syncthreads();

        // PV(t): TS-mode, A = P in TMEM, B = V^T K-major
        if (wid == 0) {
            TCGEN05_FENCE_AFTER();
            if (elect_one_pred()) {
                asm volatile("fence.proxy.async.shared::cta;" ::: "memory");
                const uint32_t vs = sbase + AT_V0 + (t % 3) * 32768;
                const uint64_t dVh = MAKE_SMEM_DESC(vs);
                const uint64_t dVl = MAKE_SMEM_DESC(vs + 16384);
#pragma unroll
                for (int s = 0; s < 8; s++) {
                    const uint64_t vb = (uint64_t)((s & 3) * 2 + (s >> 2) * 512);
                    const uint32_t pah = tmem + 320 + s * 8;
                    const uint32_t pal = tmem + 384 + s * 8;
                    mma_f16_ts_cg1(tmem + 256, pah, dVh + vb, IDESC_PV, (t > 0 || s > 0));
                    mma_f16_ts_cg1(tmem + 256, pah, dVl + vb, IDESC_PV, 1);
                    mma_f16_ts_cg1(tmem + 256, pal, dVh + vb, IDESC_PV, 1);
                }
                TCGEN05_COMMIT(mbarO);
            }
        }
    }

    *reinterpret_cast<float*>(smem + AT_LPART + (qrow * 2 + half) * 4) = l_part;
    __syncthreads();

    MBARRIER_WAIT_PARITY(mbarO, 1);
    TCGEN05_FENCE_AFTER();

    if (wid < 4) {
        const float lsum =
            *reinterpret_cast<float*>(smem + AT_LPART + (qrow * 2 + 0) * 4) +
            *reinterpret_cast<float*>(smem + AT_LPART + (qrow * 2 + 1) * 4);
        const float inv = 1.0f / lsum;
        uint32_t o0[32], o1[32];
        TCGEN05_LD_32X32B_X32(o0, tmem + 256 + loff);
        TCGEN05_LD_32X32B_X32(o1, tmem + 288 + loff);
        TCGEN05_WAIT_LD();
        uint32_t hibuf[32], lobuf[32];
#pragma unroll
        for (int c = 0; c < 32; c++) {
            float f0 = __uint_as_float(c < 16 ? o0[2*c]   : o1[2*(c-16)])   * inv;
            float f1 = __uint_as_float(c < 16 ? o0[2*c+1] : o1[2*(c-16)+1]) * inv;
            uint32_t wh;
            asm("cvt.rn.bf16x2.f32 %0, %1, %2;" : "=r"(wh) : "f"(f1), "f"(f0));
            float h0 = __uint_as_float(wh << 16);
            float h1 = __uint_as_float(wh & 0xffff0000u);
            float q0 = f0 - h0, q1 = f1 - h1;
            uint32_t wl;
            asm("cvt.rn.bf16x2.f32 %0, %1, %2;" : "=r"(wl) : "f"(q1), "f"(q0));
            hibuf[c] = wh; lobuf[c] = wl;
        }
        const size_t rowoff = (((size_t)(tok0 + qrow)) << 10) + colb;
#pragma unroll
        for (int v4 = 0; v4 < 8; v4++) {
            *reinterpret_cast<uint4*>(Ohi_g + rowoff + v4 * 8) =
                *reinterpret_cast<uint4*>(&hibuf[v4 * 4]);
            *reinterpret_cast<uint4*>(Olo_g + rowoff + v4 * 8) =
                *reinterpret_cast<uint4*>(&lobuf[v4 * 4]);
        }
    }
    __syncthreads();
    if (wid == 0) {
        TCGEN05_RELINQUISH();
        TCGEN05_DEALLOC(tmem, 512);
    }
#endif
}

// ---------------- fp32 -> bf16 hi/lo split ----------------------------------
__global__ __launch_bounds__(256)
void split_bf16_kernel(const float4* __restrict__ in,
                       uint2* __restrict__ hi, uint2* __restrict__ lo, int n4)
{
    const int i = blockIdx.x * blockDim.x + threadIdx.x;
    if (i >= n4) return;
    float4 v = in[i];
    __nv_bfloat16 h0 = __float2bfloat16_rn(v.x);
    __nv_bfloat16 h1 = __float2bfloat16_rn(v.y);
    __nv_bfloat16 h2 = __float2bfloat16_rn(v.z);
    __nv_bfloat16 h3 = __float2bfloat16_rn(v.w);
    __nv_bfloat16 l0 = __float2bfloat16_rn(v.x - __bfloat162float(h0));
    __nv_bfloat16 l1 = __float2bfloat16_rn(v.y - __bfloat162float(h1));
    __nv_bfloat16 l2 = __float2bfloat16_rn(v.z - __bfloat162float(h2));
    __nv_bfloat16 l3 = __float2bfloat16_rn(v.w - __bfloat162float(h3));
    uint2 ph, pl;
    ph.x = ((uint32_t)__bfloat16_as_ushort(h1) << 16) | __bfloat16_as_ushort(h0);
    ph.y = ((uint32_t)__bfloat16_as_ushort(h3) << 16) | __bfloat16_as_ushort(h2);
    pl.x = ((uint32_t)__bfloat16_as_ushort(l1) << 16) | __bfloat16_as_ushort(l0);
    pl.y = ((uint32_t)__bfloat16_as_ushort(l3) << 16) | __bfloat16_as_ushort(l2);
    hi[i] = ph;
    lo[i] = pl;
}

// ---------------- W [K,N] -> W^T hi/lo bf16 [N,K], all 4 weights ------------
__global__ __launch_bounds__(256)
void transpose_split4_kernel(const float* __restrict__ W0,
                             const float* __restrict__ W1,
                             const float* __restrict__ W2,
                             const float* __restrict__ W3,
                             __nv_bfloat16* __restrict__ Thi,
                             __nv_bfloat16* __restrict__ Tlo)
{
    __shared__ float tile[32][33];
    const int w = blockIdx.z;
    const float* W = (w == 0) ? W0 : (w == 1) ? W1 : (w == 2) ? W2 : W3;
    __nv_bfloat16* thi = Thi + (size_t)w * EDIM * EDIM;
    __nv_bfloat16* tlo = Tlo + (size_t)w * EDIM * EDIM;
    const int bx = blockIdx.x * 32;
    const int by = blockIdx.y * 32;
    const int tx = threadIdx.x & 31, ty = threadIdx.x >> 5;
#pragma unroll
    for (int j = ty; j < 32; j += 8)
        tile[j][tx] = W[(size_t)(by + j) * EDIM + bx + tx];
    __syncthreads();
#pragma unroll
    for (int j = ty; j < 32; j += 8) {
        float v = tile[tx][j];
        __nv_bfloat16 h = __float2bfloat16_rn(v);
        __nv_bfloat16 l = __float2bfloat16_rn(v - __bfloat162float(h));
        thi[(size_t)(bx + j) * EDIM + by + tx] = h;
        tlo[(size_t)(bx + j) * EDIM + by + tx] = l;
    }
}

// ---------------- cumprod(cos(x)) -> bf16 hi/lo, warp-per-row, z picks q/k --
__global__ __launch_bounds__(256)
void cumprod_cos_split_kernel(const float* __restrict__ in0,
                              __nv_bfloat16* __restrict__ hi0,
                              __nv_bfloat16* __restrict__ lo0,
                              const float* __restrict__ in1,
                              __nv_bfloat16* __restrict__ hi1,
                              __nv_bfloat16* __restrict__ lo1)
{
    const float* in = blockIdx.z ? in1 : in0;
    __nv_bfloat16* hi = blockIdx.z ? hi1 : hi0;
    __nv_bfloat16* lo = blockIdx.z ? lo1 : lo0;
    const int row  = blockIdx.x * 8 + (threadIdx.x >> 5);
    const int lane = threadIdx.x & 31;
    const float* rp = in + (size_t)row * EDIM + lane * 32;

    float v[32];
#pragma unroll
    for (int i = 0; i < 8; i++) {
        float4 f = reinterpret_cast<const float4*>(rp)[i];
        v[4*i+0] = f.x; v[4*i+1] = f.y; v[4*i+2] = f.z; v[4*i+3] = f.w;
    }
    float c = 1.0f;
#pragma unroll
    for (int i = 0; i < 32; i++) { c *= __cosf(v[i]); v[i] = c; }
    float p = c;
#pragma unroll
    for (int off = 1; off < 32; off <<= 1) {
        float t = __shfl_up_sync(0xffffffffu, p, off);
        if (lane >= off) p *= t;
    }
    float excl = __shfl_up_sync(0xffffffffu, p, 1);
    if (lane == 0) excl = 1.0f;

    uint32_t hiw[16], low[16];
#pragma unroll
    for (int j = 0; j < 16; j++) {
        float f0 = v[2*j] * excl;
        float f1 = v[2*j + 1] * excl;
        uint32_t wh;
        asm("cvt.rn.bf16x2.f32 %0, %1, %2;" : "=r"(wh) : "f"(f1), "f"(f0));
        float h0 = __uint_as_float(wh << 16);
        float h1 = __uint_as_float(wh & 0xffff0000u);
        float q0 = f0 - h0, q1 = f1 - h1;
        uint32_t wl;
        asm("cvt.rn.bf16x2.f32 %0, %1, %2;" : "=r"(wl) : "f"(q1), "f"(q0));
        hiw[j] = wh; low[j] = wl;
    }
    __nv_bfloat16* hp = hi + (size_t)row * EDIM + lane * 32;
    __nv_bfloat16* lp = lo + (size_t)row * EDIM + lane * 32;
#pragma unroll
    for (int j4 = 0; j4 < 4; j4++) {
        *reinterpret_cast<uint4*>(hp + j4 * 8) = *reinterpret_cast<uint4*>(&hiw[j4 * 4]);
        *reinterpret_cast<uint4*>(lp + j4 * 8) = *reinterpret_cast<uint4*>(&low[j4 * 4]);
    }
}

// ---------------- launch ----------------------------------------------------
extern "C" void kernel_launch(void* const* d_in, const int* in_sizes, int n_in,
                              void* d_out, int out_size)
{
    const float* x  = (const float*)d_in[0];
    const float* Wq = (const float*)d_in[1];
    const float* bq = (const float*)d_in[2];
    const float* Wk = (const float*)d_in[3];
    const float* bk = (const float*)d_in[4];
    const float* Wv = (const float*)d_in[5];
    const float* bv = (const float*)d_in[6];
    const float* Wo = (const float*)d_in[7];
    const float* bo = (const float*)d_in[8];
    float* out = (float*)d_out;

    float *q, *k;
    __nv_bfloat16 *xhi, *xlo, *qhi, *qlo, *khi, *klo, *vthi, *vtlo, *aohi, *aolo, *wthi, *wtlo;
    cudaGetSymbolAddress((void**)&q,    g_q);
    cudaGetSymbolAddress((void**)&k,    g_k);
    cudaGetSymbolAddress((void**)&xhi,  g_xhi);
    cudaGetSymbolAddress((void**)&xlo,  g_xlo);
    cudaGetSymbolAddress((void**)&qhi,  g_qhi);
    cudaGetSymbolAddress((void**)&qlo,  g_qlo);
    cudaGetSymbolAddress((void**)&khi,  g_khi);
    cudaGetSymbolAddress((void**)&klo,  g_klo);
    cudaGetSymbolAddress((void**)&vthi, g_vthi);
    cudaGetSymbolAddress((void**)&vtlo, g_vtlo);
    cudaGetSymbolAddress((void**)&aohi, g_aohi);
    cudaGetSymbolAddress((void**)&aolo, g_aolo);
    cudaGetSymbolAddress((void**)&wthi, g_wthi);
    cudaGetSymbolAddress((void**)&wtlo, g_wtlo);

    cudaFuncSetAttribute(gemm_tc2_kernel, cudaFuncAttributeMaxDynamicSharedMemorySize, GEMM_SMEM);
    cudaFuncSetAttribute(attention_tc_kernel, cudaFuncAttributeMaxDynamicSharedMemorySize, AT_SMEM_TOTAL);

    const int n4 = MROWS * EDIM / 4;
    split_bf16_kernel<<<(n4 + 255) / 256, 256>>>((const float4*)x, (uint2*)xhi, (uint2*)xlo, n4);

    dim3 tg4(32, 32, 4);
    transpose_split4_kernel<<<tg4, 256>>>(Wq, Wk, Wv, Wo, wthi, wtlo);

    dim3 gqkv(EDIM / 256, MROWS / 128, 3);
    gemm_tc2_kernel<<<gqkv, 512, GEMM_SMEM>>>(xhi, xlo, wthi, wtlo, 0,
                                              bq, bk, bv, q, k, vthi, vtlo, 2);

    dim3 gc(MROWS / 8, 1, 2);
    cumprod_cos_split_kernel<<<gc, 256>>>(q, qhi, qlo, k, khi, klo);

    // role swap: attention-Q = quantum(k-proj), attention-K = quantum(q-proj)
    dim3 ga(TQ / 128, NH, NB);
    attention_tc_kernel<<<ga, 256, AT_SMEM_TOTAL>>>(khi, klo, qhi, qlo, vthi, vtlo, aohi, aolo);

    dim3 go(EDIM / 256, MROWS / 128, 1);
    gemm_tc2_kernel<<<go, 512, GEMM_SMEM>>>(aohi, aolo, wthi, wtlo, 3,
                                            bo, bo, bo, out, out, nullptr, nullptr, -1);
}